// round 1
// baseline (speedup 1.0000x reference)
#include <cuda_runtime.h>
#include <math.h>

// Problem dims
#define BATCH 4
#define TSEQ  1024
#define BT    4096          // BATCH*TSEQ
#define DMODEL 1024
#define NH    16
#define DH    64
#define NE    8
#define FF    4096
#define CAP   9216          // 72 * 128 row capacity for grouped MoE GEMMs
#define NTILES 72

// ---------------- static device scratch (no allocations allowed) ----------------
__device__ float g_h  [BT * DMODEL];        // ln1(x)+c
__device__ float g_qkv[BT * 3 * DMODEL];
__device__ float g_o  [BT * DMODEL];        // attention output
__device__ float g_x2 [BT * DMODEL];        // x + proj(o)
__device__ float g_xn [BT * DMODEL];        // ln2(x2)  (also output base)
__device__ float g_xg [CAP * DMODEL];       // gathered tokens per expert
__device__ float g_hid[CAP * FF];           // gelu(xg @ w1^T)
__device__ float g_eo [CAP * DMODEL];       // expert outputs
__device__ int   g_eidx[BT * 2];
__device__ float g_wts [BT * 2];
__device__ int   g_rows[BT * 2];
__device__ int   g_tile_e[NTILES];

__device__ __forceinline__ float gelu_f(float v) {
    return 0.5f * v * (1.0f + erff(v * 0.70710678118654752f));
}

// ---------------- LayerNorm (optionally + c broadcast over T) ----------------
template<bool ADDC>
__global__ __launch_bounds__(256) void ln_kernel(const float* __restrict__ x,
                                                 const float* __restrict__ w,
                                                 const float* __restrict__ c,
                                                 float* __restrict__ out) {
    int row = blockIdx.x;
    int tid = threadIdx.x;
    const float* xr = x + (size_t)row * DMODEL;
    float4 v = *(const float4*)(xr + tid * 4);

    __shared__ float red[8];
    __shared__ float tot;

    float s = v.x + v.y + v.z + v.w;
#pragma unroll
    for (int m = 16; m > 0; m >>= 1) s += __shfl_xor_sync(0xffffffffu, s, m);
    if ((tid & 31) == 0) red[tid >> 5] = s;
    __syncthreads();
    if (tid == 0) { float t = 0.f; for (int i = 0; i < 8; i++) t += red[i]; tot = t; }
    __syncthreads();
    float mean = tot * (1.0f / DMODEL);
    float dx = v.x - mean, dy = v.y - mean, dz = v.z - mean, dw = v.w - mean;
    float s2 = dx * dx + dy * dy + dz * dz + dw * dw;
    __syncthreads();   // everyone has read tot, red reusable
#pragma unroll
    for (int m = 16; m > 0; m >>= 1) s2 += __shfl_xor_sync(0xffffffffu, s2, m);
    if ((tid & 31) == 0) red[tid >> 5] = s2;
    __syncthreads();
    if (tid == 0) { float t = 0.f; for (int i = 0; i < 8; i++) t += red[i]; tot = t; }
    __syncthreads();
    float inv = rsqrtf(tot * (1.0f / DMODEL) + 1e-5f);

    int d0 = tid * 4;
    float4 w4 = *(const float4*)(w + d0);
    float4 r;
    r.x = dx * inv * w4.x;
    r.y = dy * inv * w4.y;
    r.z = dz * inv * w4.z;
    r.w = dw * inv * w4.w;
    if (ADDC) {
        int b = row >> 10;   // row / TSEQ
        float4 c4 = *(const float4*)(c + (size_t)b * DMODEL + d0);
        r.x += c4.x; r.y += c4.y; r.z += c4.z; r.w += c4.w;
    }
    *(float4*)(out + (size_t)row * DMODEL + d0) = r;
}

// ---------------- SGEMM NT: C[M,N] = A[M,K] @ B[N,K]^T ----------------
// EPI: 0 = plain, 1 = + Res, 2 = gelu
// tile_e != nullptr => grouped: B = Bbase + tile_e[by]*bstride, exit on -1.
template<int EPI>
__global__ __launch_bounds__(256) void sgemm_nt(const float* __restrict__ A,
                                                const float* __restrict__ Bbase,
                                                size_t bstride,
                                                const int* __restrict__ tile_e,
                                                float* __restrict__ C,
                                                const float* __restrict__ Res,
                                                int N, int K) {
    __shared__ float As[8][128];
    __shared__ float Bs[8][128];
    int by = blockIdx.y, bx = blockIdx.x;
    const float* B = Bbase;
    if (tile_e) {
        int e = tile_e[by];
        if (e < 0) return;
        B += (size_t)e * bstride;
    }
    int tid = threadIdx.x;
    int lr = tid >> 1;
    int lc = (tid & 1) * 4;
    const float* Ap = A + (size_t)(by * 128 + lr) * K + lc;
    const float* Bp = B + (size_t)(bx * 128 + lr) * K + lc;
    int ty = tid >> 4, tx = tid & 15;

    float acc[8][8] = {};
    for (int k0 = 0; k0 < K; k0 += 8) {
        float4 a4 = *(const float4*)(Ap + k0);
        float4 b4 = *(const float4*)(Bp + k0);
        __syncthreads();
        As[lc + 0][lr] = a4.x; As[lc + 1][lr] = a4.y;
        As[lc + 2][lr] = a4.z; As[lc + 3][lr] = a4.w;
        Bs[lc + 0][lr] = b4.x; Bs[lc + 1][lr] = b4.y;
        Bs[lc + 2][lr] = b4.z; Bs[lc + 3][lr] = b4.w;
        __syncthreads();
        float ar[8], br[8];
#pragma unroll
        for (int kk = 0; kk < 8; kk++) {
            *(float4*)&ar[0] = *(const float4*)&As[kk][ty * 8];
            *(float4*)&ar[4] = *(const float4*)&As[kk][ty * 8 + 4];
            *(float4*)&br[0] = *(const float4*)&Bs[kk][tx * 8];
            *(float4*)&br[4] = *(const float4*)&Bs[kk][tx * 8 + 4];
#pragma unroll
            for (int i = 0; i < 8; i++)
#pragma unroll
                for (int j = 0; j < 8; j++)
                    acc[i][j] += ar[i] * br[j];
        }
    }
    size_t crow = (size_t)by * 128 + ty * 8;
    int ccol = bx * 128 + tx * 8;
#pragma unroll
    for (int i = 0; i < 8; i++) {
        size_t ro = (crow + i) * (size_t)N + ccol;
        float vals[8];
#pragma unroll
        for (int j = 0; j < 8; j++) {
            float v = acc[i][j];
            if (EPI == 1) v += Res[ro + j];
            if (EPI == 2) v = gelu_f(v);
            vals[j] = v;
        }
        *(float4*)(C + ro)     = make_float4(vals[0], vals[1], vals[2], vals[3]);
        *(float4*)(C + ro + 4) = make_float4(vals[4], vals[5], vals[6], vals[7]);
    }
}

// ---------------- Flash-style causal attention ----------------
// grid: (T/64, B*H), 256 threads, 64x64 tiles, fp32.
__global__ __launch_bounds__(256) void attn_kernel(const float* __restrict__ qkv,
                                                   float* __restrict__ o) {
    const int S = 65; // smem stride (pad to reduce conflicts)
    extern __shared__ float sm[];
    float* Qs = sm;
    float* Ks = Qs + 64 * S;
    float* Vs = Ks + 64 * S;
    float* Ps = Vs + 64 * S;

    int qi = blockIdx.x;
    int bh = blockIdx.y;
    int b = bh >> 4, h = bh & 15;
    int tid = threadIdx.x;
    int tr = tid >> 4, tc = tid & 15;

    const float* base = qkv + (size_t)b * TSEQ * 3072;

    // load Q tile (scaled by 1/sqrt(dh) = 0.125)
#pragma unroll
    for (int k = 0; k < 4; k++) {
        int e = k * 256 + tid;
        int r = e >> 4, c4 = (e & 15) * 4;
        float4 v = *(const float4*)(base + (size_t)(qi * 64 + r) * 3072 + h * 64 + c4);
        float* d = &Qs[r * S + c4];
        d[0] = v.x * 0.125f; d[1] = v.y * 0.125f; d[2] = v.z * 0.125f; d[3] = v.w * 0.125f;
    }

    float m[4], l[4], acc[4][4];
#pragma unroll
    for (int i = 0; i < 4; i++) {
        m[i] = -1e30f; l[i] = 0.f;
#pragma unroll
        for (int j = 0; j < 4; j++) acc[i][j] = 0.f;
    }

    for (int jt = 0; jt <= qi; jt++) {
        __syncthreads(); // protect Ks/Vs reuse + Q visibility on first iter
#pragma unroll
        for (int k = 0; k < 4; k++) {
            int e = k * 256 + tid;
            int r = e >> 4, c4 = (e & 15) * 4;
            size_t rowoff = (size_t)(jt * 64 + r) * 3072 + h * 64 + c4;
            float4 kv = *(const float4*)(base + rowoff + 1024);
            float4 vv = *(const float4*)(base + rowoff + 2048);
            float* dk = &Ks[r * S + c4];
            dk[0] = kv.x; dk[1] = kv.y; dk[2] = kv.z; dk[3] = kv.w;
            float* dv = &Vs[r * S + c4];
            dv[0] = vv.x; dv[1] = vv.y; dv[2] = vv.z; dv[3] = vv.w;
        }
        __syncthreads();

        // S = Q K^T
        float s[4][4] = {};
#pragma unroll 8
        for (int kk = 0; kk < 64; kk++) {
            float a0 = Qs[(4 * tr + 0) * S + kk];
            float a1 = Qs[(4 * tr + 1) * S + kk];
            float a2 = Qs[(4 * tr + 2) * S + kk];
            float a3 = Qs[(4 * tr + 3) * S + kk];
            float b0 = Ks[(4 * tc + 0) * S + kk];
            float b1 = Ks[(4 * tc + 1) * S + kk];
            float b2 = Ks[(4 * tc + 2) * S + kk];
            float b3 = Ks[(4 * tc + 3) * S + kk];
            s[0][0] += a0 * b0; s[0][1] += a0 * b1; s[0][2] += a0 * b2; s[0][3] += a0 * b3;
            s[1][0] += a1 * b0; s[1][1] += a1 * b1; s[1][2] += a1 * b2; s[1][3] += a1 * b3;
            s[2][0] += a2 * b0; s[2][1] += a2 * b1; s[2][2] += a2 * b2; s[2][3] += a2 * b3;
            s[3][0] += a3 * b0; s[3][1] += a3 * b1; s[3][2] += a3 * b2; s[3][3] += a3 * b3;
        }

        if (jt == qi) {
#pragma unroll
            for (int i = 0; i < 4; i++) {
                int rg = qi * 64 + 4 * tr + i;
#pragma unroll
                for (int j = 0; j < 4; j++) {
                    int cg = jt * 64 + 4 * tc + j;
                    if (cg > rg) s[i][j] = -1e30f;
                }
            }
        }

        // online softmax per row (16-lane row groups)
#pragma unroll
        for (int i = 0; i < 4; i++) {
            float mt = fmaxf(fmaxf(s[i][0], s[i][1]), fmaxf(s[i][2], s[i][3]));
#pragma unroll
            for (int mm = 8; mm > 0; mm >>= 1)
                mt = fmaxf(mt, __shfl_xor_sync(0xffffffffu, mt, mm));
            float mn = fmaxf(m[i], mt);
            float alpha = expf(m[i] - mn);
            float ls = 0.f;
#pragma unroll
            for (int j = 0; j < 4; j++) {
                float p = expf(s[i][j] - mn);
                s[i][j] = p;
                ls += p;
            }
#pragma unroll
            for (int mm = 8; mm > 0; mm >>= 1)
                ls += __shfl_xor_sync(0xffffffffu, ls, mm);
            l[i] = l[i] * alpha + ls;
            m[i] = mn;
#pragma unroll
            for (int j = 0; j < 4; j++) acc[i][j] *= alpha;
        }

        __syncthreads(); // everyone done reading previous Ps (sync'd at top too, keep ordering w/ compute)
#pragma unroll
        for (int i = 0; i < 4; i++)
#pragma unroll
            for (int j = 0; j < 4; j++)
                Ps[(4 * tr + i) * S + 4 * tc + j] = s[i][j];
        __syncthreads();

        // O += P V
#pragma unroll 8
        for (int kk = 0; kk < 64; kk++) {
            float p0 = Ps[(4 * tr + 0) * S + kk];
            float p1 = Ps[(4 * tr + 1) * S + kk];
            float p2 = Ps[(4 * tr + 2) * S + kk];
            float p3 = Ps[(4 * tr + 3) * S + kk];
            float v0 = Vs[kk * S + 4 * tc + 0];
            float v1 = Vs[kk * S + 4 * tc + 1];
            float v2 = Vs[kk * S + 4 * tc + 2];
            float v3 = Vs[kk * S + 4 * tc + 3];
            acc[0][0] += p0 * v0; acc[0][1] += p0 * v1; acc[0][2] += p0 * v2; acc[0][3] += p0 * v3;
            acc[1][0] += p1 * v0; acc[1][1] += p1 * v1; acc[1][2] += p1 * v2; acc[1][3] += p1 * v3;
            acc[2][0] += p2 * v0; acc[2][1] += p2 * v1; acc[2][2] += p2 * v2; acc[2][3] += p2 * v3;
            acc[3][0] += p3 * v0; acc[3][1] += p3 * v1; acc[3][2] += p3 * v2; acc[3][3] += p3 * v3;
        }
    }

#pragma unroll
    for (int i = 0; i < 4; i++) {
        int rg = qi * 64 + 4 * tr + i;
        float invl = 1.0f / l[i];
#pragma unroll
        for (int j = 0; j < 4; j++) {
            o[((size_t)(b * TSEQ + rg)) * DMODEL + h * 64 + 4 * tc + j] = acc[i][j] * invl;
        }
    }
}

// ---------------- router: logits, softmax, clamp, top-2, renorm weights ----------------
__global__ __launch_bounds__(256) void router_kernel(const float* __restrict__ xn,
                                                     const float* __restrict__ rw,
                                                     int* __restrict__ eidx,
                                                     float* __restrict__ wts) {
    int t = blockIdx.x;
    int tid = threadIdx.x, lane = tid & 31, wp = tid >> 5;
    const float* xr = xn + (size_t)t * DMODEL;
    const float* wr = rw + (size_t)wp * DMODEL;
    float s = 0.f;
    for (int d = lane * 4; d < DMODEL; d += 128) {
        float4 a = *(const float4*)(xr + d);
        float4 b = *(const float4*)(wr + d);
        s += a.x * b.x + a.y * b.y + a.z * b.z + a.w * b.w;
    }
#pragma unroll
    for (int mm = 16; mm > 0; mm >>= 1) s += __shfl_xor_sync(0xffffffffu, s, mm);
    __shared__ float lg[8];
    if (lane == 0) lg[wp] = s;
    __syncthreads();
    if (tid == 0) {
        float mx = lg[0];
        for (int e = 1; e < NE; e++) mx = fmaxf(mx, lg[e]);
        float p[NE]; float sum = 0.f;
        for (int e = 0; e < NE; e++) { p[e] = expf(lg[e] - mx); sum += p[e]; }
        float inv = 1.0f / sum;
        for (int e = 0; e < NE; e++) {
            float v = p[e] * inv + 1e-9f;
            p[e] = fminf(fmaxf(v, 1e-9f), 1.0f - 1e-9f);
        }
        int i0 = 0;
        for (int e = 1; e < NE; e++) if (p[e] > p[i0]) i0 = e;
        int i1 = (i0 == 0) ? 1 : 0;
        for (int e = 0; e < NE; e++) if (e != i0 && p[e] > p[i1]) i1 = e;
        float d2 = 1.0f / (p[i0] + p[i1]);
        eidx[2 * t] = i0; eidx[2 * t + 1] = i1;
        wts[2 * t] = p[i0] * d2; wts[2 * t + 1] = p[i1] * d2;
    }
}

// ---------------- build per-expert CSR with 128-aligned segments ----------------
__global__ __launch_bounds__(256) void build_kernel(const int* __restrict__ eidx,
                                                    int* __restrict__ rows,
                                                    int* __restrict__ tile_e) {
    __shared__ int cnt[NE];
    __shared__ int off[NE];
    int tid = threadIdx.x;
    if (tid < NE) cnt[tid] = 0;
    __syncthreads();
    for (int a = tid; a < BT * 2; a += 256) atomicAdd(&cnt[eidx[a]], 1);
    __syncthreads();
    if (tid == 0) {
        int o = 0;
        for (int e = 0; e < NE; e++) { off[e] = o; o = (o + cnt[e] + 127) & ~127; }
        for (int tt = 0; tt < NTILES; tt++) tile_e[tt] = -1;
        for (int e = 0; e < NE; e++) {
            int nt = (cnt[e] + 127) >> 7;
            int t0 = off[e] >> 7;
            for (int i = 0; i < nt; i++) tile_e[t0 + i] = e;
        }
    }
    __syncthreads();
    if (tid < NE) cnt[tid] = 0;
    __syncthreads();
    for (int a = tid; a < BT * 2; a += 256) {
        int e = eidx[a];
        int pos = atomicAdd(&cnt[e], 1);
        rows[a] = off[e] + pos;
    }
}

// ---------------- gather tokens into grouped buffer ----------------
__global__ __launch_bounds__(256) void gather_kernel(const float* __restrict__ xn,
                                                     const int* __restrict__ rows,
                                                     float* __restrict__ xg) {
    int a = blockIdx.x;
    int r = rows[a];
    int t = a >> 1;
    const float4* s = (const float4*)(xn + (size_t)t * DMODEL);
    float4* d = (float4*)(xg + (size_t)r * DMODEL);
    d[threadIdx.x] = s[threadIdx.x];
}

// ---------------- combine: out = xn + w0*eo[r0] + w1*eo[r1] ----------------
__global__ __launch_bounds__(256) void combine_kernel(const float* __restrict__ xn,
                                                      const float* __restrict__ eo,
                                                      const int* __restrict__ rows,
                                                      const float* __restrict__ wts,
                                                      float* __restrict__ out) {
    int t = blockIdx.x;
    int r0 = rows[2 * t], r1 = rows[2 * t + 1];
    float w0 = wts[2 * t], w1 = wts[2 * t + 1];
    int tid = threadIdx.x;
    float4 a = *(const float4*)(xn + (size_t)t * DMODEL + tid * 4);
    float4 b = *(const float4*)(eo + (size_t)r0 * DMODEL + tid * 4);
    float4 c = *(const float4*)(eo + (size_t)r1 * DMODEL + tid * 4);
    float4 r;
    r.x = a.x + w0 * b.x + w1 * c.x;
    r.y = a.y + w0 * b.y + w1 * c.y;
    r.z = a.z + w0 * b.z + w1 * c.z;
    r.w = a.w + w0 * b.w + w1 * c.w;
    *(float4*)(out + (size_t)t * DMODEL + tid * 4) = r;
}

// ---------------- host launcher ----------------
extern "C" void kernel_launch(void* const* d_in, const int* in_sizes, int n_in,
                              void* d_out, int out_size) {
    const float* x        = (const float*)d_in[0];
    const float* c        = (const float*)d_in[1];
    const float* ln1_w    = (const float*)d_in[2];
    const float* w_qkv    = (const float*)d_in[3];
    const float* w_proj   = (const float*)d_in[4];
    const float* ln2_w    = (const float*)d_in[5];
    const float* router_w = (const float*)d_in[6];
    const float* ew1      = (const float*)d_in[7];
    const float* ew2      = (const float*)d_in[8];
    float* out = (float*)d_out;

    float *p_h, *p_qkv, *p_o, *p_x2, *p_xn, *p_xg, *p_hid, *p_eo, *p_wts;
    int *p_eidx, *p_rows, *p_te;
    cudaGetSymbolAddress((void**)&p_h,    g_h);
    cudaGetSymbolAddress((void**)&p_qkv,  g_qkv);
    cudaGetSymbolAddress((void**)&p_o,    g_o);
    cudaGetSymbolAddress((void**)&p_x2,   g_x2);
    cudaGetSymbolAddress((void**)&p_xn,   g_xn);
    cudaGetSymbolAddress((void**)&p_xg,   g_xg);
    cudaGetSymbolAddress((void**)&p_hid,  g_hid);
    cudaGetSymbolAddress((void**)&p_eo,   g_eo);
    cudaGetSymbolAddress((void**)&p_wts,  g_wts);
    cudaGetSymbolAddress((void**)&p_eidx, g_eidx);
    cudaGetSymbolAddress((void**)&p_rows, g_rows);
    cudaGetSymbolAddress((void**)&p_te,   g_tile_e);

    // 1) h = LN1(x)*w + c
    ln_kernel<true><<<BT, 256>>>(x, ln1_w, c, p_h);

    // 2) qkv = h @ w_qkv^T   [4096 x 3072]
    sgemm_nt<0><<<dim3(24, 32), 256>>>(p_h, w_qkv, 0, nullptr, p_qkv, nullptr, 3072, 1024);

    // 3) causal attention
    int attn_smem = 4 * 64 * 65 * (int)sizeof(float);
    cudaFuncSetAttribute(attn_kernel, cudaFuncAttributeMaxDynamicSharedMemorySize, attn_smem);
    attn_kernel<<<dim3(16, 64), 256, attn_smem>>>(p_qkv, p_o);

    // 4) x2 = x + o @ w_proj^T
    sgemm_nt<1><<<dim3(8, 32), 256>>>(p_o, w_proj, 0, nullptr, p_x2, x, 1024, 1024);

    // 5) xn = LN2(x2)
    ln_kernel<false><<<BT, 256>>>(p_x2, ln2_w, nullptr, p_xn);

    // 6) router top-2
    router_kernel<<<BT, 256>>>(p_xn, router_w, p_eidx, p_wts);

    // 7) per-expert CSR
    build_kernel<<<1, 256>>>(p_eidx, p_rows, p_te);

    // 8) gather
    gather_kernel<<<BT * 2, 256>>>(p_xn, p_rows, p_xg);

    // 9) hid = gelu(xg @ w1[e]^T)  grouped [CAP x 4096]
    sgemm_nt<2><<<dim3(32, NTILES), 256>>>(p_xg, ew1, (size_t)FF * DMODEL, p_te,
                                           p_hid, nullptr, FF, DMODEL);

    // 10) eo = hid @ w2[e]^T  grouped [CAP x 1024]
    sgemm_nt<0><<<dim3(8, NTILES), 256>>>(p_hid, ew2, (size_t)DMODEL * FF, p_te,
                                          p_eo, nullptr, DMODEL, FF);

    // 11) out = xn + sum_k w_k * eo
    combine_kernel<<<BT, 256>>>(p_xn, p_eo, p_rows, p_wts, out);
}

// round 3
// speedup vs baseline: 1.9159x; 1.9159x over previous
#include <cuda_runtime.h>
#include <cuda_bf16.h>
#include <math.h>
#include <stdint.h>

// Problem dims
#define BATCH 4
#define TSEQ  1024
#define BT    4096
#define DMODEL 1024
#define NE    8
#define FF    4096
#define CAP   9216          // 72 * 128 row capacity for grouped MoE GEMMs
#define NTILES 72

// ---------------- static device scratch ----------------
__device__ float g_h  [BT * DMODEL];
__device__ float g_qkv[BT * 3 * DMODEL];
__device__ float g_o  [BT * DMODEL];
__device__ float g_x2 [BT * DMODEL];
__device__ float g_xn [BT * DMODEL];
__device__ float g_eo [CAP * DMODEL];
__device__ int   g_eidx[BT * 2];
__device__ float g_wts [BT * 2];
__device__ int   g_rows[BT * 2];
__device__ int   g_tile_e[NTILES];

// bf16 hi/lo split scratch
__device__ __nv_bfloat16 g_aHi [BT * DMODEL];
__device__ __nv_bfloat16 g_aLo [BT * DMODEL];
__device__ __nv_bfloat16 g_wHi [NE * FF * DMODEL];
__device__ __nv_bfloat16 g_wLo [NE * FF * DMODEL];
__device__ __nv_bfloat16 g_xgHi[CAP * DMODEL];
__device__ __nv_bfloat16 g_xgLo[CAP * DMODEL];
__device__ __nv_bfloat16 g_hidHi[CAP * FF];
__device__ __nv_bfloat16 g_hidLo[CAP * FF];

__device__ __forceinline__ float gelu_f(float v) {
    return 0.5f * v * (1.0f + erff(v * 0.70710678118654752f));
}

// ---------------- PTX helpers (sm_80+ portable; NO tcgen05) ----------------
__device__ __forceinline__ uint32_t smem_u32(const void* p) {
    uint32_t a;
    asm("{ .reg .u64 t; cvta.to.shared.u64 t, %1; cvt.u32.u64 %0, t; }" : "=r"(a) : "l"(p));
    return a;
}
__device__ __forceinline__ void cpa16(uint32_t dst, const void* src) {
    asm volatile("cp.async.cg.shared.global [%0], [%1], 16;" :: "r"(dst), "l"(src));
}
__device__ __forceinline__ void cp_commit() { asm volatile("cp.async.commit_group;" ::: "memory"); }
template<int NPEND> __device__ __forceinline__ void cp_wait() {
    asm volatile("cp.async.wait_group %0;" :: "n"(NPEND) : "memory");
}
__device__ __forceinline__ void ldm_x4(uint32_t* r, uint32_t a) {
    asm volatile("ldmatrix.sync.aligned.m8n8.x4.shared.b16 {%0,%1,%2,%3}, [%4];"
        : "=r"(r[0]), "=r"(r[1]), "=r"(r[2]), "=r"(r[3]) : "r"(a));
}
__device__ __forceinline__ void mma_bf16(float* d, const uint32_t* a, const uint32_t* b) {
    asm volatile("mma.sync.aligned.m16n8k16.row.col.f32.bf16.bf16.f32 "
        "{%0,%1,%2,%3}, {%4,%5,%6,%7}, {%8,%9}, {%0,%1,%2,%3};"
        : "+f"(d[0]), "+f"(d[1]), "+f"(d[2]), "+f"(d[3])
        : "r"(a[0]), "r"(a[1]), "r"(a[2]), "r"(a[3]), "r"(b[0]), "r"(b[1]));
}

// ---------------- HMMA NT GEMM: C[M,N] = A[M,K] @ B[N,K]^T ----------------
// fp32-split bf16: D = Ahi*Bhi + Ahi*Blo + Alo*Bhi, fp32 accum.
// EPI: 0 = fp32 out, 1 = fp32 out + Res, 2 = gelu -> bf16 hi/lo out
#define NSTG 3
#define KCH  32
#define APITCH 40                      // smem row pitch in elements (80B)
#define MATB  (128 * APITCH * 2)       // 10240 B per matrix per stage
#define STGB  (4 * MATB)               // 40960 B per stage
#define SMEMB (NSTG * STGB)            // 122880 B total

template<int EPI>
__global__ void __launch_bounds__(256) hmma_gemm(
    const __nv_bfloat16* __restrict__ Ahi, const __nv_bfloat16* __restrict__ Alo,
    const __nv_bfloat16* __restrict__ Bhi, const __nv_bfloat16* __restrict__ Blo,
    size_t bstride, const int* __restrict__ tile_e,
    float* __restrict__ C, const float* __restrict__ Res,
    __nv_bfloat16* __restrict__ Chi, __nv_bfloat16* __restrict__ Clo,
    int N, int K)
{
    extern __shared__ char smem[];
    uint32_t sbase = smem_u32(smem);
    int by = blockIdx.y, bx = blockIdx.x;

    const __nv_bfloat16* Bh = Bhi;
    const __nv_bfloat16* Bl = Blo;
    if (tile_e) {
        int e = tile_e[by];
        if (e < 0) return;
        Bh += (size_t)e * bstride;
        Bl += (size_t)e * bstride;
    }

    int tid = threadIdx.x, wid = tid >> 5, lane = tid & 31;
    int warpM = (wid >> 2) * 64, warpN = (wid & 3) * 32;

    // ---- load mapping: 64 rows x 4 chunks of 16B per pass, 2 passes/matrix
    int lrow = tid >> 2;
    int lchk = tid & 3;
    const __nv_bfloat16* pAh0 = Ahi + (size_t)(by * 128 + lrow) * K + lchk * 8;
    const __nv_bfloat16* pAh1 = pAh0 + (size_t)64 * K;
    const __nv_bfloat16* pAl0 = Alo + (size_t)(by * 128 + lrow) * K + lchk * 8;
    const __nv_bfloat16* pAl1 = pAl0 + (size_t)64 * K;
    const __nv_bfloat16* pBh0 = Bh + (size_t)(bx * 128 + lrow) * K + lchk * 8;
    const __nv_bfloat16* pBh1 = pBh0 + (size_t)64 * K;
    const __nv_bfloat16* pBl0 = Bl + (size_t)(bx * 128 + lrow) * K + lchk * 8;
    const __nv_bfloat16* pBl1 = pBl0 + (size_t)64 * K;
    uint32_t so0 = (uint32_t)(lrow * APITCH + lchk * 8) * 2;
    uint32_t so1 = (uint32_t)((lrow + 64) * APITCH + lchk * 8) * 2;

#define LOADST(s_) do { \
        uint32_t sb_ = sbase + ((s_) % NSTG) * STGB; \
        size_t ko_ = (size_t)(s_) * KCH; \
        cpa16(sb_ + so0,            pAh0 + ko_); \
        cpa16(sb_ + so1,            pAh1 + ko_); \
        cpa16(sb_ + MATB + so0,     pAl0 + ko_); \
        cpa16(sb_ + MATB + so1,     pAl1 + ko_); \
        cpa16(sb_ + 2 * MATB + so0, pBh0 + ko_); \
        cpa16(sb_ + 2 * MATB + so1, pBh1 + ko_); \
        cpa16(sb_ + 3 * MATB + so0, pBl0 + ko_); \
        cpa16(sb_ + 3 * MATB + so1, pBl1 + ko_); \
        cp_commit(); \
    } while (0)

    float acc[4][4][4];
#pragma unroll
    for (int i = 0; i < 4; i++)
#pragma unroll
        for (int j = 0; j < 4; j++)
#pragma unroll
            for (int q = 0; q < 4; q++) acc[i][j][q] = 0.f;

    int S = K / KCH;
    LOADST(0);
    LOADST(1);

    // ldmatrix lane address components
    int a_r = lane & 15;                      // row within 16
    int a_k = (lane >> 4) * 8;                // k-half offset
    int b_r = ((lane >> 3) & 1) * 8 + (lane & 7);
    int b_k = (lane >> 4) * 8;

    for (int s = 0; s < S; s++) {
        if (s + 2 < S) { LOADST(s + 2); cp_wait<2>(); }
        else if (s + 1 < S) cp_wait<1>();
        else cp_wait<0>();
        __syncthreads();

        uint32_t sa = sbase + (s % NSTG) * STGB;
#pragma unroll
        for (int ks = 0; ks < 2; ks++) {
            uint32_t ah[4][4], al[4][4], bhf[4][2], blf[4][2];
#pragma unroll
            for (int i = 0; i < 4; i++) {
                uint32_t ad = sa + (uint32_t)((warpM + 16 * i + a_r) * APITCH + ks * 16 + a_k) * 2;
                ldm_x4(ah[i], ad);
                ldm_x4(al[i], ad + MATB);
            }
#pragma unroll
            for (int jj = 0; jj < 2; jj++) {
                uint32_t bd = sa + 2 * MATB +
                    (uint32_t)((warpN + 16 * jj + b_r) * APITCH + ks * 16 + b_k) * 2;
                uint32_t q[4], p[4];
                ldm_x4(q, bd);
                ldm_x4(p, bd + MATB);
                bhf[2 * jj][0] = q[0]; bhf[2 * jj][1] = q[2];
                bhf[2 * jj + 1][0] = q[1]; bhf[2 * jj + 1][1] = q[3];
                blf[2 * jj][0] = p[0]; blf[2 * jj][1] = p[2];
                blf[2 * jj + 1][0] = p[1]; blf[2 * jj + 1][1] = p[3];
            }
#pragma unroll
            for (int i = 0; i < 4; i++)
#pragma unroll
                for (int j = 0; j < 4; j++) {
                    mma_bf16(acc[i][j], ah[i], bhf[j]);
                    mma_bf16(acc[i][j], ah[i], blf[j]);
                    mma_bf16(acc[i][j], al[i], bhf[j]);
                }
        }
        __syncthreads();
    }
#undef LOADST

    // ---- epilogue ----
    int r0 = lane >> 2, c0 = (lane & 3) * 2;
#pragma unroll
    for (int i = 0; i < 4; i++) {
#pragma unroll
        for (int j = 0; j < 4; j++) {
            int row = by * 128 + warpM + 16 * i + r0;
            int col = bx * 128 + warpN + 8 * j + c0;
#pragma unroll
            for (int half = 0; half < 2; half++) {
                size_t off = (size_t)(row + half * 8) * N + col;
                float v0 = acc[i][j][2 * half];
                float v1 = acc[i][j][2 * half + 1];
                if (EPI == 0) {
                    *(float2*)(C + off) = make_float2(v0, v1);
                } else if (EPI == 1) {
                    float2 rr = *(const float2*)(Res + off);
                    *(float2*)(C + off) = make_float2(v0 + rr.x, v1 + rr.y);
                } else {
                    v0 = gelu_f(v0); v1 = gelu_f(v1);
                    __nv_bfloat16 h0 = __float2bfloat16(v0);
                    __nv_bfloat16 h1 = __float2bfloat16(v1);
                    __nv_bfloat16 l0 = __float2bfloat16(v0 - __bfloat162float(h0));
                    __nv_bfloat16 l1 = __float2bfloat16(v1 - __bfloat162float(h1));
                    *(__nv_bfloat162*)(Chi + off) = __halves2bfloat162(h0, h1);
                    *(__nv_bfloat162*)(Clo + off) = __halves2bfloat162(l0, l1);
                }
            }
        }
    }
}

// ---------------- fp32 -> bf16 hi/lo split ----------------
__global__ __launch_bounds__(256) void split_kernel(const float* __restrict__ x,
                                                    __nv_bfloat16* __restrict__ hi,
                                                    __nv_bfloat16* __restrict__ lo, int n4) {
    int i = blockIdx.x * 256 + threadIdx.x;
    if (i >= n4) return;
    float4 v = ((const float4*)x)[i];
    __nv_bfloat16 h0 = __float2bfloat16(v.x), h1 = __float2bfloat16(v.y);
    __nv_bfloat16 h2 = __float2bfloat16(v.z), h3 = __float2bfloat16(v.w);
    __nv_bfloat16 l0 = __float2bfloat16(v.x - __bfloat162float(h0));
    __nv_bfloat16 l1 = __float2bfloat16(v.y - __bfloat162float(h1));
    __nv_bfloat16 l2 = __float2bfloat16(v.z - __bfloat162float(h2));
    __nv_bfloat16 l3 = __float2bfloat16(v.w - __bfloat162float(h3));
    ((__nv_bfloat162*)hi)[2 * i]     = __halves2bfloat162(h0, h1);
    ((__nv_bfloat162*)hi)[2 * i + 1] = __halves2bfloat162(h2, h3);
    ((__nv_bfloat162*)lo)[2 * i]     = __halves2bfloat162(l0, l1);
    ((__nv_bfloat162*)lo)[2 * i + 1] = __halves2bfloat162(l2, l3);
}

// ---------------- LayerNorm (optionally + c broadcast over T) ----------------
template<bool ADDC>
__global__ __launch_bounds__(256) void ln_kernel(const float* __restrict__ x,
                                                 const float* __restrict__ w,
                                                 const float* __restrict__ c,
                                                 float* __restrict__ out) {
    int row = blockIdx.x;
    int tid = threadIdx.x;
    const float* xr = x + (size_t)row * DMODEL;
    float4 v = *(const float4*)(xr + tid * 4);

    __shared__ float red[8];
    __shared__ float tot;

    float s = v.x + v.y + v.z + v.w;
#pragma unroll
    for (int m = 16; m > 0; m >>= 1) s += __shfl_xor_sync(0xffffffffu, s, m);
    if ((tid & 31) == 0) red[tid >> 5] = s;
    __syncthreads();
    if (tid == 0) { float t = 0.f; for (int i = 0; i < 8; i++) t += red[i]; tot = t; }
    __syncthreads();
    float mean = tot * (1.0f / DMODEL);
    float dx = v.x - mean, dy = v.y - mean, dz = v.z - mean, dw = v.w - mean;
    float s2 = dx * dx + dy * dy + dz * dz + dw * dw;
    __syncthreads();
#pragma unroll
    for (int m = 16; m > 0; m >>= 1) s2 += __shfl_xor_sync(0xffffffffu, s2, m);
    if ((tid & 31) == 0) red[tid >> 5] = s2;
    __syncthreads();
    if (tid == 0) { float t = 0.f; for (int i = 0; i < 8; i++) t += red[i]; tot = t; }
    __syncthreads();
    float inv = rsqrtf(tot * (1.0f / DMODEL) + 1e-5f);

    int d0 = tid * 4;
    float4 w4 = *(const float4*)(w + d0);
    float4 r;
    r.x = dx * inv * w4.x;
    r.y = dy * inv * w4.y;
    r.z = dz * inv * w4.z;
    r.w = dw * inv * w4.w;
    if (ADDC) {
        int b = row >> 10;
        float4 c4 = *(const float4*)(c + (size_t)b * DMODEL + d0);
        r.x += c4.x; r.y += c4.y; r.z += c4.z; r.w += c4.w;
    }
    *(float4*)(out + (size_t)row * DMODEL + d0) = r;
}

// ---------------- Flash-style causal attention (fp32 SIMT) ----------------
__global__ __launch_bounds__(256) void attn_kernel(const float* __restrict__ qkv,
                                                   float* __restrict__ o) {
    const int S = 65;
    extern __shared__ float sm[];
    float* Qs = sm;
    float* Ks = Qs + 64 * S;
    float* Vs = Ks + 64 * S;
    float* Ps = Vs + 64 * S;

    int qi = blockIdx.x;
    int bh = blockIdx.y;
    int b = bh >> 4, h = bh & 15;
    int tid = threadIdx.x;
    int tr = tid >> 4, tc = tid & 15;

    const float* base = qkv + (size_t)b * TSEQ * 3072;

#pragma unroll
    for (int k = 0; k < 4; k++) {
        int e = k * 256 + tid;
        int r = e >> 4, c4 = (e & 15) * 4;
        float4 v = *(const float4*)(base + (size_t)(qi * 64 + r) * 3072 + h * 64 + c4);
        float* d = &Qs[r * S + c4];
        d[0] = v.x * 0.125f; d[1] = v.y * 0.125f; d[2] = v.z * 0.125f; d[3] = v.w * 0.125f;
    }

    float m[4], l[4], acc[4][4];
#pragma unroll
    for (int i = 0; i < 4; i++) {
        m[i] = -1e30f; l[i] = 0.f;
#pragma unroll
        for (int j = 0; j < 4; j++) acc[i][j] = 0.f;
    }

    for (int jt = 0; jt <= qi; jt++) {
        __syncthreads();
#pragma unroll
        for (int k = 0; k < 4; k++) {
            int e = k * 256 + tid;
            int r = e >> 4, c4 = (e & 15) * 4;
            size_t rowoff = (size_t)(jt * 64 + r) * 3072 + h * 64 + c4;
            float4 kv = *(const float4*)(base + rowoff + 1024);
            float4 vv = *(const float4*)(base + rowoff + 2048);
            float* dk = &Ks[r * S + c4];
            dk[0] = kv.x; dk[1] = kv.y; dk[2] = kv.z; dk[3] = kv.w;
            float* dv = &Vs[r * S + c4];
            dv[0] = vv.x; dv[1] = vv.y; dv[2] = vv.z; dv[3] = vv.w;
        }
        __syncthreads();

        float s[4][4] = {};
#pragma unroll 8
        for (int kk = 0; kk < 64; kk++) {
            float a0 = Qs[(4 * tr + 0) * S + kk];
            float a1 = Qs[(4 * tr + 1) * S + kk];
            float a2 = Qs[(4 * tr + 2) * S + kk];
            float a3 = Qs[(4 * tr + 3) * S + kk];
            float b0 = Ks[(4 * tc + 0) * S + kk];
            float b1 = Ks[(4 * tc + 1) * S + kk];
            float b2 = Ks[(4 * tc + 2) * S + kk];
            float b3 = Ks[(4 * tc + 3) * S + kk];
            s[0][0] += a0 * b0; s[0][1] += a0 * b1; s[0][2] += a0 * b2; s[0][3] += a0 * b3;
            s[1][0] += a1 * b0; s[1][1] += a1 * b1; s[1][2] += a1 * b2; s[1][3] += a1 * b3;
            s[2][0] += a2 * b0; s[2][1] += a2 * b1; s[2][2] += a2 * b2; s[2][3] += a2 * b3;
            s[3][0] += a3 * b0; s[3][1] += a3 * b1; s[3][2] += a3 * b2; s[3][3] += a3 * b3;
        }

        if (jt == qi) {
#pragma unroll
            for (int i = 0; i < 4; i++) {
                int rg = qi * 64 + 4 * tr + i;
#pragma unroll
                for (int j = 0; j < 4; j++) {
                    int cg = jt * 64 + 4 * tc + j;
                    if (cg > rg) s[i][j] = -1e30f;
                }
            }
        }

#pragma unroll
        for (int i = 0; i < 4; i++) {
            float mt = fmaxf(fmaxf(s[i][0], s[i][1]), fmaxf(s[i][2], s[i][3]));
#pragma unroll
            for (int mm = 8; mm > 0; mm >>= 1)
                mt = fmaxf(mt, __shfl_xor_sync(0xffffffffu, mt, mm));
            float mn = fmaxf(m[i], mt);
            float alpha = expf(m[i] - mn);
            float ls = 0.f;
#pragma unroll
            for (int j = 0; j < 4; j++) {
                float p = expf(s[i][j] - mn);
                s[i][j] = p;
                ls += p;
            }
#pragma unroll
            for (int mm = 8; mm > 0; mm >>= 1)
                ls += __shfl_xor_sync(0xffffffffu, ls, mm);
            l[i] = l[i] * alpha + ls;
            m[i] = mn;
#pragma unroll
            for (int j = 0; j < 4; j++) acc[i][j] *= alpha;
        }

        __syncthreads();
#pragma unroll
        for (int i = 0; i < 4; i++)
#pragma unroll
            for (int j = 0; j < 4; j++)
                Ps[(4 * tr + i) * S + 4 * tc + j] = s[i][j];
        __syncthreads();

#pragma unroll 8
        for (int kk = 0; kk < 64; kk++) {
            float p0 = Ps[(4 * tr + 0) * S + kk];
            float p1 = Ps[(4 * tr + 1) * S + kk];
            float p2 = Ps[(4 * tr + 2) * S + kk];
            float p3 = Ps[(4 * tr + 3) * S + kk];
            float v0 = Vs[kk * S + 4 * tc + 0];
            float v1 = Vs[kk * S + 4 * tc + 1];
            float v2 = Vs[kk * S + 4 * tc + 2];
            float v3 = Vs[kk * S + 4 * tc + 3];
            acc[0][0] += p0 * v0; acc[0][1] += p0 * v1; acc[0][2] += p0 * v2; acc[0][3] += p0 * v3;
            acc[1][0] += p1 * v0; acc[1][1] += p1 * v1; acc[1][2] += p1 * v2; acc[1][3] += p1 * v3;
            acc[2][0] += p2 * v0; acc[2][1] += p2 * v1; acc[2][2] += p2 * v2; acc[2][3] += p2 * v3;
            acc[3][0] += p3 * v0; acc[3][1] += p3 * v1; acc[3][2] += p3 * v2; acc[3][3] += p3 * v3;
        }
    }

#pragma unroll
    for (int i = 0; i < 4; i++) {
        int rg = qi * 64 + 4 * tr + i;
        float invl = 1.0f / l[i];
#pragma unroll
        for (int j = 0; j < 4; j++) {
            o[((size_t)(b * TSEQ + rg)) * DMODEL + h * 64 + 4 * tc + j] = acc[i][j] * invl;
        }
    }
}

// ---------------- router ----------------
__global__ __launch_bounds__(256) void router_kernel(const float* __restrict__ xn,
                                                     const float* __restrict__ rw,
                                                     int* __restrict__ eidx,
                                                     float* __restrict__ wts) {
    int t = blockIdx.x;
    int tid = threadIdx.x, lane = tid & 31, wp = tid >> 5;
    const float* xr = xn + (size_t)t * DMODEL;
    const float* wr = rw + (size_t)wp * DMODEL;
    float s = 0.f;
    for (int d = lane * 4; d < DMODEL; d += 128) {
        float4 a = *(const float4*)(xr + d);
        float4 b = *(const float4*)(wr + d);
        s += a.x * b.x + a.y * b.y + a.z * b.z + a.w * b.w;
    }
#pragma unroll
    for (int mm = 16; mm > 0; mm >>= 1) s += __shfl_xor_sync(0xffffffffu, s, mm);
    __shared__ float lg[8];
    if (lane == 0) lg[wp] = s;
    __syncthreads();
    if (tid == 0) {
        float mx = lg[0];
        for (int e = 1; e < NE; e++) mx = fmaxf(mx, lg[e]);
        float p[NE]; float sum = 0.f;
        for (int e = 0; e < NE; e++) { p[e] = expf(lg[e] - mx); sum += p[e]; }
        float inv = 1.0f / sum;
        for (int e = 0; e < NE; e++) {
            float v = p[e] * inv + 1e-9f;
            p[e] = fminf(fmaxf(v, 1e-9f), 1.0f - 1e-9f);
        }
        int i0 = 0;
        for (int e = 1; e < NE; e++) if (p[e] > p[i0]) i0 = e;
        int i1 = (i0 == 0) ? 1 : 0;
        for (int e = 0; e < NE; e++) if (e != i0 && p[e] > p[i1]) i1 = e;
        float d2 = 1.0f / (p[i0] + p[i1]);
        eidx[2 * t] = i0; eidx[2 * t + 1] = i1;
        wts[2 * t] = p[i0] * d2; wts[2 * t + 1] = p[i1] * d2;
    }
}

// ---------------- build per-expert CSR ----------------
__global__ __launch_bounds__(256) void build_kernel(const int* __restrict__ eidx,
                                                    int* __restrict__ rows,
                                                    int* __restrict__ tile_e) {
    __shared__ int cnt[NE];
    __shared__ int off[NE];
    int tid = threadIdx.x;
    if (tid < NE) cnt[tid] = 0;
    __syncthreads();
    for (int a = tid; a < BT * 2; a += 256) atomicAdd(&cnt[eidx[a]], 1);
    __syncthreads();
    if (tid == 0) {
        int o = 0;
        for (int e = 0; e < NE; e++) { off[e] = o; o = (o + cnt[e] + 127) & ~127; }
        for (int tt = 0; tt < NTILES; tt++) tile_e[tt] = -1;
        for (int e = 0; e < NE; e++) {
            int nt = (cnt[e] + 127) >> 7;
            int t0 = off[e] >> 7;
            for (int i = 0; i < nt; i++) tile_e[t0 + i] = e;
        }
    }
    __syncthreads();
    if (tid < NE) cnt[tid] = 0;
    __syncthreads();
    for (int a = tid; a < BT * 2; a += 256) {
        int e = eidx[a];
        int pos = atomicAdd(&cnt[e], 1);
        rows[a] = off[e] + pos;
    }
}

// ---------------- gather bf16 rows ----------------
__global__ __launch_bounds__(128) void gather_bf(const __nv_bfloat16* __restrict__ xhi,
                                                 const __nv_bfloat16* __restrict__ xlo,
                                                 const int* __restrict__ rows,
                                                 __nv_bfloat16* __restrict__ ghi,
                                                 __nv_bfloat16* __restrict__ glo) {
    int a = blockIdx.x;
    int r = rows[a];
    int t = a >> 1;
    int tid = threadIdx.x;
    ((uint4*)(ghi + (size_t)r * DMODEL))[tid] = ((const uint4*)(xhi + (size_t)t * DMODEL))[tid];
    ((uint4*)(glo + (size_t)r * DMODEL))[tid] = ((const uint4*)(xlo + (size_t)t * DMODEL))[tid];
}

// ---------------- combine ----------------
__global__ __launch_bounds__(256) void combine_kernel(const float* __restrict__ xn,
                                                      const float* __restrict__ eo,
                                                      const int* __restrict__ rows,
                                                      const float* __restrict__ wts,
                                                      float* __restrict__ out) {
    int t = blockIdx.x;
    int r0 = rows[2 * t], r1 = rows[2 * t + 1];
    float w0 = wts[2 * t], w1 = wts[2 * t + 1];
    int tid = threadIdx.x;
    float4 a = *(const float4*)(xn + (size_t)t * DMODEL + tid * 4);
    float4 b = *(const float4*)(eo + (size_t)r0 * DMODEL + tid * 4);
    float4 c = *(const float4*)(eo + (size_t)r1 * DMODEL + tid * 4);
    float4 r;
    r.x = a.x + w0 * b.x + w1 * c.x;
    r.y = a.y + w0 * b.y + w1 * c.y;
    r.z = a.z + w0 * b.z + w1 * c.z;
    r.w = a.w + w0 * b.w + w1 * c.w;
    *(float4*)(out + (size_t)t * DMODEL + tid * 4) = r;
}

// ---------------- host launcher ----------------
extern "C" void kernel_launch(void* const* d_in, const int* in_sizes, int n_in,
                              void* d_out, int out_size) {
    const float* x        = (const float*)d_in[0];
    const float* c        = (const float*)d_in[1];
    const float* ln1_w    = (const float*)d_in[2];
    const float* w_qkv    = (const float*)d_in[3];
    const float* w_proj   = (const float*)d_in[4];
    const float* ln2_w    = (const float*)d_in[5];
    const float* router_w = (const float*)d_in[6];
    const float* ew1      = (const float*)d_in[7];
    const float* ew2      = (const float*)d_in[8];
    float* out = (float*)d_out;

    float *p_h, *p_qkv, *p_o, *p_x2, *p_xn, *p_eo, *p_wts;
    int *p_eidx, *p_rows, *p_te;
    __nv_bfloat16 *p_aHi, *p_aLo, *p_wHi, *p_wLo, *p_xgHi, *p_xgLo, *p_hidHi, *p_hidLo;
    cudaGetSymbolAddress((void**)&p_h,     g_h);
    cudaGetSymbolAddress((void**)&p_qkv,   g_qkv);
    cudaGetSymbolAddress((void**)&p_o,     g_o);
    cudaGetSymbolAddress((void**)&p_x2,    g_x2);
    cudaGetSymbolAddress((void**)&p_xn,    g_xn);
    cudaGetSymbolAddress((void**)&p_eo,    g_eo);
    cudaGetSymbolAddress((void**)&p_wts,   g_wts);
    cudaGetSymbolAddress((void**)&p_eidx,  g_eidx);
    cudaGetSymbolAddress((void**)&p_rows,  g_rows);
    cudaGetSymbolAddress((void**)&p_te,    g_tile_e);
    cudaGetSymbolAddress((void**)&p_aHi,   g_aHi);
    cudaGetSymbolAddress((void**)&p_aLo,   g_aLo);
    cudaGetSymbolAddress((void**)&p_wHi,   g_wHi);
    cudaGetSymbolAddress((void**)&p_wLo,   g_wLo);
    cudaGetSymbolAddress((void**)&p_xgHi,  g_xgHi);
    cudaGetSymbolAddress((void**)&p_xgLo,  g_xgLo);
    cudaGetSymbolAddress((void**)&p_hidHi, g_hidHi);
    cudaGetSymbolAddress((void**)&p_hidLo, g_hidLo);

    cudaFuncSetAttribute(hmma_gemm<0>, cudaFuncAttributeMaxDynamicSharedMemorySize, SMEMB);
    cudaFuncSetAttribute(hmma_gemm<1>, cudaFuncAttributeMaxDynamicSharedMemorySize, SMEMB);
    cudaFuncSetAttribute(hmma_gemm<2>, cudaFuncAttributeMaxDynamicSharedMemorySize, SMEMB);

    // 1) h = LN1(x)*w + c ; split to bf16
    ln_kernel<true><<<BT, 256>>>(x, ln1_w, c, p_h);
    split_kernel<<<(BT * DMODEL / 4 + 255) / 256, 256>>>(p_h, p_aHi, p_aLo, BT * DMODEL / 4);
    split_kernel<<<(3 * DMODEL * DMODEL / 4 + 255) / 256, 256>>>(w_qkv, p_wHi, p_wLo, 3 * DMODEL * DMODEL / 4);

    // 2) qkv = h @ w_qkv^T
    hmma_gemm<0><<<dim3(24, 32), 256, SMEMB>>>(p_aHi, p_aLo, p_wHi, p_wLo, 0, nullptr,
                                               p_qkv, nullptr, nullptr, nullptr, 3072, 1024);

    // 3) causal attention
    int attn_smem = 4 * 64 * 65 * (int)sizeof(float);
    cudaFuncSetAttribute(attn_kernel, cudaFuncAttributeMaxDynamicSharedMemorySize, attn_smem);
    attn_kernel<<<dim3(16, 64), 256, attn_smem>>>(p_qkv, p_o);

    // 4) x2 = x + o @ w_proj^T
    split_kernel<<<(BT * DMODEL / 4 + 255) / 256, 256>>>(p_o, p_aHi, p_aLo, BT * DMODEL / 4);
    split_kernel<<<(DMODEL * DMODEL / 4 + 255) / 256, 256>>>(w_proj, p_wHi, p_wLo, DMODEL * DMODEL / 4);
    hmma_gemm<1><<<dim3(8, 32), 256, SMEMB>>>(p_aHi, p_aLo, p_wHi, p_wLo, 0, nullptr,
                                              p_x2, x, nullptr, nullptr, 1024, 1024);

    // 5) xn = LN2(x2)
    ln_kernel<false><<<BT, 256>>>(p_x2, ln2_w, nullptr, p_xn);

    // 6) router + CSR
    router_kernel<<<BT, 256>>>(p_xn, router_w, p_eidx, p_wts);
    build_kernel<<<1, 256>>>(p_eidx, p_rows, p_te);

    // 7) split xn, gather bf16
    split_kernel<<<(BT * DMODEL / 4 + 255) / 256, 256>>>(p_xn, p_aHi, p_aLo, BT * DMODEL / 4);
    gather_bf<<<BT * 2, 128>>>(p_aHi, p_aLo, p_rows, p_xgHi, p_xgLo);

    // 8) hid = gelu(xg @ w1[e]^T), bf16 hi/lo out
    split_kernel<<<(NE * FF * DMODEL / 4 + 255) / 256, 256>>>(ew1, p_wHi, p_wLo, NE * FF * DMODEL / 4);
    hmma_gemm<2><<<dim3(32, NTILES), 256, SMEMB>>>(p_xgHi, p_xgLo, p_wHi, p_wLo,
                                                   (size_t)FF * DMODEL, p_te,
                                                   nullptr, nullptr, p_hidHi, p_hidLo, FF, 1024);

    // 9) eo = hid @ w2[e]^T
    split_kernel<<<(NE * DMODEL * FF / 4 + 255) / 256, 256>>>(ew2, p_wHi, p_wLo, NE * DMODEL * FF / 4);
    hmma_gemm<0><<<dim3(8, NTILES), 256, SMEMB>>>(p_hidHi, p_hidLo, p_wHi, p_wLo,
                                                  (size_t)DMODEL * FF, p_te,
                                                  p_eo, nullptr, nullptr, nullptr, 1024, 4096);

    // 10) out = xn + sum_k w_k * eo
    combine_kernel<<<BT, 256>>>(p_xn, p_eo, p_rows, p_wts, out);
}

// round 4
// speedup vs baseline: 2.1612x; 1.1280x over previous
#include <cuda_runtime.h>
#include <cuda_bf16.h>
#include <math.h>
#include <stdint.h>

// Problem dims
#define BATCH 4
#define TSEQ  1024
#define BT    4096
#define DMODEL 1024
#define NE    8
#define FF    4096
#define CAP   9216          // 72 * 128 row capacity for grouped MoE GEMMs
#define NTILES 72

// ---------------- static device scratch ----------------
__device__ float g_h  [BT * DMODEL];
__device__ float g_qkv[BT * 3 * DMODEL];
__device__ float g_o  [BT * DMODEL];
__device__ float g_x2 [BT * DMODEL];
__device__ float g_xn [BT * DMODEL];
__device__ float g_eo [CAP * DMODEL];
__device__ int   g_eidx[BT * 2];
__device__ float g_wts [BT * 2];
__device__ int   g_rows[BT * 2];
__device__ int   g_tile_e[NTILES];

// bf16 hi/lo split scratch
__device__ __nv_bfloat16 g_aHi [BT * DMODEL];
__device__ __nv_bfloat16 g_aLo [BT * DMODEL];
__device__ __nv_bfloat16 g_wHi [NE * FF * DMODEL];
__device__ __nv_bfloat16 g_wLo [NE * FF * DMODEL];
__device__ __nv_bfloat16 g_xgHi[CAP * DMODEL];
__device__ __nv_bfloat16 g_xgLo[CAP * DMODEL];
__device__ __nv_bfloat16 g_hidHi[CAP * FF];
__device__ __nv_bfloat16 g_hidLo[CAP * FF];

__device__ __forceinline__ float gelu_f(float v) {
    return 0.5f * v * (1.0f + erff(v * 0.70710678118654752f));
}

// ---------------- PTX helpers (sm_80+ portable; NO tcgen05) ----------------
__device__ __forceinline__ uint32_t smem_u32(const void* p) {
    uint32_t a;
    asm("{ .reg .u64 t; cvta.to.shared.u64 t, %1; cvt.u32.u64 %0, t; }" : "=r"(a) : "l"(p));
    return a;
}
__device__ __forceinline__ void cpa16(uint32_t dst, const void* src) {
    asm volatile("cp.async.cg.shared.global [%0], [%1], 16;" :: "r"(dst), "l"(src));
}
__device__ __forceinline__ void cp_commit() { asm volatile("cp.async.commit_group;" ::: "memory"); }
template<int NPEND> __device__ __forceinline__ void cp_wait() {
    asm volatile("cp.async.wait_group %0;" :: "n"(NPEND) : "memory");
}
__device__ __forceinline__ void ldm_x4(uint32_t* r, uint32_t a) {
    asm volatile("ldmatrix.sync.aligned.m8n8.x4.shared.b16 {%0,%1,%2,%3}, [%4];"
        : "=r"(r[0]), "=r"(r[1]), "=r"(r[2]), "=r"(r[3]) : "r"(a));
}
__device__ __forceinline__ void mma_bf16(float* d, const uint32_t* a, const uint32_t* b) {
    asm volatile("mma.sync.aligned.m16n8k16.row.col.f32.bf16.bf16.f32 "
        "{%0,%1,%2,%3}, {%4,%5,%6,%7}, {%8,%9}, {%0,%1,%2,%3};"
        : "+f"(d[0]), "+f"(d[1]), "+f"(d[2]), "+f"(d[3])
        : "r"(a[0]), "r"(a[1]), "r"(a[2]), "r"(a[3]), "r"(b[0]), "r"(b[1]));
}

// ---------------- HMMA NT GEMM: C[M,N] = A[M,K] @ B[N,K]^T ----------------
// fp32-split bf16: D = Ahi*Bhi + Ahi*Blo + Alo*Bhi, fp32 accum.
// EPI: 0 = fp32 out, 1 = fp32 out + Res, 2 = gelu -> bf16 hi/lo out
#define NSTG 2
#define KCH  32
#define APITCH 40                      // smem row pitch in elements (80B)
#define MATB  (128 * APITCH * 2)       // 10240 B per matrix per stage
#define STGB  (4 * MATB)               // 40960 B per stage
#define SMEMB (NSTG * STGB)            // 81920 B total -> 2 CTAs/SM

template<int EPI>
__global__ void __launch_bounds__(256, 2) hmma_gemm(
    const __nv_bfloat16* __restrict__ Ahi, const __nv_bfloat16* __restrict__ Alo,
    const __nv_bfloat16* __restrict__ Bhi, const __nv_bfloat16* __restrict__ Blo,
    size_t bstride, const int* __restrict__ tile_e,
    float* __restrict__ C, const float* __restrict__ Res,
    __nv_bfloat16* __restrict__ Chi, __nv_bfloat16* __restrict__ Clo,
    int N, int K)
{
    extern __shared__ char smem[];
    uint32_t sbase = smem_u32(smem);
    int by = blockIdx.y, bx = blockIdx.x;

    const __nv_bfloat16* Bh = Bhi;
    const __nv_bfloat16* Bl = Blo;
    if (tile_e) {
        int e = tile_e[by];
        if (e < 0) return;
        Bh += (size_t)e * bstride;
        Bl += (size_t)e * bstride;
    }

    int tid = threadIdx.x, wid = tid >> 5, lane = tid & 31;
    int warpM = (wid >> 2) * 64, warpN = (wid & 3) * 32;

    // ---- load mapping: 64 rows x 4 chunks of 16B per pass, 2 passes/matrix
    int lrow = tid >> 2;
    int lchk = tid & 3;
    const __nv_bfloat16* pAh0 = Ahi + (size_t)(by * 128 + lrow) * K + lchk * 8;
    const __nv_bfloat16* pAh1 = pAh0 + (size_t)64 * K;
    const __nv_bfloat16* pAl0 = Alo + (size_t)(by * 128 + lrow) * K + lchk * 8;
    const __nv_bfloat16* pAl1 = pAl0 + (size_t)64 * K;
    const __nv_bfloat16* pBh0 = Bh + (size_t)(bx * 128 + lrow) * K + lchk * 8;
    const __nv_bfloat16* pBh1 = pBh0 + (size_t)64 * K;
    const __nv_bfloat16* pBl0 = Bl + (size_t)(bx * 128 + lrow) * K + lchk * 8;
    const __nv_bfloat16* pBl1 = pBl0 + (size_t)64 * K;
    uint32_t so0 = (uint32_t)(lrow * APITCH + lchk * 8) * 2;
    uint32_t so1 = (uint32_t)((lrow + 64) * APITCH + lchk * 8) * 2;

#define LOADST(s_) do { \
        uint32_t sb_ = sbase + ((s_) & 1) * STGB; \
        size_t ko_ = (size_t)(s_) * KCH; \
        cpa16(sb_ + so0,            pAh0 + ko_); \
        cpa16(sb_ + so1,            pAh1 + ko_); \
        cpa16(sb_ + MATB + so0,     pAl0 + ko_); \
        cpa16(sb_ + MATB + so1,     pAl1 + ko_); \
        cpa16(sb_ + 2 * MATB + so0, pBh0 + ko_); \
        cpa16(sb_ + 2 * MATB + so1, pBh1 + ko_); \
        cpa16(sb_ + 3 * MATB + so0, pBl0 + ko_); \
        cpa16(sb_ + 3 * MATB + so1, pBl1 + ko_); \
        cp_commit(); \
    } while (0)

    float acc[4][4][4];
#pragma unroll
    for (int i = 0; i < 4; i++)
#pragma unroll
        for (int j = 0; j < 4; j++)
#pragma unroll
            for (int q = 0; q < 4; q++) acc[i][j][q] = 0.f;

    int S = K / KCH;
    LOADST(0);

    // ldmatrix lane address components
    int a_r = lane & 15;                      // row within 16
    int a_k = (lane >> 4) * 8;                // k-half offset
    int b_r = ((lane >> 3) & 1) * 8 + (lane & 7);
    int b_k = (lane >> 4) * 8;

    for (int s = 0; s < S; s++) {
        cp_wait<0>();          // stage s data has landed
        __syncthreads();       // also separates compute(s-1) reads from the overwrite below
        if (s + 1 < S) LOADST(s + 1);

        uint32_t sa = sbase + (s & 1) * STGB;
#pragma unroll
        for (int ks = 0; ks < 2; ks++) {
            uint32_t ah[4][4], al[4][4], bhf[4][2], blf[4][2];
#pragma unroll
            for (int i = 0; i < 4; i++) {
                uint32_t ad = sa + (uint32_t)((warpM + 16 * i + a_r) * APITCH + ks * 16 + a_k) * 2;
                ldm_x4(ah[i], ad);
                ldm_x4(al[i], ad + MATB);
            }
#pragma unroll
            for (int jj = 0; jj < 2; jj++) {
                uint32_t bd = sa + 2 * MATB +
                    (uint32_t)((warpN + 16 * jj + b_r) * APITCH + ks * 16 + b_k) * 2;
                uint32_t q[4], p[4];
                ldm_x4(q, bd);
                ldm_x4(p, bd + MATB);
                bhf[2 * jj][0] = q[0]; bhf[2 * jj][1] = q[2];
                bhf[2 * jj + 1][0] = q[1]; bhf[2 * jj + 1][1] = q[3];
                blf[2 * jj][0] = p[0]; blf[2 * jj][1] = p[2];
                blf[2 * jj + 1][0] = p[1]; blf[2 * jj + 1][1] = p[3];
            }
            // 3 independent passes: accumulator reuse distance = 16 MMAs (no RAW chain)
#pragma unroll
            for (int i = 0; i < 4; i++)
#pragma unroll
                for (int j = 0; j < 4; j++)
                    mma_bf16(acc[i][j], ah[i], bhf[j]);
#pragma unroll
            for (int i = 0; i < 4; i++)
#pragma unroll
                for (int j = 0; j < 4; j++)
                    mma_bf16(acc[i][j], ah[i], blf[j]);
#pragma unroll
            for (int i = 0; i < 4; i++)
#pragma unroll
                for (int j = 0; j < 4; j++)
                    mma_bf16(acc[i][j], al[i], bhf[j]);
        }
    }
#undef LOADST

    // ---- epilogue ----
    int r0 = lane >> 2, c0 = (lane & 3) * 2;
#pragma unroll
    for (int i = 0; i < 4; i++) {
#pragma unroll
        for (int j = 0; j < 4; j++) {
            int row = by * 128 + warpM + 16 * i + r0;
            int col = bx * 128 + warpN + 8 * j + c0;
#pragma unroll
            for (int half = 0; half < 2; half++) {
                size_t off = (size_t)(row + half * 8) * N + col;
                float v0 = acc[i][j][2 * half];
                float v1 = acc[i][j][2 * half + 1];
                if (EPI == 0) {
                    *(float2*)(C + off) = make_float2(v0, v1);
                } else if (EPI == 1) {
                    float2 rr = *(const float2*)(Res + off);
                    *(float2*)(C + off) = make_float2(v0 + rr.x, v1 + rr.y);
                } else {
                    v0 = gelu_f(v0); v1 = gelu_f(v1);
                    __nv_bfloat16 h0 = __float2bfloat16(v0);
                    __nv_bfloat16 h1 = __float2bfloat16(v1);
                    __nv_bfloat16 l0 = __float2bfloat16(v0 - __bfloat162float(h0));
                    __nv_bfloat16 l1 = __float2bfloat16(v1 - __bfloat162float(h1));
                    *(__nv_bfloat162*)(Chi + off) = __halves2bfloat162(h0, h1);
                    *(__nv_bfloat162*)(Clo + off) = __halves2bfloat162(l0, l1);
                }
            }
        }
    }
}

// ---------------- fp32 -> bf16 hi/lo split ----------------
__global__ __launch_bounds__(256) void split_kernel(const float* __restrict__ x,
                                                    __nv_bfloat16* __restrict__ hi,
                                                    __nv_bfloat16* __restrict__ lo, int n4) {
    int i = blockIdx.x * 256 + threadIdx.x;
    if (i >= n4) return;
    float4 v = ((const float4*)x)[i];
    __nv_bfloat16 h0 = __float2bfloat16(v.x), h1 = __float2bfloat16(v.y);
    __nv_bfloat16 h2 = __float2bfloat16(v.z), h3 = __float2bfloat16(v.w);
    __nv_bfloat16 l0 = __float2bfloat16(v.x - __bfloat162float(h0));
    __nv_bfloat16 l1 = __float2bfloat16(v.y - __bfloat162float(h1));
    __nv_bfloat16 l2 = __float2bfloat16(v.z - __bfloat162float(h2));
    __nv_bfloat16 l3 = __float2bfloat16(v.w - __bfloat162float(h3));
    ((__nv_bfloat162*)hi)[2 * i]     = __halves2bfloat162(h0, h1);
    ((__nv_bfloat162*)hi)[2 * i + 1] = __halves2bfloat162(h2, h3);
    ((__nv_bfloat162*)lo)[2 * i]     = __halves2bfloat162(l0, l1);
    ((__nv_bfloat162*)lo)[2 * i + 1] = __halves2bfloat162(l2, l3);
}

// ---------------- LayerNorm (optionally + c broadcast over T) ----------------
template<bool ADDC>
__global__ __launch_bounds__(256) void ln_kernel(const float* __restrict__ x,
                                                 const float* __restrict__ w,
                                                 const float* __restrict__ c,
                                                 float* __restrict__ out) {
    int row = blockIdx.x;
    int tid = threadIdx.x;
    const float* xr = x + (size_t)row * DMODEL;
    float4 v = *(const float4*)(xr + tid * 4);

    __shared__ float red[8];
    __shared__ float tot;

    float s = v.x + v.y + v.z + v.w;
#pragma unroll
    for (int m = 16; m > 0; m >>= 1) s += __shfl_xor_sync(0xffffffffu, s, m);
    if ((tid & 31) == 0) red[tid >> 5] = s;
    __syncthreads();
    if (tid == 0) { float t = 0.f; for (int i = 0; i < 8; i++) t += red[i]; tot = t; }
    __syncthreads();
    float mean = tot * (1.0f / DMODEL);
    float dx = v.x - mean, dy = v.y - mean, dz = v.z - mean, dw = v.w - mean;
    float s2 = dx * dx + dy * dy + dz * dz + dw * dw;
    __syncthreads();
#pragma unroll
    for (int m = 16; m > 0; m >>= 1) s2 += __shfl_xor_sync(0xffffffffu, s2, m);
    if ((tid & 31) == 0) red[tid >> 5] = s2;
    __syncthreads();
    if (tid == 0) { float t = 0.f; for (int i = 0; i < 8; i++) t += red[i]; tot = t; }
    __syncthreads();
    float inv = rsqrtf(tot * (1.0f / DMODEL) + 1e-5f);

    int d0 = tid * 4;
    float4 w4 = *(const float4*)(w + d0);
    float4 r;
    r.x = dx * inv * w4.x;
    r.y = dy * inv * w4.y;
    r.z = dz * inv * w4.z;
    r.w = dw * inv * w4.w;
    if (ADDC) {
        int b = row >> 10;
        float4 c4 = *(const float4*)(c + (size_t)b * DMODEL + d0);
        r.x += c4.x; r.y += c4.y; r.z += c4.z; r.w += c4.w;
    }
    *(float4*)(out + (size_t)row * DMODEL + d0) = r;
}

// ---------------- Flash-style causal attention (fp32 SIMT) ----------------
__global__ __launch_bounds__(256) void attn_kernel(const float* __restrict__ qkv,
                                                   float* __restrict__ o) {
    const int S = 65;
    extern __shared__ float sm[];
    float* Qs = sm;
    float* Ks = Qs + 64 * S;
    float* Vs = Ks + 64 * S;
    float* Ps = Vs + 64 * S;

    int qi = blockIdx.x;
    int bh = blockIdx.y;
    int b = bh >> 4, h = bh & 15;
    int tid = threadIdx.x;
    int tr = tid >> 4, tc = tid & 15;

    const float* base = qkv + (size_t)b * TSEQ * 3072;

#pragma unroll
    for (int k = 0; k < 4; k++) {
        int e = k * 256 + tid;
        int r = e >> 4, c4 = (e & 15) * 4;
        float4 v = *(const float4*)(base + (size_t)(qi * 64 + r) * 3072 + h * 64 + c4);
        float* d = &Qs[r * S + c4];
        d[0] = v.x * 0.125f; d[1] = v.y * 0.125f; d[2] = v.z * 0.125f; d[3] = v.w * 0.125f;
    }

    float m[4], l[4], acc[4][4];
#pragma unroll
    for (int i = 0; i < 4; i++) {
        m[i] = -1e30f; l[i] = 0.f;
#pragma unroll
        for (int j = 0; j < 4; j++) acc[i][j] = 0.f;
    }

    for (int jt = 0; jt <= qi; jt++) {
        __syncthreads();
#pragma unroll
        for (int k = 0; k < 4; k++) {
            int e = k * 256 + tid;
            int r = e >> 4, c4 = (e & 15) * 4;
            size_t rowoff = (size_t)(jt * 64 + r) * 3072 + h * 64 + c4;
            float4 kv = *(const float4*)(base + rowoff + 1024);
            float4 vv = *(const float4*)(base + rowoff + 2048);
            float* dk = &Ks[r * S + c4];
            dk[0] = kv.x; dk[1] = kv.y; dk[2] = kv.z; dk[3] = kv.w;
            float* dv = &Vs[r * S + c4];
            dv[0] = vv.x; dv[1] = vv.y; dv[2] = vv.z; dv[3] = vv.w;
        }
        __syncthreads();

        float s[4][4] = {};
#pragma unroll 8
        for (int kk = 0; kk < 64; kk++) {
            float a0 = Qs[(4 * tr + 0) * S + kk];
            float a1 = Qs[(4 * tr + 1) * S + kk];
            float a2 = Qs[(4 * tr + 2) * S + kk];
            float a3 = Qs[(4 * tr + 3) * S + kk];
            float b0 = Ks[(4 * tc + 0) * S + kk];
            float b1 = Ks[(4 * tc + 1) * S + kk];
            float b2 = Ks[(4 * tc + 2) * S + kk];
            float b3 = Ks[(4 * tc + 3) * S + kk];
            s[0][0] += a0 * b0; s[0][1] += a0 * b1; s[0][2] += a0 * b2; s[0][3] += a0 * b3;
            s[1][0] += a1 * b0; s[1][1] += a1 * b1; s[1][2] += a1 * b2; s[1][3] += a1 * b3;
            s[2][0] += a2 * b0; s[2][1] += a2 * b1; s[2][2] += a2 * b2; s[2][3] += a2 * b3;
            s[3][0] += a3 * b0; s[3][1] += a3 * b1; s[3][2] += a3 * b2; s[3][3] += a3 * b3;
        }

        if (jt == qi) {
#pragma unroll
            for (int i = 0; i < 4; i++) {
                int rg = qi * 64 + 4 * tr + i;
#pragma unroll
                for (int j = 0; j < 4; j++) {
                    int cg = jt * 64 + 4 * tc + j;
                    if (cg > rg) s[i][j] = -1e30f;
                }
            }
        }

#pragma unroll
        for (int i = 0; i < 4; i++) {
            float mt = fmaxf(fmaxf(s[i][0], s[i][1]), fmaxf(s[i][2], s[i][3]));
#pragma unroll
            for (int mm = 8; mm > 0; mm >>= 1)
                mt = fmaxf(mt, __shfl_xor_sync(0xffffffffu, mt, mm));
            float mn = fmaxf(m[i], mt);
            float alpha = expf(m[i] - mn);
            float ls = 0.f;
#pragma unroll
            for (int j = 0; j < 4; j++) {
                float p = expf(s[i][j] - mn);
                s[i][j] = p;
                ls += p;
            }
#pragma unroll
            for (int mm = 8; mm > 0; mm >>= 1)
                ls += __shfl_xor_sync(0xffffffffu, ls, mm);
            l[i] = l[i] * alpha + ls;
            m[i] = mn;
#pragma unroll
            for (int j = 0; j < 4; j++) acc[i][j] *= alpha;
        }

        __syncthreads();
#pragma unroll
        for (int i = 0; i < 4; i++)
#pragma unroll
            for (int j = 0; j < 4; j++)
                Ps[(4 * tr + i) * S + 4 * tc + j] = s[i][j];
        __syncthreads();

#pragma unroll 8
        for (int kk = 0; kk < 64; kk++) {
            float p0 = Ps[(4 * tr + 0) * S + kk];
            float p1 = Ps[(4 * tr + 1) * S + kk];
            float p2 = Ps[(4 * tr + 2) * S + kk];
            float p3 = Ps[(4 * tr + 3) * S + kk];
            float v0 = Vs[kk * S + 4 * tc + 0];
            float v1 = Vs[kk * S + 4 * tc + 1];
            float v2 = Vs[kk * S + 4 * tc + 2];
            float v3 = Vs[kk * S + 4 * tc + 3];
            acc[0][0] += p0 * v0; acc[0][1] += p0 * v1; acc[0][2] += p0 * v2; acc[0][3] += p0 * v3;
            acc[1][0] += p1 * v0; acc[1][1] += p1 * v1; acc[1][2] += p1 * v2; acc[1][3] += p1 * v3;
            acc[2][0] += p2 * v0; acc[2][1] += p2 * v1; acc[2][2] += p2 * v2; acc[2][3] += p2 * v3;
            acc[3][0] += p3 * v0; acc[3][1] += p3 * v1; acc[3][2] += p3 * v2; acc[3][3] += p3 * v3;
        }
    }

#pragma unroll
    for (int i = 0; i < 4; i++) {
        int rg = qi * 64 + 4 * tr + i;
        float invl = 1.0f / l[i];
#pragma unroll
        for (int j = 0; j < 4; j++) {
            o[((size_t)(b * TSEQ + rg)) * DMODEL + h * 64 + 4 * tc + j] = acc[i][j] * invl;
        }
    }
}

// ---------------- router ----------------
__global__ __launch_bounds__(256) void router_kernel(const float* __restrict__ xn,
                                                     const float* __restrict__ rw,
                                                     int* __restrict__ eidx,
                                                     float* __restrict__ wts) {
    int t = blockIdx.x;
    int tid = threadIdx.x, lane = tid & 31, wp = tid >> 5;
    const float* xr = xn + (size_t)t * DMODEL;
    const float* wr = rw + (size_t)wp * DMODEL;
    float s = 0.f;
    for (int d = lane * 4; d < DMODEL; d += 128) {
        float4 a = *(const float4*)(xr + d);
        float4 b = *(const float4*)(wr + d);
        s += a.x * b.x + a.y * b.y + a.z * b.z + a.w * b.w;
    }
#pragma unroll
    for (int mm = 16; mm > 0; mm >>= 1) s += __shfl_xor_sync(0xffffffffu, s, mm);
    __shared__ float lg[8];
    if (lane == 0) lg[wp] = s;
    __syncthreads();
    if (tid == 0) {
        float mx = lg[0];
        for (int e = 1; e < NE; e++) mx = fmaxf(mx, lg[e]);
        float p[NE]; float sum = 0.f;
        for (int e = 0; e < NE; e++) { p[e] = expf(lg[e] - mx); sum += p[e]; }
        float inv = 1.0f / sum;
        for (int e = 0; e < NE; e++) {
            float v = p[e] * inv + 1e-9f;
            p[e] = fminf(fmaxf(v, 1e-9f), 1.0f - 1e-9f);
        }
        int i0 = 0;
        for (int e = 1; e < NE; e++) if (p[e] > p[i0]) i0 = e;
        int i1 = (i0 == 0) ? 1 : 0;
        for (int e = 0; e < NE; e++) if (e != i0 && p[e] > p[i1]) i1 = e;
        float d2 = 1.0f / (p[i0] + p[i1]);
        eidx[2 * t] = i0; eidx[2 * t + 1] = i1;
        wts[2 * t] = p[i0] * d2; wts[2 * t + 1] = p[i1] * d2;
    }
}

// ---------------- build per-expert CSR ----------------
__global__ __launch_bounds__(256) void build_kernel(const int* __restrict__ eidx,
                                                    int* __restrict__ rows,
                                                    int* __restrict__ tile_e) {
    __shared__ int cnt[NE];
    __shared__ int off[NE];
    int tid = threadIdx.x;
    if (tid < NE) cnt[tid] = 0;
    __syncthreads();
    for (int a = tid; a < BT * 2; a += 256) atomicAdd(&cnt[eidx[a]], 1);
    __syncthreads();
    if (tid == 0) {
        int o = 0;
        for (int e = 0; e < NE; e++) { off[e] = o; o = (o + cnt[e] + 127) & ~127; }
        for (int tt = 0; tt < NTILES; tt++) tile_e[tt] = -1;
        for (int e = 0; e < NE; e++) {
            int nt = (cnt[e] + 127) >> 7;
            int t0 = off[e] >> 7;
            for (int i = 0; i < nt; i++) tile_e[t0 + i] = e;
        }
    }
    __syncthreads();
    if (tid < NE) cnt[tid] = 0;
    __syncthreads();
    for (int a = tid; a < BT * 2; a += 256) {
        int e = eidx[a];
        int pos = atomicAdd(&cnt[e], 1);
        rows[a] = off[e] + pos;
    }
}

// ---------------- gather bf16 rows ----------------
__global__ __launch_bounds__(128) void gather_bf(const __nv_bfloat16* __restrict__ xhi,
                                                 const __nv_bfloat16* __restrict__ xlo,
                                                 const int* __restrict__ rows,
                                                 __nv_bfloat16* __restrict__ ghi,
                                                 __nv_bfloat16* __restrict__ glo) {
    int a = blockIdx.x;
    int r = rows[a];
    int t = a >> 1;
    int tid = threadIdx.x;
    ((uint4*)(ghi + (size_t)r * DMODEL))[tid] = ((const uint4*)(xhi + (size_t)t * DMODEL))[tid];
    ((uint4*)(glo + (size_t)r * DMODEL))[tid] = ((const uint4*)(xlo + (size_t)t * DMODEL))[tid];
}

// ---------------- combine ----------------
__global__ __launch_bounds__(256) void combine_kernel(const float* __restrict__ xn,
                                                      const float* __restrict__ eo,
                                                      const int* __restrict__ rows,
                                                      const float* __restrict__ wts,
                                                      float* __restrict__ out) {
    int t = blockIdx.x;
    int r0 = rows[2 * t], r1 = rows[2 * t + 1];
    float w0 = wts[2 * t], w1 = wts[2 * t + 1];
    int tid = threadIdx.x;
    float4 a = *(const float4*)(xn + (size_t)t * DMODEL + tid * 4);
    float4 b = *(const float4*)(eo + (size_t)r0 * DMODEL + tid * 4);
    float4 c = *(const float4*)(eo + (size_t)r1 * DMODEL + tid * 4);
    float4 r;
    r.x = a.x + w0 * b.x + w1 * c.x;
    r.y = a.y + w0 * b.y + w1 * c.y;
    r.z = a.z + w0 * b.z + w1 * c.z;
    r.w = a.w + w0 * b.w + w1 * c.w;
    *(float4*)(out + (size_t)t * DMODEL + tid * 4) = r;
}

// ---------------- host launcher ----------------
extern "C" void kernel_launch(void* const* d_in, const int* in_sizes, int n_in,
                              void* d_out, int out_size) {
    const float* x        = (const float*)d_in[0];
    const float* c        = (const float*)d_in[1];
    const float* ln1_w    = (const float*)d_in[2];
    const float* w_qkv    = (const float*)d_in[3];
    const float* w_proj   = (const float*)d_in[4];
    const float* ln2_w    = (const float*)d_in[5];
    const float* router_w = (const float*)d_in[6];
    const float* ew1      = (const float*)d_in[7];
    const float* ew2      = (const float*)d_in[8];
    float* out = (float*)d_out;

    float *p_h, *p_qkv, *p_o, *p_x2, *p_xn, *p_eo, *p_wts;
    int *p_eidx, *p_rows, *p_te;
    __nv_bfloat16 *p_aHi, *p_aLo, *p_wHi, *p_wLo, *p_xgHi, *p_xgLo, *p_hidHi, *p_hidLo;
    cudaGetSymbolAddress((void**)&p_h,     g_h);
    cudaGetSymbolAddress((void**)&p_qkv,   g_qkv);
    cudaGetSymbolAddress((void**)&p_o,     g_o);
    cudaGetSymbolAddress((void**)&p_x2,    g_x2);
    cudaGetSymbolAddress((void**)&p_xn,    g_xn);
    cudaGetSymbolAddress((void**)&p_eo,    g_eo);
    cudaGetSymbolAddress((void**)&p_wts,   g_wts);
    cudaGetSymbolAddress((void**)&p_eidx,  g_eidx);
    cudaGetSymbolAddress((void**)&p_rows,  g_rows);
    cudaGetSymbolAddress((void**)&p_te,    g_tile_e);
    cudaGetSymbolAddress((void**)&p_aHi,   g_aHi);
    cudaGetSymbolAddress((void**)&p_aLo,   g_aLo);
    cudaGetSymbolAddress((void**)&p_wHi,   g_wHi);
    cudaGetSymbolAddress((void**)&p_wLo,   g_wLo);
    cudaGetSymbolAddress((void**)&p_xgHi,  g_xgHi);
    cudaGetSymbolAddress((void**)&p_xgLo,  g_xgLo);
    cudaGetSymbolAddress((void**)&p_hidHi, g_hidHi);
    cudaGetSymbolAddress((void**)&p_hidLo, g_hidLo);

    cudaFuncSetAttribute(hmma_gemm<0>, cudaFuncAttributeMaxDynamicSharedMemorySize, SMEMB);
    cudaFuncSetAttribute(hmma_gemm<1>, cudaFuncAttributeMaxDynamicSharedMemorySize, SMEMB);
    cudaFuncSetAttribute(hmma_gemm<2>, cudaFuncAttributeMaxDynamicSharedMemorySize, SMEMB);

    // 1) h = LN1(x)*w + c ; split to bf16
    ln_kernel<true><<<BT, 256>>>(x, ln1_w, c, p_h);
    split_kernel<<<(BT * DMODEL / 4 + 255) / 256, 256>>>(p_h, p_aHi, p_aLo, BT * DMODEL / 4);
    split_kernel<<<(3 * DMODEL * DMODEL / 4 + 255) / 256, 256>>>(w_qkv, p_wHi, p_wLo, 3 * DMODEL * DMODEL / 4);

    // 2) qkv = h @ w_qkv^T
    hmma_gemm<0><<<dim3(24, 32), 256, SMEMB>>>(p_aHi, p_aLo, p_wHi, p_wLo, 0, nullptr,
                                               p_qkv, nullptr, nullptr, nullptr, 3072, 1024);

    // 3) causal attention
    int attn_smem = 4 * 64 * 65 * (int)sizeof(float);
    cudaFuncSetAttribute(attn_kernel, cudaFuncAttributeMaxDynamicSharedMemorySize, attn_smem);
    attn_kernel<<<dim3(16, 64), 256, attn_smem>>>(p_qkv, p_o);

    // 4) x2 = x + o @ w_proj^T
    split_kernel<<<(BT * DMODEL / 4 + 255) / 256, 256>>>(p_o, p_aHi, p_aLo, BT * DMODEL / 4);
    split_kernel<<<(DMODEL * DMODEL / 4 + 255) / 256, 256>>>(w_proj, p_wHi, p_wLo, DMODEL * DMODEL / 4);
    hmma_gemm<1><<<dim3(8, 32), 256, SMEMB>>>(p_aHi, p_aLo, p_wHi, p_wLo, 0, nullptr,
                                              p_x2, x, nullptr, nullptr, 1024, 1024);

    // 5) xn = LN2(x2)
    ln_kernel<false><<<BT, 256>>>(p_x2, ln2_w, nullptr, p_xn);

    // 6) router + CSR
    router_kernel<<<BT, 256>>>(p_xn, router_w, p_eidx, p_wts);
    build_kernel<<<1, 256>>>(p_eidx, p_rows, p_te);

    // 7) split xn, gather bf16
    split_kernel<<<(BT * DMODEL / 4 + 255) / 256, 256>>>(p_xn, p_aHi, p_aLo, BT * DMODEL / 4);
    gather_bf<<<BT * 2, 128>>>(p_aHi, p_aLo, p_rows, p_xgHi, p_xgLo);

    // 8) hid = gelu(xg @ w1[e]^T), bf16 hi/lo out
    split_kernel<<<(NE * FF * DMODEL / 4 + 255) / 256, 256>>>(ew1, p_wHi, p_wLo, NE * FF * DMODEL / 4);
    hmma_gemm<2><<<dim3(32, NTILES), 256, SMEMB>>>(p_xgHi, p_xgLo, p_wHi, p_wLo,
                                                   (size_t)FF * DMODEL, p_te,
                                                   nullptr, nullptr, p_hidHi, p_hidLo, FF, 1024);

    // 9) eo = hid @ w2[e]^T
    split_kernel<<<(NE * DMODEL * FF / 4 + 255) / 256, 256>>>(ew2, p_wHi, p_wLo, NE * DMODEL * FF / 4);
    hmma_gemm<0><<<dim3(8, NTILES), 256, SMEMB>>>(p_hidHi, p_hidLo, p_wHi, p_wLo,
                                                  (size_t)DMODEL * FF, p_te,
                                                  p_eo, nullptr, nullptr, nullptr, 1024, 4096);

    // 10) out = xn + sum_k w_k * eo
    combine_kernel<<<BT, 256>>>(p_xn, p_eo, p_rows, p_wts, out);
}

// round 6
// speedup vs baseline: 2.3395x; 1.0825x over previous
#include <cuda_runtime.h>
#include <cuda_bf16.h>
#include <math.h>
#include <stdint.h>

// Problem dims
#define BATCH 4
#define TSEQ  1024
#define BT    4096
#define DMODEL 1024
#define NE    8
#define FF    4096
#define CAP   9216          // 72 * 128 row capacity for grouped MoE GEMMs
#define NTILES 72

// ---------------- static device scratch ----------------
__device__ float g_h  [BT * DMODEL];
__device__ float g_qkv[BT * 3 * DMODEL];
__device__ float g_o  [BT * DMODEL];
__device__ float g_x2 [BT * DMODEL];
__device__ float g_xn [BT * DMODEL];
__device__ float g_eo [CAP * DMODEL];
__device__ int   g_eidx[BT * 2];
__device__ float g_wts [BT * 2];
__device__ int   g_rows[BT * 2];
__device__ int   g_tile_e[NTILES];

// bf16 hi/lo split scratch
__device__ __nv_bfloat16 g_aHi [BT * DMODEL];
__device__ __nv_bfloat16 g_aLo [BT * DMODEL];
__device__ __nv_bfloat16 g_wHi [NE * FF * DMODEL];
__device__ __nv_bfloat16 g_wLo [NE * FF * DMODEL];
__device__ __nv_bfloat16 g_xgHi[CAP * DMODEL];
__device__ __nv_bfloat16 g_xgLo[CAP * DMODEL];
__device__ __nv_bfloat16 g_hidHi[CAP * FF];
__device__ __nv_bfloat16 g_hidLo[CAP * FF];

__device__ __forceinline__ float gelu_f(float v) {
    return 0.5f * v * (1.0f + erff(v * 0.70710678118654752f));
}

// ---------------- PTX helpers (sm_80+ portable; NO tcgen05) ----------------
__device__ __forceinline__ uint32_t smem_u32(const void* p) {
    uint32_t a;
    asm("{ .reg .u64 t; cvta.to.shared.u64 t, %1; cvt.u32.u64 %0, t; }" : "=r"(a) : "l"(p));
    return a;
}
__device__ __forceinline__ void cpa16(uint32_t dst, const void* src) {
    asm volatile("cp.async.cg.shared.global [%0], [%1], 16;" :: "r"(dst), "l"(src));
}
__device__ __forceinline__ void cp_commit() { asm volatile("cp.async.commit_group;" ::: "memory"); }
template<int NPEND> __device__ __forceinline__ void cp_wait() {
    asm volatile("cp.async.wait_group %0;" :: "n"(NPEND) : "memory");
}
__device__ __forceinline__ void ldm_x4(uint32_t* r, uint32_t a) {
    asm volatile("ldmatrix.sync.aligned.m8n8.x4.shared.b16 {%0,%1,%2,%3}, [%4];"
        : "=r"(r[0]), "=r"(r[1]), "=r"(r[2]), "=r"(r[3]) : "r"(a));
}
__device__ __forceinline__ void mma_bf16(float* d, const uint32_t* a, const uint32_t* b) {
    asm volatile("mma.sync.aligned.m16n8k16.row.col.f32.bf16.bf16.f32 "
        "{%0,%1,%2,%3}, {%4,%5,%6,%7}, {%8,%9}, {%0,%1,%2,%3};"
        : "+f"(d[0]), "+f"(d[1]), "+f"(d[2]), "+f"(d[3])
        : "r"(a[0]), "r"(a[1]), "r"(a[2]), "r"(a[3]), "r"(b[0]), "r"(b[1]));
}

// ---------------- HMMA NT GEMM: C[M,N] = A[M,K] @ B[N,K]^T ----------------
// fp32-split bf16: D = Ahi*Bhi + Ahi*Blo + Alo*Bhi, fp32 accum.
// Smem layout: 64B rows (KCH=32 bf16), XOR swizzle chunk^=((row>>1)&3).
// Conflict-free for ldmatrix; every cp.async dst is 16B aligned.
// EPI: 0 = fp32 out, 1 = fp32 out + Res, 2 = gelu -> bf16 hi/lo out
#define NSTG 3
#define KCH  32
#define MATB  (128 * 64)               // 8192 B per matrix per stage
#define STGB  (4 * MATB)               // 32768 B per stage
#define SMEMB (NSTG * STGB)            // 98304 B total -> 2 CTAs/SM

// swizzled byte offset of (row, 16B-chunk) within one matrix
#define SWO(row_, chk_) ((uint32_t)((row_) * 64 + (((chk_) ^ (((row_) >> 1) & 3)) << 4)))

template<int EPI>
__global__ void __launch_bounds__(256, 2) hmma_gemm(
    const __nv_bfloat16* __restrict__ Ahi, const __nv_bfloat16* __restrict__ Alo,
    const __nv_bfloat16* __restrict__ Bhi, const __nv_bfloat16* __restrict__ Blo,
    size_t bstride, const int* __restrict__ tile_e,
    float* __restrict__ C, const float* __restrict__ Res,
    __nv_bfloat16* __restrict__ Chi, __nv_bfloat16* __restrict__ Clo,
    int N, int K)
{
    extern __shared__ char smem[];
    uint32_t sbase = smem_u32(smem);
    int by = blockIdx.y, bx = blockIdx.x;

    const __nv_bfloat16* Bh = Bhi;
    const __nv_bfloat16* Bl = Blo;
    if (tile_e) {
        int e = tile_e[by];
        if (e < 0) return;
        Bh += (size_t)e * bstride;
        Bl += (size_t)e * bstride;
    }

    int tid = threadIdx.x, wid = tid >> 5, lane = tid & 31;
    int warpM = (wid >> 3) * 64, warpN = (wid & 7) * 0; // placeholder, real below
    warpM = (wid >> 2) * 64; warpN = (wid & 3) * 32;

    // ---- load mapping: 64 rows x 4 chunks of 16B per pass, 2 passes/matrix
    int lrow = tid >> 2;
    int lchk = tid & 3;
    const __nv_bfloat16* pAh0 = Ahi + (size_t)(by * 128 + lrow) * K + lchk * 8;
    const __nv_bfloat16* pAh1 = pAh0 + (size_t)64 * K;
    const __nv_bfloat16* pAl0 = Alo + (size_t)(by * 128 + lrow) * K + lchk * 8;
    const __nv_bfloat16* pAl1 = pAl0 + (size_t)64 * K;
    const __nv_bfloat16* pBh0 = Bh + (size_t)(bx * 128 + lrow) * K + lchk * 8;
    const __nv_bfloat16* pBh1 = pBh0 + (size_t)64 * K;
    const __nv_bfloat16* pBl0 = Bl + (size_t)(bx * 128 + lrow) * K + lchk * 8;
    const __nv_bfloat16* pBl1 = pBl0 + (size_t)64 * K;
    uint32_t so0 = SWO(lrow, lchk);
    uint32_t so1 = so0 + 64 * 64;     // rows +64: same XOR (bit 6 of row doesn't enter (row>>1)&3... it does not: (row+64)>>1 & 3 == (row>>1)&3 since 64>>1=32, 32&3=0)

#define LOADST(s_) do { \
        uint32_t sb_ = sbase + ((s_) % NSTG) * STGB; \
        size_t ko_ = (size_t)(s_) * KCH; \
        cpa16(sb_ + so0,            pAh0 + ko_); \
        cpa16(sb_ + so1,            pAh1 + ko_); \
        cpa16(sb_ + MATB + so0,     pAl0 + ko_); \
        cpa16(sb_ + MATB + so1,     pAl1 + ko_); \
        cpa16(sb_ + 2 * MATB + so0, pBh0 + ko_); \
        cpa16(sb_ + 2 * MATB + so1, pBh1 + ko_); \
        cpa16(sb_ + 3 * MATB + so0, pBl0 + ko_); \
        cpa16(sb_ + 3 * MATB + so1, pBl1 + ko_); \
        cp_commit(); \
    } while (0)

    float acc[4][4][4];
#pragma unroll
    for (int i = 0; i < 4; i++)
#pragma unroll
        for (int j = 0; j < 4; j++)
#pragma unroll
            for (int q = 0; q < 4; q++) acc[i][j][q] = 0.f;

    int S = K / KCH;
    LOADST(0);
    LOADST(1);

    // ldmatrix lane address components
    int a_r = lane & 15;                      // row within 16
    int a_c = lane >> 4;                      // k 16B-chunk half (0/1)
    int b_r = ((lane >> 3) & 1) * 8 + (lane & 7);
    int b_c = lane >> 4;

    for (int s = 0; s < S; s++) {
        if (s == S - 1) cp_wait<0>(); else cp_wait<1>();  // stage s landed; s+1 may fly
        __syncthreads();        // all warps done reading buffer (s+2)%NSTG (= compute s-1)
        if (s + 2 < S) LOADST(s + 2);

        uint32_t sa = sbase + (s % NSTG) * STGB;
#pragma unroll
        for (int ks = 0; ks < 2; ks++) {
            uint32_t ah[4][4], al[4][4], bhf[4][2], blf[4][2];
#pragma unroll
            for (int i = 0; i < 4; i++) {
                int row = warpM + 16 * i + a_r;
                uint32_t ad = sa + SWO(row, ks * 2 + a_c);
                ldm_x4(ah[i], ad);
                ldm_x4(al[i], ad + MATB);
            }
#pragma unroll
            for (int jj = 0; jj < 2; jj++) {
                int row = warpN + 16 * jj + b_r;
                uint32_t bd = sa + 2 * MATB + SWO(row, ks * 2 + b_c);
                uint32_t q[4], p[4];
                ldm_x4(q, bd);
                ldm_x4(p, bd + MATB);
                bhf[2 * jj][0] = q[0]; bhf[2 * jj][1] = q[2];
                bhf[2 * jj + 1][0] = q[1]; bhf[2 * jj + 1][1] = q[3];
                blf[2 * jj][0] = p[0]; blf[2 * jj][1] = p[2];
                blf[2 * jj + 1][0] = p[1]; blf[2 * jj + 1][1] = p[3];
            }
            // 3 independent passes: accumulator reuse distance = 16 MMAs (no RAW chain)
#pragma unroll
            for (int i = 0; i < 4; i++)
#pragma unroll
                for (int j = 0; j < 4; j++)
                    mma_bf16(acc[i][j], ah[i], bhf[j]);
#pragma unroll
            for (int i = 0; i < 4; i++)
#pragma unroll
                for (int j = 0; j < 4; j++)
                    mma_bf16(acc[i][j], ah[i], blf[j]);
#pragma unroll
            for (int i = 0; i < 4; i++)
#pragma unroll
                for (int j = 0; j < 4; j++)
                    mma_bf16(acc[i][j], al[i], bhf[j]);
        }
    }
#undef LOADST

    // ---- epilogue ----
    int r0 = lane >> 2, c0 = (lane & 3) * 2;
#pragma unroll
    for (int i = 0; i < 4; i++) {
#pragma unroll
        for (int j = 0; j < 4; j++) {
            int row = by * 128 + warpM + 16 * i + r0;
            int col = bx * 128 + warpN + 8 * j + c0;
#pragma unroll
            for (int half = 0; half < 2; half++) {
                size_t off = (size_t)(row + half * 8) * N + col;
                float v0 = acc[i][j][2 * half];
                float v1 = acc[i][j][2 * half + 1];
                if (EPI == 0) {
                    *(float2*)(C + off) = make_float2(v0, v1);
                } else if (EPI == 1) {
                    float2 rr = *(const float2*)(Res + off);
                    *(float2*)(C + off) = make_float2(v0 + rr.x, v1 + rr.y);
                } else {
                    v0 = gelu_f(v0); v1 = gelu_f(v1);
                    __nv_bfloat16 h0 = __float2bfloat16(v0);
                    __nv_bfloat16 h1 = __float2bfloat16(v1);
                    __nv_bfloat16 l0 = __float2bfloat16(v0 - __bfloat162float(h0));
                    __nv_bfloat16 l1 = __float2bfloat16(v1 - __bfloat162float(h1));
                    *(__nv_bfloat162*)(Chi + off) = __halves2bfloat162(h0, h1);
                    *(__nv_bfloat162*)(Clo + off) = __halves2bfloat162(l0, l1);
                }
            }
        }
    }
}

// ---------------- fp32 -> bf16 hi/lo split ----------------
__global__ __launch_bounds__(256) void split_kernel(const float* __restrict__ x,
                                                    __nv_bfloat16* __restrict__ hi,
                                                    __nv_bfloat16* __restrict__ lo, int n4) {
    int i = blockIdx.x * 256 + threadIdx.x;
    if (i >= n4) return;
    float4 v = ((const float4*)x)[i];
    __nv_bfloat16 h0 = __float2bfloat16(v.x), h1 = __float2bfloat16(v.y);
    __nv_bfloat16 h2 = __float2bfloat16(v.z), h3 = __float2bfloat16(v.w);
    __nv_bfloat16 l0 = __float2bfloat16(v.x - __bfloat162float(h0));
    __nv_bfloat16 l1 = __float2bfloat16(v.y - __bfloat162float(h1));
    __nv_bfloat16 l2 = __float2bfloat16(v.z - __bfloat162float(h2));
    __nv_bfloat16 l3 = __float2bfloat16(v.w - __bfloat162float(h3));
    ((__nv_bfloat162*)hi)[2 * i]     = __halves2bfloat162(h0, h1);
    ((__nv_bfloat162*)hi)[2 * i + 1] = __halves2bfloat162(h2, h3);
    ((__nv_bfloat162*)lo)[2 * i]     = __halves2bfloat162(l0, l1);
    ((__nv_bfloat162*)lo)[2 * i + 1] = __halves2bfloat162(l2, l3);
}

// ---------------- LayerNorm (optionally + c broadcast over T) ----------------
template<bool ADDC>
__global__ __launch_bounds__(256) void ln_kernel(const float* __restrict__ x,
                                                 const float* __restrict__ w,
                                                 const float* __restrict__ c,
                                                 float* __restrict__ out) {
    int row = blockIdx.x;
    int tid = threadIdx.x;
    const float* xr = x + (size_t)row * DMODEL;
    float4 v = *(const float4*)(xr + tid * 4);

    __shared__ float red[8];
    __shared__ float tot;

    float s = v.x + v.y + v.z + v.w;
#pragma unroll
    for (int m = 16; m > 0; m >>= 1) s += __shfl_xor_sync(0xffffffffu, s, m);
    if ((tid & 31) == 0) red[tid >> 5] = s;
    __syncthreads();
    if (tid == 0) { float t = 0.f; for (int i = 0; i < 8; i++) t += red[i]; tot = t; }
    __syncthreads();
    float mean = tot * (1.0f / DMODEL);
    float dx = v.x - mean, dy = v.y - mean, dz = v.z - mean, dw = v.w - mean;
    float s2 = dx * dx + dy * dy + dz * dz + dw * dw;
    __syncthreads();
#pragma unroll
    for (int m = 16; m > 0; m >>= 1) s2 += __shfl_xor_sync(0xffffffffu, s2, m);
    if ((tid & 31) == 0) red[tid >> 5] = s2;
    __syncthreads();
    if (tid == 0) { float t = 0.f; for (int i = 0; i < 8; i++) t += red[i]; tot = t; }
    __syncthreads();
    float inv = rsqrtf(tot * (1.0f / DMODEL) + 1e-5f);

    int d0 = tid * 4;
    float4 w4 = *(const float4*)(w + d0);
    float4 r;
    r.x = dx * inv * w4.x;
    r.y = dy * inv * w4.y;
    r.z = dz * inv * w4.z;
    r.w = dw * inv * w4.w;
    if (ADDC) {
        int b = row >> 10;
        float4 c4 = *(const float4*)(c + (size_t)b * DMODEL + d0);
        r.x += c4.x; r.y += c4.y; r.z += c4.z; r.w += c4.w;
    }
    *(float4*)(out + (size_t)row * DMODEL + d0) = r;
}

// ---------------- Flash-style causal attention (fp32 SIMT) ----------------
__global__ __launch_bounds__(256) void attn_kernel(const float* __restrict__ qkv,
                                                   float* __restrict__ o) {
    const int S = 65;
    extern __shared__ float sm[];
    float* Qs = sm;
    float* Ks = Qs + 64 * S;
    float* Vs = Ks + 64 * S;
    float* Ps = Vs + 64 * S;

    int qi = blockIdx.x;
    int bh = blockIdx.y;
    int b = bh >> 4, h = bh & 15;
    int tid = threadIdx.x;
    int tr = tid >> 4, tc = tid & 15;

    const float* base = qkv + (size_t)b * TSEQ * 3072;

#pragma unroll
    for (int k = 0; k < 4; k++) {
        int e = k * 256 + tid;
        int r = e >> 4, c4 = (e & 15) * 4;
        float4 v = *(const float4*)(base + (size_t)(qi * 64 + r) * 3072 + h * 64 + c4);
        float* d = &Qs[r * S + c4];
        d[0] = v.x * 0.125f; d[1] = v.y * 0.125f; d[2] = v.z * 0.125f; d[3] = v.w * 0.125f;
    }

    float m[4], l[4], acc[4][4];
#pragma unroll
    for (int i = 0; i < 4; i++) {
        m[i] = -1e30f; l[i] = 0.f;
#pragma unroll
        for (int j = 0; j < 4; j++) acc[i][j] = 0.f;
    }

    for (int jt = 0; jt <= qi; jt++) {
        __syncthreads();
#pragma unroll
        for (int k = 0; k < 4; k++) {
            int e = k * 256 + tid;
            int r = e >> 4, c4 = (e & 15) * 4;
            size_t rowoff = (size_t)(jt * 64 + r) * 3072 + h * 64 + c4;
            float4 kv = *(const float4*)(base + rowoff + 1024);
            float4 vv = *(const float4*)(base + rowoff + 2048);
            float* dk = &Ks[r * S + c4];
            dk[0] = kv.x; dk[1] = kv.y; dk[2] = kv.z; dk[3] = kv.w;
            float* dv = &Vs[r * S + c4];
            dv[0] = vv.x; dv[1] = vv.y; dv[2] = vv.z; dv[3] = vv.w;
        }
        __syncthreads();

        float s[4][4] = {};
#pragma unroll 8
        for (int kk = 0; kk < 64; kk++) {
            float a0 = Qs[(4 * tr + 0) * S + kk];
            float a1 = Qs[(4 * tr + 1) * S + kk];
            float a2 = Qs[(4 * tr + 2) * S + kk];
            float a3 = Qs[(4 * tr + 3) * S + kk];
            float b0 = Ks[(4 * tc + 0) * S + kk];
            float b1 = Ks[(4 * tc + 1) * S + kk];
            float b2 = Ks[(4 * tc + 2) * S + kk];
            float b3 = Ks[(4 * tc + 3) * S + kk];
            s[0][0] += a0 * b0; s[0][1] += a0 * b1; s[0][2] += a0 * b2; s[0][3] += a0 * b3;
            s[1][0] += a1 * b0; s[1][1] += a1 * b1; s[1][2] += a1 * b2; s[1][3] += a1 * b3;
            s[2][0] += a2 * b0; s[2][1] += a2 * b1; s[2][2] += a2 * b2; s[2][3] += a2 * b3;
            s[3][0] += a3 * b0; s[3][1] += a3 * b1; s[3][2] += a3 * b2; s[3][3] += a3 * b3;
        }

        if (jt == qi) {
#pragma unroll
            for (int i = 0; i < 4; i++) {
                int rg = qi * 64 + 4 * tr + i;
#pragma unroll
                for (int j = 0; j < 4; j++) {
                    int cg = jt * 64 + 4 * tc + j;
                    if (cg > rg) s[i][j] = -1e30f;
                }
            }
        }

#pragma unroll
        for (int i = 0; i < 4; i++) {
            float mt = fmaxf(fmaxf(s[i][0], s[i][1]), fmaxf(s[i][2], s[i][3]));
#pragma unroll
            for (int mm = 8; mm > 0; mm >>= 1)
                mt = fmaxf(mt, __shfl_xor_sync(0xffffffffu, mt, mm));
            float mn = fmaxf(m[i], mt);
            float alpha = expf(m[i] - mn);
            float ls = 0.f;
#pragma unroll
            for (int j = 0; j < 4; j++) {
                float p = expf(s[i][j] - mn);
                s[i][j] = p;
                ls += p;
            }
#pragma unroll
            for (int mm = 8; mm > 0; mm >>= 1)
                ls += __shfl_xor_sync(0xffffffffu, ls, mm);
            l[i] = l[i] * alpha + ls;
            m[i] = mn;
#pragma unroll
            for (int j = 0; j < 4; j++) acc[i][j] *= alpha;
        }

        __syncthreads();
#pragma unroll
        for (int i = 0; i < 4; i++)
#pragma unroll
            for (int j = 0; j < 4; j++)
                Ps[(4 * tr + i) * S + 4 * tc + j] = s[i][j];
        __syncthreads();

#pragma unroll 8
        for (int kk = 0; kk < 64; kk++) {
            float p0 = Ps[(4 * tr + 0) * S + kk];
            float p1 = Ps[(4 * tr + 1) * S + kk];
            float p2 = Ps[(4 * tr + 2) * S + kk];
            float p3 = Ps[(4 * tr + 3) * S + kk];
            float v0 = Vs[kk * S + 4 * tc + 0];
            float v1 = Vs[kk * S + 4 * tc + 1];
            float v2 = Vs[kk * S + 4 * tc + 2];
            float v3 = Vs[kk * S + 4 * tc + 3];
            acc[0][0] += p0 * v0; acc[0][1] += p0 * v1; acc[0][2] += p0 * v2; acc[0][3] += p0 * v3;
            acc[1][0] += p1 * v0; acc[1][1] += p1 * v1; acc[1][2] += p1 * v2; acc[1][3] += p1 * v3;
            acc[2][0] += p2 * v0; acc[2][1] += p2 * v1; acc[2][2] += p2 * v2; acc[2][3] += p2 * v3;
            acc[3][0] += p3 * v0; acc[3][1] += p3 * v1; acc[3][2] += p3 * v2; acc[3][3] += p3 * v3;
        }
    }

#pragma unroll
    for (int i = 0; i < 4; i++) {
        int rg = qi * 64 + 4 * tr + i;
        float invl = 1.0f / l[i];
#pragma unroll
        for (int j = 0; j < 4; j++) {
            o[((size_t)(b * TSEQ + rg)) * DMODEL + h * 64 + 4 * tc + j] = acc[i][j] * invl;
        }
    }
}

// ---------------- router ----------------
__global__ __launch_bounds__(256) void router_kernel(const float* __restrict__ xn,
                                                     const float* __restrict__ rw,
                                                     int* __restrict__ eidx,
                                                     float* __restrict__ wts) {
    int t = blockIdx.x;
    int tid = threadIdx.x, lane = tid & 31, wp = tid >> 5;
    const float* xr = xn + (size_t)t * DMODEL;
    const float* wr = rw + (size_t)wp * DMODEL;
    float s = 0.f;
    for (int d = lane * 4; d < DMODEL; d += 128) {
        float4 a = *(const float4*)(xr + d);
        float4 b = *(const float4*)(wr + d);
        s += a.x * b.x + a.y * b.y + a.z * b.z + a.w * b.w;
    }
#pragma unroll
    for (int mm = 16; mm > 0; mm >>= 1) s += __shfl_xor_sync(0xffffffffu, s, mm);
    __shared__ float lg[8];
    if (lane == 0) lg[wp] = s;
    __syncthreads();
    if (tid == 0) {
        float mx = lg[0];
        for (int e = 1; e < NE; e++) mx = fmaxf(mx, lg[e]);
        float p[NE]; float sum = 0.f;
        for (int e = 0; e < NE; e++) { p[e] = expf(lg[e] - mx); sum += p[e]; }
        float inv = 1.0f / sum;
        for (int e = 0; e < NE; e++) {
            float v = p[e] * inv + 1e-9f;
            p[e] = fminf(fmaxf(v, 1e-9f), 1.0f - 1e-9f);
        }
        int i0 = 0;
        for (int e = 1; e < NE; e++) if (p[e] > p[i0]) i0 = e;
        int i1 = (i0 == 0) ? 1 : 0;
        for (int e = 0; e < NE; e++) if (e != i0 && p[e] > p[i1]) i1 = e;
        float d2 = 1.0f / (p[i0] + p[i1]);
        eidx[2 * t] = i0; eidx[2 * t + 1] = i1;
        wts[2 * t] = p[i0] * d2; wts[2 * t + 1] = p[i1] * d2;
    }
}

// ---------------- build per-expert CSR ----------------
__global__ __launch_bounds__(256) void build_kernel(const int* __restrict__ eidx,
                                                    int* __restrict__ rows,
                                                    int* __restrict__ tile_e) {
    __shared__ int cnt[NE];
    __shared__ int off[NE];
    int tid = threadIdx.x;
    if (tid < NE) cnt[tid] = 0;
    __syncthreads();
    for (int a = tid; a < BT * 2; a += 256) atomicAdd(&cnt[eidx[a]], 1);
    __syncthreads();
    if (tid == 0) {
        int o = 0;
        for (int e = 0; e < NE; e++) { off[e] = o; o = (o + cnt[e] + 127) & ~127; }
        for (int tt = 0; tt < NTILES; tt++) tile_e[tt] = -1;
        for (int e = 0; e < NE; e++) {
            int nt = (cnt[e] + 127) >> 7;
            int t0 = off[e] >> 7;
            for (int i = 0; i < nt; i++) tile_e[t0 + i] = e;
        }
    }
    __syncthreads();
    if (tid < NE) cnt[tid] = 0;
    __syncthreads();
    for (int a = tid; a < BT * 2; a += 256) {
        int e = eidx[a];
        int pos = atomicAdd(&cnt[e], 1);
        rows[a] = off[e] + pos;
    }
}

// ---------------- gather bf16 rows ----------------
__global__ __launch_bounds__(128) void gather_bf(const __nv_bfloat16* __restrict__ xhi,
                                                 const __nv_bfloat16* __restrict__ xlo,
                                                 const int* __restrict__ rows,
                                                 __nv_bfloat16* __restrict__ ghi,
                                                 __nv_bfloat16* __restrict__ glo) {
    int a = blockIdx.x;
    int r = rows[a];
    int t = a >> 1;
    int tid = threadIdx.x;
    ((uint4*)(ghi + (size_t)r * DMODEL))[tid] = ((const uint4*)(xhi + (size_t)t * DMODEL))[tid];
    ((uint4*)(glo + (size_t)r * DMODEL))[tid] = ((const uint4*)(xlo + (size_t)t * DMODEL))[tid];
}

// ---------------- combine ----------------
__global__ __launch_bounds__(256) void combine_kernel(const float* __restrict__ xn,
                                                      const float* __restrict__ eo,
                                                      const int* __restrict__ rows,
                                                      const float* __restrict__ wts,
                                                      float* __restrict__ out) {
    int t = blockIdx.x;
    int r0 = rows[2 * t], r1 = rows[2 * t + 1];
    float w0 = wts[2 * t], w1 = wts[2 * t + 1];
    int tid = threadIdx.x;
    float4 a = *(const float4*)(xn + (size_t)t * DMODEL + tid * 4);
    float4 b = *(const float4*)(eo + (size_t)r0 * DMODEL + tid * 4);
    float4 c = *(const float4*)(eo + (size_t)r1 * DMODEL + tid * 4);
    float4 r;
    r.x = a.x + w0 * b.x + w1 * c.x;
    r.y = a.y + w0 * b.y + w1 * c.y;
    r.z = a.z + w0 * b.z + w1 * c.z;
    r.w = a.w + w0 * b.w + w1 * c.w;
    *(float4*)(out + (size_t)t * DMODEL + tid * 4) = r;
}

// ---------------- host launcher ----------------
extern "C" void kernel_launch(void* const* d_in, const int* in_sizes, int n_in,
                              void* d_out, int out_size) {
    const float* x        = (const float*)d_in[0];
    const float* c        = (const float*)d_in[1];
    const float* ln1_w    = (const float*)d_in[2];
    const float* w_qkv    = (const float*)d_in[3];
    const float* w_proj   = (const float*)d_in[4];
    const float* ln2_w    = (const float*)d_in[5];
    const float* router_w = (const float*)d_in[6];
    const float* ew1      = (const float*)d_in[7];
    const float* ew2      = (const float*)d_in[8];
    float* out = (float*)d_out;

    float *p_h, *p_qkv, *p_o, *p_x2, *p_xn, *p_eo, *p_wts;
    int *p_eidx, *p_rows, *p_te;
    __nv_bfloat16 *p_aHi, *p_aLo, *p_wHi, *p_wLo, *p_xgHi, *p_xgLo, *p_hidHi, *p_hidLo;
    cudaGetSymbolAddress((void**)&p_h,     g_h);
    cudaGetSymbolAddress((void**)&p_qkv,   g_qkv);
    cudaGetSymbolAddress((void**)&p_o,     g_o);
    cudaGetSymbolAddress((void**)&p_x2,    g_x2);
    cudaGetSymbolAddress((void**)&p_xn,    g_xn);
    cudaGetSymbolAddress((void**)&p_eo,    g_eo);
    cudaGetSymbolAddress((void**)&p_wts,   g_wts);
    cudaGetSymbolAddress((void**)&p_eidx,  g_eidx);
    cudaGetSymbolAddress((void**)&p_rows,  g_rows);
    cudaGetSymbolAddress((void**)&p_te,    g_tile_e);
    cudaGetSymbolAddress((void**)&p_aHi,   g_aHi);
    cudaGetSymbolAddress((void**)&p_aLo,   g_aLo);
    cudaGetSymbolAddress((void**)&p_wHi,   g_wHi);
    cudaGetSymbolAddress((void**)&p_wLo,   g_wLo);
    cudaGetSymbolAddress((void**)&p_xgHi,  g_xgHi);
    cudaGetSymbolAddress((void**)&p_xgLo,  g_xgLo);
    cudaGetSymbolAddress((void**)&p_hidHi, g_hidHi);
    cudaGetSymbolAddress((void**)&p_hidLo, g_hidLo);

    cudaFuncSetAttribute(hmma_gemm<0>, cudaFuncAttributeMaxDynamicSharedMemorySize, SMEMB);
    cudaFuncSetAttribute(hmma_gemm<1>, cudaFuncAttributeMaxDynamicSharedMemorySize, SMEMB);
    cudaFuncSetAttribute(hmma_gemm<2>, cudaFuncAttributeMaxDynamicSharedMemorySize, SMEMB);

    // 1) h = LN1(x)*w + c ; split to bf16
    ln_kernel<true><<<BT, 256>>>(x, ln1_w, c, p_h);
    split_kernel<<<(BT * DMODEL / 4 + 255) / 256, 256>>>(p_h, p_aHi, p_aLo, BT * DMODEL / 4);
    split_kernel<<<(3 * DMODEL * DMODEL / 4 + 255) / 256, 256>>>(w_qkv, p_wHi, p_wLo, 3 * DMODEL * DMODEL / 4);

    // 2) qkv = h @ w_qkv^T
    hmma_gemm<0><<<dim3(24, 32), 256, SMEMB>>>(p_aHi, p_aLo, p_wHi, p_wLo, 0, nullptr,
                                               p_qkv, nullptr, nullptr, nullptr, 3072, 1024);

    // 3) causal attention
    int attn_smem = 4 * 64 * 65 * (int)sizeof(float);
    cudaFuncSetAttribute(attn_kernel, cudaFuncAttributeMaxDynamicSharedMemorySize, attn_smem);
    attn_kernel<<<dim3(16, 64), 256, attn_smem>>>(p_qkv, p_o);

    // 4) x2 = x + o @ w_proj^T
    split_kernel<<<(BT * DMODEL / 4 + 255) / 256, 256>>>(p_o, p_aHi, p_aLo, BT * DMODEL / 4);
    split_kernel<<<(DMODEL * DMODEL / 4 + 255) / 256, 256>>>(w_proj, p_wHi, p_wLo, DMODEL * DMODEL / 4);
    hmma_gemm<1><<<dim3(8, 32), 256, SMEMB>>>(p_aHi, p_aLo, p_wHi, p_wLo, 0, nullptr,
                                              p_x2, x, nullptr, nullptr, 1024, 1024);

    // 5) xn = LN2(x2)
    ln_kernel<false><<<BT, 256>>>(p_x2, ln2_w, nullptr, p_xn);

    // 6) router + CSR
    router_kernel<<<BT, 256>>>(p_xn, router_w, p_eidx, p_wts);
    build_kernel<<<1, 256>>>(p_eidx, p_rows, p_te);

    // 7) split xn, gather bf16
    split_kernel<<<(BT * DMODEL / 4 + 255) / 256, 256>>>(p_xn, p_aHi, p_aLo, BT * DMODEL / 4);
    gather_bf<<<BT * 2, 128>>>(p_aHi, p_aLo, p_rows, p_xgHi, p_xgLo);

    // 8) hid = gelu(xg @ w1[e]^T), bf16 hi/lo out
    split_kernel<<<(NE * FF * DMODEL / 4 + 255) / 256, 256>>>(ew1, p_wHi, p_wLo, NE * FF * DMODEL / 4);
    hmma_gemm<2><<<dim3(32, NTILES), 256, SMEMB>>>(p_xgHi, p_xgLo, p_wHi, p_wLo,
                                                   (size_t)FF * DMODEL, p_te,
                                                   nullptr, nullptr, p_hidHi, p_hidLo, FF, 1024);

    // 9) eo = hid @ w2[e]^T
    split_kernel<<<(NE * DMODEL * FF / 4 + 255) / 256, 256>>>(ew2, p_wHi, p_wLo, NE * DMODEL * FF / 4);
    hmma_gemm<0><<<dim3(8, NTILES), 256, SMEMB>>>(p_hidHi, p_hidLo, p_wHi, p_wLo,
                                                  (size_t)DMODEL * FF, p_te,
                                                  p_eo, nullptr, nullptr, nullptr, 1024, 4096);

    // 10) out = xn + sum_k w_k * eo
    combine_kernel<<<BT, 256>>>(p_xn, p_eo, p_rows, p_wts, out);
}

// round 8
// speedup vs baseline: 2.3515x; 1.0051x over previous
#include <cuda_runtime.h>
#include <cuda_fp16.h>
#include <math.h>
#include <stdint.h>

// Problem dims
#define BATCH 4
#define TSEQ  1024
#define BT    4096
#define DMODEL 1024
#define NE    8
#define FF    4096
#define CAP   9216          // 72 * 128 row capacity for grouped MoE GEMMs
#define NTILES 72

// ---------------- static device scratch ----------------
__device__ float g_h  [BT * DMODEL];
__device__ float g_qkv[BT * 3 * DMODEL];
__device__ float g_o  [BT * DMODEL];
__device__ float g_x2 [BT * DMODEL];
__device__ float g_xn [BT * DMODEL];
__device__ float g_eo [CAP * DMODEL];
__device__ int   g_eidx[BT * 2];
__device__ float g_wts [BT * 2];
__device__ int   g_rows[BT * 2];
__device__ int   g_tile_e[NTILES];

// fp16 split scratch: everything hi/lo
__device__ __half g_aHi [BT * DMODEL];
__device__ __half g_aLo [BT * DMODEL];
__device__ __half g_wHi [NE * FF * DMODEL];
__device__ __half g_wLo [NE * FF * DMODEL];
__device__ __half g_xgHi[CAP * DMODEL];
__device__ __half g_xgLo[CAP * DMODEL];
__device__ __half g_hidHi[CAP * FF];
__device__ __half g_hidLo[CAP * FF];

__device__ __forceinline__ float gelu_f(float v) {
    return 0.5f * v * (1.0f + erff(v * 0.70710678118654752f));
}

// ---------------- PTX helpers (sm_80+ portable; NO tcgen05) ----------------
__device__ __forceinline__ uint32_t smem_u32(const void* p) {
    uint32_t a;
    asm("{ .reg .u64 t; cvta.to.shared.u64 t, %1; cvt.u32.u64 %0, t; }" : "=r"(a) : "l"(p));
    return a;
}
__device__ __forceinline__ void cpa16(uint32_t dst, const void* src) {
    asm volatile("cp.async.cg.shared.global [%0], [%1], 16;" :: "r"(dst), "l"(src));
}
__device__ __forceinline__ void cp_commit() { asm volatile("cp.async.commit_group;" ::: "memory"); }
template<int NPEND> __device__ __forceinline__ void cp_wait() {
    asm volatile("cp.async.wait_group %0;" :: "n"(NPEND) : "memory");
}
__device__ __forceinline__ void ldm_x4(uint32_t* r, uint32_t a) {
    asm volatile("ldmatrix.sync.aligned.m8n8.x4.shared.b16 {%0,%1,%2,%3}, [%4];"
        : "=r"(r[0]), "=r"(r[1]), "=r"(r[2]), "=r"(r[3]) : "r"(a));
}
__device__ __forceinline__ void mma_f16(float* d, const uint32_t* a, const uint32_t* b) {
    asm volatile("mma.sync.aligned.m16n8k16.row.col.f32.f16.f16.f32 "
        "{%0,%1,%2,%3}, {%4,%5,%6,%7}, {%8,%9}, {%0,%1,%2,%3};"
        : "+f"(d[0]), "+f"(d[1]), "+f"(d[2]), "+f"(d[3])
        : "r"(a[0]), "r"(a[1]), "r"(a[2]), "r"(a[3]), "r"(b[0]), "r"(b[1]));
}

// ---------------- HMMA NT GEMM: C[M,N] = A[M,K] @ B[N,K]^T ----------------
// fp16 3-term: D = Ahi*Bhi + Ahi*Blo + Alo*Bhi (dropped Alo*Blo ~2^-22)
// CTA tile 128x128, 4 warps of 64x64 (LDSM/MMA = 0.167), NSTG=3.
// Smem: 4 matrices/stage, 64B rows, XOR swizzle chunk^=((row>>1)&3).
// EPI: 0 = fp32 out, 1 = fp32 out + Res, 2 = gelu -> fp16 hi/lo out
#define NSTG 3
#define KCH  32
#define MATB  (128 * 64)               // 8192 B per matrix per stage
#define STGB  (4 * MATB)               // 32768 B per stage
#define SMEMB (NSTG * STGB)            // 98304 B total -> 2 CTAs/SM

// swizzled byte offset of (row, 16B-chunk) within one matrix
#define SWO(row_, chk_) ((uint32_t)((row_) * 64 + (((chk_) ^ (((row_) >> 1) & 3)) << 4)))

template<int EPI>
__global__ void __launch_bounds__(128, 2) hmma_gemm(
    const __half* __restrict__ Ahi, const __half* __restrict__ Alo,
    const __half* __restrict__ Bhi, const __half* __restrict__ Blo,
    size_t bstride, const int* __restrict__ tile_e,
    float* __restrict__ C, const float* __restrict__ Res,
    __half* __restrict__ Chi, __half* __restrict__ Clo,
    int N, int K)
{
    extern __shared__ char smem[];
    uint32_t sbase = smem_u32(smem);
    int by = blockIdx.y, bx = blockIdx.x;

    const __half* Bh = Bhi;
    const __half* Bl = Blo;
    if (tile_e) {
        int e = tile_e[by];
        if (e < 0) return;
        Bh += (size_t)e * bstride;
        Bl += (size_t)e * bstride;
    }

    int tid = threadIdx.x, wid = tid >> 5, lane = tid & 31;
    int warpM = (wid >> 1) * 64, warpN = (wid & 1) * 64;

    // ---- load mapping: 128 threads, 32 rows x 4 chunks per pass, 4 passes/matrix
    int lrow = tid >> 2;                // 0..31
    int lchk = tid & 3;
    const __half* pAh = Ahi + (size_t)(by * 128 + lrow) * K + lchk * 8;
    const __half* pAl = Alo + (size_t)(by * 128 + lrow) * K + lchk * 8;
    const __half* pB0 = Bh + (size_t)(bx * 128 + lrow) * K + lchk * 8;
    const __half* pB1 = Bl + (size_t)(bx * 128 + lrow) * K + lchk * 8;
    uint32_t so = SWO(lrow, lchk);      // +32 rows: swizzle bits unchanged (32>>1=16, 16&3=0)

#define LOADST(s_) do { \
        uint32_t sb_ = sbase + ((s_) % NSTG) * STGB; \
        size_t ko_ = (size_t)(s_) * KCH; \
        _Pragma("unroll") \
        for (int p_ = 0; p_ < 4; p_++) { \
            uint32_t o_ = so + p_ * (32 * 64); \
            size_t g_ = ko_ + (size_t)p_ * 32 * K; \
            cpa16(sb_ + o_,            pAh + g_); \
            cpa16(sb_ + MATB + o_,     pAl + g_); \
            cpa16(sb_ + 2 * MATB + o_, pB0 + g_); \
            cpa16(sb_ + 3 * MATB + o_, pB1 + g_); \
        } \
        cp_commit(); \
    } while (0)

    float acc[4][8][4];
#pragma unroll
    for (int i = 0; i < 4; i++)
#pragma unroll
        for (int j = 0; j < 8; j++)
#pragma unroll
            for (int q = 0; q < 4; q++) acc[i][j][q] = 0.f;

    int S = K / KCH;
    LOADST(0);
    LOADST(1);

    // ldmatrix lane address components
    int a_r = lane & 15;                      // row within 16
    int a_c = lane >> 4;                      // k 16B-chunk half (0/1)
    int b_r = ((lane >> 3) & 1) * 8 + (lane & 7);
    int b_c = lane >> 4;

    for (int s = 0; s < S; s++) {
        if (s == S - 1) cp_wait<0>(); else cp_wait<1>();
        __syncthreads();        // all warps done reading buffer (s+2)%NSTG
        if (s + 2 < S) LOADST(s + 2);

        uint32_t sa = sbase + (s % NSTG) * STGB;
#pragma unroll
        for (int ks = 0; ks < 2; ks++) {
            uint32_t ah[4][4], al[4][4], bhf[8][2];
#pragma unroll
            for (int i = 0; i < 4; i++) {
                int row = warpM + 16 * i + a_r;
                uint32_t ad = sa + SWO(row, ks * 2 + a_c);
                ldm_x4(ah[i], ad);
                ldm_x4(al[i], ad + MATB);
            }
#pragma unroll
            for (int jj = 0; jj < 4; jj++) {
                int row = warpN + 16 * jj + b_r;
                uint32_t bd = sa + 2 * MATB + SWO(row, ks * 2 + b_c);
                uint32_t q[4];
                ldm_x4(q, bd);
                bhf[2 * jj][0] = q[0]; bhf[2 * jj][1] = q[2];
                bhf[2 * jj + 1][0] = q[1]; bhf[2 * jj + 1][1] = q[3];
            }
            // pass 1: Ahi*Bhi ; pass 3: Alo*Bhi (bhf still live, al dies after)
#pragma unroll
            for (int i = 0; i < 4; i++)
#pragma unroll
                for (int j = 0; j < 8; j++)
                    mma_f16(acc[i][j], ah[i], bhf[j]);
#pragma unroll
            for (int i = 0; i < 4; i++)
#pragma unroll
                for (int j = 0; j < 8; j++)
                    mma_f16(acc[i][j], al[i], bhf[j]);
            // load Blo into the same fragment slots, pass 2: Ahi*Blo
            uint32_t blf[8][2];
#pragma unroll
            for (int jj = 0; jj < 4; jj++) {
                int row = warpN + 16 * jj + b_r;
                uint32_t bd = sa + 3 * MATB + SWO(row, ks * 2 + b_c);
                uint32_t p[4];
                ldm_x4(p, bd);
                blf[2 * jj][0] = p[0]; blf[2 * jj][1] = p[2];
                blf[2 * jj + 1][0] = p[1]; blf[2 * jj + 1][1] = p[3];
            }
#pragma unroll
            for (int i = 0; i < 4; i++)
#pragma unroll
                for (int j = 0; j < 8; j++)
                    mma_f16(acc[i][j], ah[i], blf[j]);
        }
    }
#undef LOADST

    // ---- epilogue ----
    int r0 = lane >> 2, c0 = (lane & 3) * 2;
#pragma unroll
    for (int i = 0; i < 4; i++) {
#pragma unroll
        for (int j = 0; j < 8; j++) {
            int row = by * 128 + warpM + 16 * i + r0;
            int col = bx * 128 + warpN + 8 * j + c0;
#pragma unroll
            for (int half = 0; half < 2; half++) {
                size_t off = (size_t)(row + half * 8) * N + col;
                float v0 = acc[i][j][2 * half];
                float v1 = acc[i][j][2 * half + 1];
                if (EPI == 0) {
                    *(float2*)(C + off) = make_float2(v0, v1);
                } else if (EPI == 1) {
                    float2 rr = *(const float2*)(Res + off);
                    *(float2*)(C + off) = make_float2(v0 + rr.x, v1 + rr.y);
                } else {
                    v0 = gelu_f(v0); v1 = gelu_f(v1);
                    __half h0 = __float2half(v0);
                    __half h1 = __float2half(v1);
                    __half l0 = __float2half(v0 - __half2float(h0));
                    __half l1 = __float2half(v1 - __half2float(h1));
                    *(__half2*)(Chi + off) = __halves2half2(h0, h1);
                    *(__half2*)(Clo + off) = __halves2half2(l0, l1);
                }
            }
        }
    }
}

// ---------------- fp32 -> fp16 hi/lo split ----------------
__global__ __launch_bounds__(256) void split2_kernel(const float* __restrict__ x,
                                                     __half* __restrict__ hi,
                                                     __half* __restrict__ lo, int n4) {
    int i = blockIdx.x * 256 + threadIdx.x;
    if (i >= n4) return;
    float4 v = ((const float4*)x)[i];
    __half h0 = __float2half(v.x), h1 = __float2half(v.y);
    __half h2 = __float2half(v.z), h3 = __float2half(v.w);
    __half l0 = __float2half(v.x - __half2float(h0));
    __half l1 = __float2half(v.y - __half2float(h1));
    __half l2 = __float2half(v.z - __half2float(h2));
    __half l3 = __float2half(v.w - __half2float(h3));
    ((__half2*)hi)[2 * i]     = __halves2half2(h0, h1);
    ((__half2*)hi)[2 * i + 1] = __halves2half2(h2, h3);
    ((__half2*)lo)[2 * i]     = __halves2half2(l0, l1);
    ((__half2*)lo)[2 * i + 1] = __halves2half2(l2, l3);
}

// ---------------- LayerNorm (optionally + c broadcast over T) ----------------
template<bool ADDC>
__global__ __launch_bounds__(256) void ln_kernel(const float* __restrict__ x,
                                                 const float* __restrict__ w,
                                                 const float* __restrict__ c,
                                                 float* __restrict__ out) {
    int row = blockIdx.x;
    int tid = threadIdx.x;
    const float* xr = x + (size_t)row * DMODEL;
    float4 v = *(const float4*)(xr + tid * 4);

    __shared__ float red[8];
    __shared__ float tot;

    float s = v.x + v.y + v.z + v.w;
#pragma unroll
    for (int m = 16; m > 0; m >>= 1) s += __shfl_xor_sync(0xffffffffu, s, m);
    if ((tid & 31) == 0) red[tid >> 5] = s;
    __syncthreads();
    if (tid == 0) { float t = 0.f; for (int i = 0; i < 8; i++) t += red[i]; tot = t; }
    __syncthreads();
    float mean = tot * (1.0f / DMODEL);
    float dx = v.x - mean, dy = v.y - mean, dz = v.z - mean, dw = v.w - mean;
    float s2 = dx * dx + dy * dy + dz * dz + dw * dw;
    __syncthreads();
#pragma unroll
    for (int m = 16; m > 0; m >>= 1) s2 += __shfl_xor_sync(0xffffffffu, s2, m);
    if ((tid & 31) == 0) red[tid >> 5] = s2;
    __syncthreads();
    if (tid == 0) { float t = 0.f; for (int i = 0; i < 8; i++) t += red[i]; tot = t; }
    __syncthreads();
    float inv = rsqrtf(tot * (1.0f / DMODEL) + 1e-5f);

    int d0 = tid * 4;
    float4 w4 = *(const float4*)(w + d0);
    float4 r;
    r.x = dx * inv * w4.x;
    r.y = dy * inv * w4.y;
    r.z = dz * inv * w4.z;
    r.w = dw * inv * w4.w;
    if (ADDC) {
        int b = row >> 10;
        float4 c4 = *(const float4*)(c + (size_t)b * DMODEL + d0);
        r.x += c4.x; r.y += c4.y; r.z += c4.z; r.w += c4.w;
    }
    *(float4*)(out + (size_t)row * DMODEL + d0) = r;
}

// ---------------- Flash-style causal attention (fp32 SIMT) ----------------
__global__ __launch_bounds__(256) void attn_kernel(const float* __restrict__ qkv,
                                                   float* __restrict__ o) {
    const int S = 65;
    extern __shared__ float sm[];
    float* Qs = sm;
    float* Ks = Qs + 64 * S;
    float* Vs = Ks + 64 * S;
    float* Ps = Vs + 64 * S;

    int qi = blockIdx.x;
    int bh = blockIdx.y;
    int b = bh >> 4, h = bh & 15;
    int tid = threadIdx.x;
    int tr = tid >> 4, tc = tid & 15;

    const float* base = qkv + (size_t)b * TSEQ * 3072;

#pragma unroll
    for (int k = 0; k < 4; k++) {
        int e = k * 256 + tid;
        int r = e >> 4, c4 = (e & 15) * 4;
        float4 v = *(const float4*)(base + (size_t)(qi * 64 + r) * 3072 + h * 64 + c4);
        float* d = &Qs[r * S + c4];
        d[0] = v.x * 0.125f; d[1] = v.y * 0.125f; d[2] = v.z * 0.125f; d[3] = v.w * 0.125f;
    }

    float m[4], l[4], acc[4][4];
#pragma unroll
    for (int i = 0; i < 4; i++) {
        m[i] = -1e30f; l[i] = 0.f;
#pragma unroll
        for (int j = 0; j < 4; j++) acc[i][j] = 0.f;
    }

    for (int jt = 0; jt <= qi; jt++) {
        __syncthreads();
#pragma unroll
        for (int k = 0; k < 4; k++) {
            int e = k * 256 + tid;
            int r = e >> 4, c4 = (e & 15) * 4;
            size_t rowoff = (size_t)(jt * 64 + r) * 3072 + h * 64 + c4;
            float4 kv = *(const float4*)(base + rowoff + 1024);
            float4 vv = *(const float4*)(base + rowoff + 2048);
            float* dk = &Ks[r * S + c4];
            dk[0] = kv.x; dk[1] = kv.y; dk[2] = kv.z; dk[3] = kv.w;
            float* dv = &Vs[r * S + c4];
            dv[0] = vv.x; dv[1] = vv.y; dv[2] = vv.z; dv[3] = vv.w;
        }
        __syncthreads();

        float s[4][4] = {};
#pragma unroll 8
        for (int kk = 0; kk < 64; kk++) {
            float a0 = Qs[(4 * tr + 0) * S + kk];
            float a1 = Qs[(4 * tr + 1) * S + kk];
            float a2 = Qs[(4 * tr + 2) * S + kk];
            float a3 = Qs[(4 * tr + 3) * S + kk];
            float b0 = Ks[(4 * tc + 0) * S + kk];
            float b1 = Ks[(4 * tc + 1) * S + kk];
            float b2 = Ks[(4 * tc + 2) * S + kk];
            float b3 = Ks[(4 * tc + 3) * S + kk];
            s[0][0] += a0 * b0; s[0][1] += a0 * b1; s[0][2] += a0 * b2; s[0][3] += a0 * b3;
            s[1][0] += a1 * b0; s[1][1] += a1 * b1; s[1][2] += a1 * b2; s[1][3] += a1 * b3;
            s[2][0] += a2 * b0; s[2][1] += a2 * b1; s[2][2] += a2 * b2; s[2][3] += a2 * b3;
            s[3][0] += a3 * b0; s[3][1] += a3 * b1; s[3][2] += a3 * b2; s[3][3] += a3 * b3;
        }

        if (jt == qi) {
#pragma unroll
            for (int i = 0; i < 4; i++) {
                int rg = qi * 64 + 4 * tr + i;
#pragma unroll
                for (int j = 0; j < 4; j++) {
                    int cg = jt * 64 + 4 * tc + j;
                    if (cg > rg) s[i][j] = -1e30f;
                }
            }
        }

#pragma unroll
        for (int i = 0; i < 4; i++) {
            float mt = fmaxf(fmaxf(s[i][0], s[i][1]), fmaxf(s[i][2], s[i][3]));
#pragma unroll
            for (int mm = 8; mm > 0; mm >>= 1)
                mt = fmaxf(mt, __shfl_xor_sync(0xffffffffu, mt, mm));
            float mn = fmaxf(m[i], mt);
            float alpha = expf(m[i] - mn);
            float ls = 0.f;
#pragma unroll
            for (int j = 0; j < 4; j++) {
                float p = expf(s[i][j] - mn);
                s[i][j] = p;
                ls += p;
            }
#pragma unroll
            for (int mm = 8; mm > 0; mm >>= 1)
                ls += __shfl_xor_sync(0xffffffffu, ls, mm);
            l[i] = l[i] * alpha + ls;
            m[i] = mn;
#pragma unroll
            for (int j = 0; j < 4; j++) acc[i][j] *= alpha;
        }

        __syncthreads();
#pragma unroll
        for (int i = 0; i < 4; i++)
#pragma unroll
            for (int j = 0; j < 4; j++)
                Ps[(4 * tr + i) * S + 4 * tc + j] = s[i][j];
        __syncthreads();

#pragma unroll 8
        for (int kk = 0; kk < 64; kk++) {
            float p0 = Ps[(4 * tr + 0) * S + kk];
            float p1 = Ps[(4 * tr + 1) * S + kk];
            float p2 = Ps[(4 * tr + 2) * S + kk];
            float p3 = Ps[(4 * tr + 3) * S + kk];
            float v0 = Vs[kk * S + 4 * tc + 0];
            float v1 = Vs[kk * S + 4 * tc + 1];
            float v2 = Vs[kk * S + 4 * tc + 2];
            float v3 = Vs[kk * S + 4 * tc + 3];
            acc[0][0] += p0 * v0; acc[0][1] += p0 * v1; acc[0][2] += p0 * v2; acc[0][3] += p0 * v3;
            acc[1][0] += p1 * v0; acc[1][1] += p1 * v1; acc[1][2] += p1 * v2; acc[1][3] += p1 * v3;
            acc[2][0] += p2 * v0; acc[2][1] += p2 * v1; acc[2][2] += p2 * v2; acc[2][3] += p2 * v3;
            acc[3][0] += p3 * v0; acc[3][1] += p3 * v1; acc[3][2] += p3 * v2; acc[3][3] += p3 * v3;
        }
    }

#pragma unroll
    for (int i = 0; i < 4; i++) {
        int rg = qi * 64 + 4 * tr + i;
        float invl = 1.0f / l[i];
#pragma unroll
        for (int j = 0; j < 4; j++) {
            o[((size_t)(b * TSEQ + rg)) * DMODEL + h * 64 + 4 * tc + j] = acc[i][j] * invl;
        }
    }
}

// ---------------- router ----------------
__global__ __launch_bounds__(256) void router_kernel(const float* __restrict__ xn,
                                                     const float* __restrict__ rw,
                                                     int* __restrict__ eidx,
                                                     float* __restrict__ wts) {
    int t = blockIdx.x;
    int tid = threadIdx.x, lane = tid & 31, wp = tid >> 5;
    const float* xr = xn + (size_t)t * DMODEL;
    const float* wr = rw + (size_t)wp * DMODEL;
    float s = 0.f;
    for (int d = lane * 4; d < DMODEL; d += 128) {
        float4 a = *(const float4*)(xr + d);
        float4 b = *(const float4*)(wr + d);
        s += a.x * b.x + a.y * b.y + a.z * b.z + a.w * b.w;
    }
#pragma unroll
    for (int mm = 16; mm > 0; mm >>= 1) s += __shfl_xor_sync(0xffffffffu, s, mm);
    __shared__ float lg[8];
    if (lane == 0) lg[wp] = s;
    __syncthreads();
    if (tid == 0) {
        float mx = lg[0];
        for (int e = 1; e < NE; e++) mx = fmaxf(mx, lg[e]);
        float p[NE]; float sum = 0.f;
        for (int e = 0; e < NE; e++) { p[e] = expf(lg[e] - mx); sum += p[e]; }
        float inv = 1.0f / sum;
        for (int e = 0; e < NE; e++) {
            float v = p[e] * inv + 1e-9f;
            p[e] = fminf(fmaxf(v, 1e-9f), 1.0f - 1e-9f);
        }
        int i0 = 0;
        for (int e = 1; e < NE; e++) if (p[e] > p[i0]) i0 = e;
        int i1 = (i0 == 0) ? 1 : 0;
        for (int e = 0; e < NE; e++) if (e != i0 && p[e] > p[i1]) i1 = e;
        float d2 = 1.0f / (p[i0] + p[i1]);
        eidx[2 * t] = i0; eidx[2 * t + 1] = i1;
        wts[2 * t] = p[i0] * d2; wts[2 * t + 1] = p[i1] * d2;
    }
}

// ---------------- build per-expert CSR ----------------
__global__ __launch_bounds__(256) void build_kernel(const int* __restrict__ eidx,
                                                    int* __restrict__ rows,
                                                    int* __restrict__ tile_e) {
    __shared__ int cnt[NE];
    __shared__ int off[NE];
    int tid = threadIdx.x;
    if (tid < NE) cnt[tid] = 0;
    __syncthreads();
    for (int a = tid; a < BT * 2; a += 256) atomicAdd(&cnt[eidx[a]], 1);
    __syncthreads();
    if (tid == 0) {
        int o = 0;
        for (int e = 0; e < NE; e++) { off[e] = o; o = (o + cnt[e] + 127) & ~127; }
        for (int tt = 0; tt < NTILES; tt++) tile_e[tt] = -1;
        for (int e = 0; e < NE; e++) {
            int nt = (cnt[e] + 127) >> 7;
            int t0 = off[e] >> 7;
            for (int i = 0; i < nt; i++) tile_e[t0 + i] = e;
        }
    }
    __syncthreads();
    if (tid < NE) cnt[tid] = 0;
    __syncthreads();
    for (int a = tid; a < BT * 2; a += 256) {
        int e = eidx[a];
        int pos = atomicAdd(&cnt[e], 1);
        rows[a] = off[e] + pos;
    }
}

// ---------------- gather fp16 rows ----------------
__global__ __launch_bounds__(128) void gather_hf(const __half* __restrict__ xhi,
                                                 const __half* __restrict__ xlo,
                                                 const int* __restrict__ rows,
                                                 __half* __restrict__ ghi,
                                                 __half* __restrict__ glo) {
    int a = blockIdx.x;
    int r = rows[a];
    int t = a >> 1;
    int tid = threadIdx.x;
    ((uint4*)(ghi + (size_t)r * DMODEL))[tid] = ((const uint4*)(xhi + (size_t)t * DMODEL))[tid];
    ((uint4*)(glo + (size_t)r * DMODEL))[tid] = ((const uint4*)(xlo + (size_t)t * DMODEL))[tid];
}

// ---------------- combine ----------------
__global__ __launch_bounds__(256) void combine_kernel(const float* __restrict__ xn,
                                                      const float* __restrict__ eo,
                                                      const int* __restrict__ rows,
                                                      const float* __restrict__ wts,
                                                      float* __restrict__ out) {
    int t = blockIdx.x;
    int r0 = rows[2 * t], r1 = rows[2 * t + 1];
    float w0 = wts[2 * t], w1 = wts[2 * t + 1];
    int tid = threadIdx.x;
    float4 a = *(const float4*)(xn + (size_t)t * DMODEL + tid * 4);
    float4 b = *(const float4*)(eo + (size_t)r0 * DMODEL + tid * 4);
    float4 c = *(const float4*)(eo + (size_t)r1 * DMODEL + tid * 4);
    float4 r;
    r.x = a.x + w0 * b.x + w1 * c.x;
    r.y = a.y + w0 * b.y + w1 * c.y;
    r.z = a.z + w0 * b.z + w1 * c.z;
    r.w = a.w + w0 * b.w + w1 * c.w;
    *(float4*)(out + (size_t)t * DMODEL + tid * 4) = r;
}

// ---------------- host launcher ----------------
extern "C" void kernel_launch(void* const* d_in, const int* in_sizes, int n_in,
                              void* d_out, int out_size) {
    const float* x        = (const float*)d_in[0];
    const float* c        = (const float*)d_in[1];
    const float* ln1_w    = (const float*)d_in[2];
    const float* w_qkv    = (const float*)d_in[3];
    const float* w_proj   = (const float*)d_in[4];
    const float* ln2_w    = (const float*)d_in[5];
    const float* router_w = (const float*)d_in[6];
    const float* ew1      = (const float*)d_in[7];
    const float* ew2      = (const float*)d_in[8];
    float* out = (float*)d_out;

    float *p_h, *p_qkv, *p_o, *p_x2, *p_xn, *p_eo, *p_wts;
    int *p_eidx, *p_rows, *p_te;
    __half *p_aHi, *p_aLo, *p_wHi, *p_wLo, *p_xgHi, *p_xgLo, *p_hidHi, *p_hidLo;
    cudaGetSymbolAddress((void**)&p_h,     g_h);
    cudaGetSymbolAddress((void**)&p_qkv,   g_qkv);
    cudaGetSymbolAddress((void**)&p_o,     g_o);
    cudaGetSymbolAddress((void**)&p_x2,    g_x2);
    cudaGetSymbolAddress((void**)&p_xn,    g_xn);
    cudaGetSymbolAddress((void**)&p_eo,    g_eo);
    cudaGetSymbolAddress((void**)&p_wts,   g_wts);
    cudaGetSymbolAddress((void**)&p_eidx,  g_eidx);
    cudaGetSymbolAddress((void**)&p_rows,  g_rows);
    cudaGetSymbolAddress((void**)&p_te,    g_tile_e);
    cudaGetSymbolAddress((void**)&p_aHi,   g_aHi);
    cudaGetSymbolAddress((void**)&p_aLo,   g_aLo);
    cudaGetSymbolAddress((void**)&p_wHi,   g_wHi);
    cudaGetSymbolAddress((void**)&p_wLo,   g_wLo);
    cudaGetSymbolAddress((void**)&p_xgHi,  g_xgHi);
    cudaGetSymbolAddress((void**)&p_xgLo,  g_xgLo);
    cudaGetSymbolAddress((void**)&p_hidHi, g_hidHi);
    cudaGetSymbolAddress((void**)&p_hidLo, g_hidLo);

    cudaFuncSetAttribute(hmma_gemm<0>, cudaFuncAttributeMaxDynamicSharedMemorySize, SMEMB);
    cudaFuncSetAttribute(hmma_gemm<1>, cudaFuncAttributeMaxDynamicSharedMemorySize, SMEMB);
    cudaFuncSetAttribute(hmma_gemm<2>, cudaFuncAttributeMaxDynamicSharedMemorySize, SMEMB);

    // 1) h = LN1(x)*w + c ; split activations + weights to fp16 hi/lo
    ln_kernel<true><<<BT, 256>>>(x, ln1_w, c, p_h);
    split2_kernel<<<(BT * DMODEL / 4 + 255) / 256, 256>>>(p_h, p_aHi, p_aLo, BT * DMODEL / 4);
    split2_kernel<<<(3 * DMODEL * DMODEL / 4 + 255) / 256, 256>>>(w_qkv, p_wHi, p_wLo, 3 * DMODEL * DMODEL / 4);

    // 2) qkv = h @ w_qkv^T
    hmma_gemm<0><<<dim3(24, 32), 128, SMEMB>>>(p_aHi, p_aLo, p_wHi, p_wLo, 0, nullptr,
                                               p_qkv, nullptr, nullptr, nullptr, 3072, 1024);

    // 3) causal attention
    int attn_smem = 4 * 64 * 65 * (int)sizeof(float);
    cudaFuncSetAttribute(attn_kernel, cudaFuncAttributeMaxDynamicSharedMemorySize, attn_smem);
    attn_kernel<<<dim3(16, 64), 256, attn_smem>>>(p_qkv, p_o);

    // 4) x2 = x + o @ w_proj^T
    split2_kernel<<<(BT * DMODEL / 4 + 255) / 256, 256>>>(p_o, p_aHi, p_aLo, BT * DMODEL / 4);
    split2_kernel<<<(DMODEL * DMODEL / 4 + 255) / 256, 256>>>(w_proj, p_wHi, p_wLo, DMODEL * DMODEL / 4);
    hmma_gemm<1><<<dim3(8, 32), 128, SMEMB>>>(p_aHi, p_aLo, p_wHi, p_wLo, 0, nullptr,
                                              p_x2, x, nullptr, nullptr, 1024, 1024);

    // 5) xn = LN2(x2)
    ln_kernel<false><<<BT, 256>>>(p_x2, ln2_w, nullptr, p_xn);

    // 6) router + CSR
    router_kernel<<<BT, 256>>>(p_xn, router_w, p_eidx, p_wts);
    build_kernel<<<1, 256>>>(p_eidx, p_rows, p_te);

    // 7) split xn, gather fp16
    split2_kernel<<<(BT * DMODEL / 4 + 255) / 256, 256>>>(p_xn, p_aHi, p_aLo, BT * DMODEL / 4);
    gather_hf<<<BT * 2, 128>>>(p_aHi, p_aLo, p_rows, p_xgHi, p_xgLo);

    // 8) hid = gelu(xg @ w1[e]^T), fp16 hi/lo out
    split2_kernel<<<(NE * FF * DMODEL / 4 + 255) / 256, 256>>>(ew1, p_wHi, p_wLo, NE * FF * DMODEL / 4);
    hmma_gemm<2><<<dim3(32, NTILES), 128, SMEMB>>>(p_xgHi, p_xgLo, p_wHi, p_wLo,
                                                   (size_t)FF * DMODEL, p_te,
                                                   nullptr, nullptr, p_hidHi, p_hidLo, FF, 1024);

    // 9) eo = hid @ w2[e]^T
    split2_kernel<<<(NE * DMODEL * FF / 4 + 255) / 256, 256>>>(ew2, p_wHi, p_wLo, NE * DMODEL * FF / 4);
    hmma_gemm<0><<<dim3(8, NTILES), 128, SMEMB>>>(p_hidHi, p_hidLo, p_wHi, p_wLo,
                                                  (size_t)DMODEL * FF, p_te,
                                                  p_eo, nullptr, nullptr, nullptr, 1024, 4096);

    // 10) out = xn + sum_k w_k * eo
    combine_kernel<<<BT, 256>>>(p_xn, p_eo, p_rows, p_wts, out);
}

// round 9
// speedup vs baseline: 2.6588x; 1.1307x over previous
#include <cuda_runtime.h>
#include <cuda_fp16.h>
#include <math.h>
#include <stdint.h>

// Problem dims
#define BATCH 4
#define TSEQ  1024
#define BT    4096
#define DMODEL 1024
#define NE    8
#define FF    4096
#define CAP   9216
#define NTILES 72

// ---------------- static device scratch ----------------
__device__ float g_x2 [BT * DMODEL];
__device__ float g_xn [BT * DMODEL];
__device__ float g_eo [CAP * DMODEL];
__device__ int   g_eidx[BT * 2];
__device__ float g_wts [BT * 2];
__device__ int   g_rows[BT * 2];
__device__ int   g_tile_e[NTILES];

// fp16 split scratch
__device__ __half g_aHi [BT * DMODEL];
__device__ __half g_aLo [BT * DMODEL];
__device__ __half g_qkvHi[BT * 3 * DMODEL];
__device__ __half g_qkvLo[BT * 3 * DMODEL];
__device__ __half g_wHi [NE * FF * DMODEL];
__device__ __half g_wLo [NE * FF * DMODEL];
__device__ __half g_xgHi[CAP * DMODEL];
__device__ __half g_xgLo[CAP * DMODEL];
__device__ __half g_hidHi[CAP * FF];
__device__ __half g_hidLo[CAP * FF];

__device__ __forceinline__ float gelu_f(float v) {
    return 0.5f * v * (1.0f + erff(v * 0.70710678118654752f));
}

// ---------------- PTX helpers ----------------
__device__ __forceinline__ uint32_t smem_u32(const void* p) {
    uint32_t a;
    asm("{ .reg .u64 t; cvta.to.shared.u64 t, %1; cvt.u32.u64 %0, t; }" : "=r"(a) : "l"(p));
    return a;
}
__device__ __forceinline__ void cpa16(uint32_t dst, const void* src) {
    asm volatile("cp.async.cg.shared.global [%0], [%1], 16;" :: "r"(dst), "l"(src));
}
__device__ __forceinline__ void cp_commit() { asm volatile("cp.async.commit_group;" ::: "memory"); }
template<int NPEND> __device__ __forceinline__ void cp_wait() {
    asm volatile("cp.async.wait_group %0;" :: "n"(NPEND) : "memory");
}
__device__ __forceinline__ void ldm_x4(uint32_t* r, uint32_t a) {
    asm volatile("ldmatrix.sync.aligned.m8n8.x4.shared.b16 {%0,%1,%2,%3}, [%4];"
        : "=r"(r[0]), "=r"(r[1]), "=r"(r[2]), "=r"(r[3]) : "r"(a));
}
__device__ __forceinline__ void ldm_x4t(uint32_t* r, uint32_t a) {
    asm volatile("ldmatrix.sync.aligned.m8n8.x4.trans.shared.b16 {%0,%1,%2,%3}, [%4];"
        : "=r"(r[0]), "=r"(r[1]), "=r"(r[2]), "=r"(r[3]) : "r"(a));
}
__device__ __forceinline__ void mma_f16(float* d, const uint32_t* a, const uint32_t* b) {
    asm volatile("mma.sync.aligned.m16n8k16.row.col.f32.f16.f16.f32 "
        "{%0,%1,%2,%3}, {%4,%5,%6,%7}, {%8,%9}, {%0,%1,%2,%3};"
        : "+f"(d[0]), "+f"(d[1]), "+f"(d[2]), "+f"(d[3])
        : "r"(a[0]), "r"(a[1]), "r"(a[2]), "r"(a[3]), "r"(b[0]), "r"(b[1]));
}
__device__ __forceinline__ uint32_t pack2h(float x, float y) {
    __half2 h = __halves2half2(__float2half(x), __float2half(y));
    return *(uint32_t*)&h;
}

// ---------------- HMMA NT GEMM (round-8 config, + EPI=3) ----------------
#define NSTG 3
#define KCH  32
#define MATB  (128 * 64)
#define STGB  (4 * MATB)
#define SMEMB (NSTG * STGB)            // 98304 B -> 2 CTAs/SM
#define SWO(row_, chk_) ((uint32_t)((row_) * 64 + (((chk_) ^ (((row_) >> 1) & 3)) << 4)))

// EPI: 0 fp32; 1 fp32+Res; 2 gelu->hi/lo; 3 hi/lo
template<int EPI>
__global__ void __launch_bounds__(128, 2) hmma_gemm(
    const __half* __restrict__ Ahi, const __half* __restrict__ Alo,
    const __half* __restrict__ Bhi, const __half* __restrict__ Blo,
    size_t bstride, const int* __restrict__ tile_e,
    float* __restrict__ C, const float* __restrict__ Res,
    __half* __restrict__ Chi, __half* __restrict__ Clo,
    int N, int K)
{
    extern __shared__ char smem[];
    uint32_t sbase = smem_u32(smem);
    int by = blockIdx.y, bx = blockIdx.x;

    const __half* Bh = Bhi;
    const __half* Bl = Blo;
    if (tile_e) {
        int e = tile_e[by];
        if (e < 0) return;
        Bh += (size_t)e * bstride;
        Bl += (size_t)e * bstride;
    }

    int tid = threadIdx.x, wid = tid >> 5, lane = tid & 31;
    int warpM = (wid >> 1) * 64, warpN = (wid & 1) * 64;

    int lrow = tid >> 2;
    int lchk = tid & 3;
    const __half* pAh = Ahi + (size_t)(by * 128 + lrow) * K + lchk * 8;
    const __half* pAl = Alo + (size_t)(by * 128 + lrow) * K + lchk * 8;
    const __half* pB0 = Bh + (size_t)(bx * 128 + lrow) * K + lchk * 8;
    const __half* pB1 = Bl + (size_t)(bx * 128 + lrow) * K + lchk * 8;
    uint32_t so = SWO(lrow, lchk);

#define LOADST(s_) do { \
        uint32_t sb_ = sbase + ((s_) % NSTG) * STGB; \
        size_t ko_ = (size_t)(s_) * KCH; \
        _Pragma("unroll") \
        for (int p_ = 0; p_ < 4; p_++) { \
            uint32_t o_ = so + p_ * (32 * 64); \
            size_t g_ = ko_ + (size_t)p_ * 32 * K; \
            cpa16(sb_ + o_,            pAh + g_); \
            cpa16(sb_ + MATB + o_,     pAl + g_); \
            cpa16(sb_ + 2 * MATB + o_, pB0 + g_); \
            cpa16(sb_ + 3 * MATB + o_, pB1 + g_); \
        } \
        cp_commit(); \
    } while (0)

    float acc[4][8][4];
#pragma unroll
    for (int i = 0; i < 4; i++)
#pragma unroll
        for (int j = 0; j < 8; j++)
#pragma unroll
            for (int q = 0; q < 4; q++) acc[i][j][q] = 0.f;

    int S = K / KCH;
    LOADST(0);
    LOADST(1);

    int a_r = lane & 15;
    int a_c = lane >> 4;
    int b_r = ((lane >> 3) & 1) * 8 + (lane & 7);
    int b_c = lane >> 4;

    for (int s = 0; s < S; s++) {
        if (s == S - 1) cp_wait<0>(); else cp_wait<1>();
        __syncthreads();
        if (s + 2 < S) LOADST(s + 2);

        uint32_t sa = sbase + (s % NSTG) * STGB;
#pragma unroll
        for (int ks = 0; ks < 2; ks++) {
            uint32_t ah[4][4], al[4][4], bhf[8][2];
#pragma unroll
            for (int i = 0; i < 4; i++) {
                int row = warpM + 16 * i + a_r;
                uint32_t ad = sa + SWO(row, ks * 2 + a_c);
                ldm_x4(ah[i], ad);
                ldm_x4(al[i], ad + MATB);
            }
#pragma unroll
            for (int jj = 0; jj < 4; jj++) {
                int row = warpN + 16 * jj + b_r;
                uint32_t bd = sa + 2 * MATB + SWO(row, ks * 2 + b_c);
                uint32_t q[4];
                ldm_x4(q, bd);
                bhf[2 * jj][0] = q[0]; bhf[2 * jj][1] = q[2];
                bhf[2 * jj + 1][0] = q[1]; bhf[2 * jj + 1][1] = q[3];
            }
#pragma unroll
            for (int i = 0; i < 4; i++)
#pragma unroll
                for (int j = 0; j < 8; j++)
                    mma_f16(acc[i][j], ah[i], bhf[j]);
#pragma unroll
            for (int i = 0; i < 4; i++)
#pragma unroll
                for (int j = 0; j < 8; j++)
                    mma_f16(acc[i][j], al[i], bhf[j]);
            uint32_t blf[8][2];
#pragma unroll
            for (int jj = 0; jj < 4; jj++) {
                int row = warpN + 16 * jj + b_r;
                uint32_t bd = sa + 3 * MATB + SWO(row, ks * 2 + b_c);
                uint32_t p[4];
                ldm_x4(p, bd);
                blf[2 * jj][0] = p[0]; blf[2 * jj][1] = p[2];
                blf[2 * jj + 1][0] = p[1]; blf[2 * jj + 1][1] = p[3];
            }
#pragma unroll
            for (int i = 0; i < 4; i++)
#pragma unroll
                for (int j = 0; j < 8; j++)
                    mma_f16(acc[i][j], ah[i], blf[j]);
        }
    }
#undef LOADST

    int r0 = lane >> 2, c0 = (lane & 3) * 2;
#pragma unroll
    for (int i = 0; i < 4; i++) {
#pragma unroll
        for (int j = 0; j < 8; j++) {
            int row = by * 128 + warpM + 16 * i + r0;
            int col = bx * 128 + warpN + 8 * j + c0;
#pragma unroll
            for (int half = 0; half < 2; half++) {
                size_t off = (size_t)(row + half * 8) * N + col;
                float v0 = acc[i][j][2 * half];
                float v1 = acc[i][j][2 * half + 1];
                if (EPI == 0) {
                    *(float2*)(C + off) = make_float2(v0, v1);
                } else if (EPI == 1) {
                    float2 rr = *(const float2*)(Res + off);
                    *(float2*)(C + off) = make_float2(v0 + rr.x, v1 + rr.y);
                } else {
                    if (EPI == 2) { v0 = gelu_f(v0); v1 = gelu_f(v1); }
                    __half h0 = __float2half(v0);
                    __half h1 = __float2half(v1);
                    __half l0 = __float2half(v0 - __half2float(h0));
                    __half l1 = __float2half(v1 - __half2float(h1));
                    *(__half2*)(Chi + off) = __halves2half2(h0, h1);
                    *(__half2*)(Clo + off) = __halves2half2(l0, l1);
                }
            }
        }
    }
}

// ---------------- HMMA flash attention ----------------
// 64-row Q tile per CTA, 4 warps x 16 rows. dh=64. fp16 3-term everywhere.
// smem tiles: 64 rows x 128B (8 chunks of 16B), swizzle chk^= (row&7).
#define SWO8(row_, chk_) ((uint32_t)((row_) * 128 + (((chk_) ^ ((row_) & 7)) << 4)))
#define AT_Q   0
#define AT_QL  8192
#define AT_K   16384
#define AT_KL  24576
#define AT_V   32768
#define AT_VL  40960
#define AT_SMEM 49152

__global__ void __launch_bounds__(128) attn_hmma(
    const __half* __restrict__ qkvHi, const __half* __restrict__ qkvLo,
    __half* __restrict__ oHi, __half* __restrict__ oLo)
{
    extern __shared__ char smem[];
    uint32_t sbase = smem_u32(smem);
    int qi = blockIdx.x;
    int bh = blockIdx.y;
    int b = bh >> 4, h = bh & 15;
    int tid = threadIdx.x, wid = tid >> 5, lane = tid & 31;
    int warpM = wid * 16;

    // gmem base for this (b, h): row stride 3072 halfs
    const size_t tokbase = (size_t)b * TSEQ * 3072;
    const __half* qH = qkvHi + tokbase + h * 64;
    const __half* qL = qkvLo + tokbase + h * 64;
    const __half* kH = qH + 1024;
    const __half* kL = qL + 1024;
    const __half* vH = qH + 2048;
    const __half* vL = qL + 2048;

    // load mapping: 64 rows x 8 chunks, 128 threads -> 4 chunks/thread/matrix
    int lrow = tid >> 1;               // 0..63
    int lc0 = (tid & 1) * 4;           // chunk 0..3 or 4..7

    // Q tiles (once)
#pragma unroll
    for (int i = 0; i < 4; i++) {
        int chk = lc0 + i;
        size_t g = (size_t)(qi * 64 + lrow) * 3072 + chk * 8;
        cpa16(sbase + AT_Q + SWO8(lrow, chk), qH + g);
        cpa16(sbase + AT_QL + SWO8(lrow, chk), qL + g);
    }
    cp_commit();

    float acc_o[8][4];
#pragma unroll
    for (int j = 0; j < 8; j++)
#pragma unroll
        for (int q = 0; q < 4; q++) acc_o[j][q] = 0.f;
    float mrow[2] = {-1e30f, -1e30f};
    float lrw[2] = {0.f, 0.f};

    int a_r = lane & 15;
    int a_c = lane >> 4;
    int b_r = ((lane >> 3) & 1) * 8 + (lane & 7);
    int b_c = lane >> 4;

    for (int jt = 0; jt <= qi; jt++) {
        __syncthreads();   // previous K/V reads done
#pragma unroll
        for (int i = 0; i < 4; i++) {
            int chk = lc0 + i;
            size_t g = (size_t)(jt * 64 + lrow) * 3072 + chk * 8;
            uint32_t soff = SWO8(lrow, chk);
            cpa16(sbase + AT_K + soff, kH + g);
            cpa16(sbase + AT_KL + soff, kL + g);
            cpa16(sbase + AT_V + soff, vH + g);
            cpa16(sbase + AT_VL + soff, vL + g);
        }
        cp_commit();
        cp_wait<0>();
        __syncthreads();

        // S = Q K^T (3-term), 16x64 per warp
        float s[8][4];
#pragma unroll
        for (int j = 0; j < 8; j++)
#pragma unroll
            for (int q = 0; q < 4; q++) s[j][q] = 0.f;

#pragma unroll
        for (int kc = 0; kc < 4; kc++) {
            uint32_t ah[4], al[4], kf[8][2];
            uint32_t ad = sbase + AT_Q + SWO8(warpM + a_r, kc * 2 + a_c);
            ldm_x4(ah, ad);
            ldm_x4(al, ad + (AT_QL - AT_Q));
#pragma unroll
            for (int jj = 0; jj < 4; jj++) {
                uint32_t bd = sbase + AT_K + SWO8(16 * jj + b_r, kc * 2 + b_c);
                uint32_t q[4];
                ldm_x4(q, bd);
                kf[2 * jj][0] = q[0]; kf[2 * jj][1] = q[2];
                kf[2 * jj + 1][0] = q[1]; kf[2 * jj + 1][1] = q[3];
            }
#pragma unroll
            for (int j = 0; j < 8; j++)
                mma_f16(s[j], ah, kf[j]);
#pragma unroll
            for (int j = 0; j < 8; j++)
                mma_f16(s[j], al, kf[j]);
            uint32_t klf[8][2];
#pragma unroll
            for (int jj = 0; jj < 4; jj++) {
                uint32_t bd = sbase + AT_KL + SWO8(16 * jj + b_r, kc * 2 + b_c);
                uint32_t p[4];
                ldm_x4(p, bd);
                klf[2 * jj][0] = p[0]; klf[2 * jj][1] = p[2];
                klf[2 * jj + 1][0] = p[1]; klf[2 * jj + 1][1] = p[3];
            }
#pragma unroll
            for (int j = 0; j < 8; j++)
                mma_f16(s[j], ah, klf[j]);
        }

        // scale + causal mask
        int rA = qi * 64 + warpM + (lane >> 2);
        int cbase = jt * 64 + (lane & 3) * 2;
#pragma unroll
        for (int j = 0; j < 8; j++) {
#pragma unroll
            for (int q = 0; q < 4; q++) {
                float v = s[j][q] * 0.125f;
                if (jt == qi) {
                    int col = cbase + j * 8 + (q & 1);
                    int row = rA + (q >= 2 ? 8 : 0);
                    if (col > row) v = -1e30f;
                }
                s[j][q] = v;
            }
        }

        // online softmax (rows: half 0 -> q{0,1}, half 1 -> q{2,3})
#pragma unroll
        for (int hf = 0; hf < 2; hf++) {
            float mt = -1e30f;
#pragma unroll
            for (int j = 0; j < 8; j++)
                mt = fmaxf(mt, fmaxf(s[j][2 * hf], s[j][2 * hf + 1]));
            mt = fmaxf(mt, __shfl_xor_sync(0xffffffffu, mt, 1));
            mt = fmaxf(mt, __shfl_xor_sync(0xffffffffu, mt, 2));
            float mn = fmaxf(mrow[hf], mt);
            float alpha = __expf(mrow[hf] - mn);
            float ls = 0.f;
#pragma unroll
            for (int j = 0; j < 8; j++) {
                float p0 = __expf(s[j][2 * hf] - mn);
                float p1 = __expf(s[j][2 * hf + 1] - mn);
                s[j][2 * hf] = p0; s[j][2 * hf + 1] = p1;
                ls += p0 + p1;
            }
            ls += __shfl_xor_sync(0xffffffffu, ls, 1);
            ls += __shfl_xor_sync(0xffffffffu, ls, 2);
            lrw[hf] = lrw[hf] * alpha + ls;
            mrow[hf] = mn;
#pragma unroll
            for (int j = 0; j < 8; j++) {
                acc_o[j][2 * hf] *= alpha;
                acc_o[j][2 * hf + 1] *= alpha;
            }
        }

        // O += P V  (3-term; P from fragments, V via ldmatrix.trans)
#pragma unroll
        for (int kc = 0; kc < 4; kc++) {
            uint32_t phi[4], plo[4];
            {
                float p00 = s[2 * kc][0], p01 = s[2 * kc][1];
                float p02 = s[2 * kc][2], p03 = s[2 * kc][3];
                float p10 = s[2 * kc + 1][0], p11 = s[2 * kc + 1][1];
                float p12 = s[2 * kc + 1][2], p13 = s[2 * kc + 1][3];
                phi[0] = pack2h(p00, p01);
                phi[1] = pack2h(p02, p03);
                phi[2] = pack2h(p10, p11);
                phi[3] = pack2h(p12, p13);
                __half2 h0 = *(__half2*)&phi[0];
                __half2 h1 = *(__half2*)&phi[1];
                __half2 h2 = *(__half2*)&phi[2];
                __half2 h3 = *(__half2*)&phi[3];
                plo[0] = pack2h(p00 - __half2float(__low2half(h0)), p01 - __half2float(__high2half(h0)));
                plo[1] = pack2h(p02 - __half2float(__low2half(h1)), p03 - __half2float(__high2half(h1)));
                plo[2] = pack2h(p10 - __half2float(__low2half(h2)), p11 - __half2float(__high2half(h2)));
                plo[3] = pack2h(p12 - __half2float(__low2half(h3)), p13 - __half2float(__high2half(h3)));
            }
            uint32_t vfh[8][2], vfl[8][2];
#pragma unroll
            for (int g = 0; g < 4; g++) {
                uint32_t bd = sbase + AT_V + SWO8(kc * 16 + b_r, 2 * g + b_c);
                uint32_t q[4];
                ldm_x4t(q, bd);
                vfh[2 * g][0] = q[0]; vfh[2 * g][1] = q[1];       // trans pairing!
                vfh[2 * g + 1][0] = q[2]; vfh[2 * g + 1][1] = q[3];
                uint32_t p[4];
                ldm_x4t(p, bd + (AT_VL - AT_V));
                vfl[2 * g][0] = p[0]; vfl[2 * g][1] = p[1];
                vfl[2 * g + 1][0] = p[2]; vfl[2 * g + 1][1] = p[3];
            }
#pragma unroll
            for (int j = 0; j < 8; j++)
                mma_f16(acc_o[j], phi, vfh[j]);
#pragma unroll
            for (int j = 0; j < 8; j++)
                mma_f16(acc_o[j], phi, vfl[j]);
#pragma unroll
            for (int j = 0; j < 8; j++)
                mma_f16(acc_o[j], plo, vfh[j]);
        }
    }

    // epilogue: normalize, split hi/lo, store to aHi/aLo (input of proj GEMM)
    float inv0 = 1.0f / lrw[0];
    float inv1 = 1.0f / lrw[1];
#pragma unroll
    for (int j = 0; j < 8; j++) {
#pragma unroll
        for (int hf = 0; hf < 2; hf++) {
            int row = b * TSEQ + qi * 64 + warpM + (lane >> 2) + hf * 8;
            int col = h * 64 + j * 8 + (lane & 3) * 2;
            float inv = hf ? inv1 : inv0;
            float v0 = acc_o[j][2 * hf] * inv;
            float v1 = acc_o[j][2 * hf + 1] * inv;
            __half h0 = __float2half(v0);
            __half h1 = __float2half(v1);
            __half l0 = __float2half(v0 - __half2float(h0));
            __half l1 = __float2half(v1 - __half2float(h1));
            size_t off = (size_t)row * DMODEL + col;
            *(__half2*)(oHi + off) = __halves2half2(h0, h1);
            *(__half2*)(oLo + off) = __halves2half2(l0, l1);
        }
    }
}

// ---------------- fp32 -> fp16 hi/lo split ----------------
__global__ __launch_bounds__(256) void split2_kernel(const float* __restrict__ x,
                                                     __half* __restrict__ hi,
                                                     __half* __restrict__ lo, int n4) {
    int i = blockIdx.x * 256 + threadIdx.x;
    if (i >= n4) return;
    float4 v = ((const float4*)x)[i];
    __half h0 = __float2half(v.x), h1 = __float2half(v.y);
    __half h2 = __float2half(v.z), h3 = __float2half(v.w);
    __half l0 = __float2half(v.x - __half2float(h0));
    __half l1 = __float2half(v.y - __half2float(h1));
    __half l2 = __float2half(v.z - __half2float(h2));
    __half l3 = __float2half(v.w - __half2float(h3));
    ((__half2*)hi)[2 * i]     = __halves2half2(h0, h1);
    ((__half2*)hi)[2 * i + 1] = __halves2half2(h2, h3);
    ((__half2*)lo)[2 * i]     = __halves2half2(l0, l1);
    ((__half2*)lo)[2 * i + 1] = __halves2half2(l2, l3);
}

// ---------------- LayerNorm fused with hi/lo split ----------------
// MODE 0: ln1 (+c), outputs hi/lo only. MODE 1: ln2, outputs fp32 + hi/lo.
template<int MODE>
__global__ __launch_bounds__(256) void ln_fused(const float* __restrict__ x,
                                                const float* __restrict__ w,
                                                const float* __restrict__ c,
                                                float* __restrict__ outf,
                                                __half* __restrict__ hi,
                                                __half* __restrict__ lo) {
    int row = blockIdx.x;
    int tid = threadIdx.x;
    const float* xr = x + (size_t)row * DMODEL;
    float4 v = *(const float4*)(xr + tid * 4);

    __shared__ float red[8];
    __shared__ float tot;

    float s = v.x + v.y + v.z + v.w;
#pragma unroll
    for (int m = 16; m > 0; m >>= 1) s += __shfl_xor_sync(0xffffffffu, s, m);
    if ((tid & 31) == 0) red[tid >> 5] = s;
    __syncthreads();
    if (tid == 0) { float t = 0.f; for (int i = 0; i < 8; i++) t += red[i]; tot = t; }
    __syncthreads();
    float mean = tot * (1.0f / DMODEL);
    float dx = v.x - mean, dy = v.y - mean, dz = v.z - mean, dw = v.w - mean;
    float s2 = dx * dx + dy * dy + dz * dz + dw * dw;
    __syncthreads();
#pragma unroll
    for (int m = 16; m > 0; m >>= 1) s2 += __shfl_xor_sync(0xffffffffu, s2, m);
    if ((tid & 31) == 0) red[tid >> 5] = s2;
    __syncthreads();
    if (tid == 0) { float t = 0.f; for (int i = 0; i < 8; i++) t += red[i]; tot = t; }
    __syncthreads();
    float inv = rsqrtf(tot * (1.0f / DMODEL) + 1e-5f);

    int d0 = tid * 4;
    float4 w4 = *(const float4*)(w + d0);
    float r0 = dx * inv * w4.x;
    float r1 = dy * inv * w4.y;
    float r2 = dz * inv * w4.z;
    float r3 = dw * inv * w4.w;
    if (MODE == 0) {
        int b = row >> 10;
        float4 c4 = *(const float4*)(c + (size_t)b * DMODEL + d0);
        r0 += c4.x; r1 += c4.y; r2 += c4.z; r3 += c4.w;
    }
    if (MODE == 1)
        *(float4*)(outf + (size_t)row * DMODEL + d0) = make_float4(r0, r1, r2, r3);
    __half h0 = __float2half(r0), h1 = __float2half(r1);
    __half h2 = __float2half(r2), h3 = __float2half(r3);
    __half l0 = __float2half(r0 - __half2float(h0));
    __half l1 = __float2half(r1 - __half2float(h1));
    __half l2 = __float2half(r2 - __half2float(h2));
    __half l3 = __float2half(r3 - __half2float(h3));
    size_t ho = (size_t)row * DMODEL + d0;
    *(__half2*)(hi + ho)     = __halves2half2(h0, h1);
    *(__half2*)(hi + ho + 2) = __halves2half2(h2, h3);
    *(__half2*)(lo + ho)     = __halves2half2(l0, l1);
    *(__half2*)(lo + ho + 2) = __halves2half2(l2, l3);
}

// ---------------- router ----------------
__global__ __launch_bounds__(256) void router_kernel(const float* __restrict__ xn,
                                                     const float* __restrict__ rw,
                                                     int* __restrict__ eidx,
                                                     float* __restrict__ wts) {
    int t = blockIdx.x;
    int tid = threadIdx.x, lane = tid & 31, wp = tid >> 5;
    const float* xr = xn + (size_t)t * DMODEL;
    const float* wr = rw + (size_t)wp * DMODEL;
    float s = 0.f;
    for (int d = lane * 4; d < DMODEL; d += 128) {
        float4 a = *(const float4*)(xr + d);
        float4 b = *(const float4*)(wr + d);
        s += a.x * b.x + a.y * b.y + a.z * b.z + a.w * b.w;
    }
#pragma unroll
    for (int mm = 16; mm > 0; mm >>= 1) s += __shfl_xor_sync(0xffffffffu, s, mm);
    __shared__ float lg[8];
    if (lane == 0) lg[wp] = s;
    __syncthreads();
    if (tid == 0) {
        float mx = lg[0];
        for (int e = 1; e < NE; e++) mx = fmaxf(mx, lg[e]);
        float p[NE]; float sum = 0.f;
        for (int e = 0; e < NE; e++) { p[e] = expf(lg[e] - mx); sum += p[e]; }
        float inv = 1.0f / sum;
        for (int e = 0; e < NE; e++) {
            float v = p[e] * inv + 1e-9f;
            p[e] = fminf(fmaxf(v, 1e-9f), 1.0f - 1e-9f);
        }
        int i0 = 0;
        for (int e = 1; e < NE; e++) if (p[e] > p[i0]) i0 = e;
        int i1 = (i0 == 0) ? 1 : 0;
        for (int e = 0; e < NE; e++) if (e != i0 && p[e] > p[i1]) i1 = e;
        float d2 = 1.0f / (p[i0] + p[i1]);
        eidx[2 * t] = i0; eidx[2 * t + 1] = i1;
        wts[2 * t] = p[i0] * d2; wts[2 * t + 1] = p[i1] * d2;
    }
}

// ---------------- build per-expert CSR ----------------
__global__ __launch_bounds__(256) void build_kernel(const int* __restrict__ eidx,
                                                    int* __restrict__ rows,
                                                    int* __restrict__ tile_e) {
    __shared__ int cnt[NE];
    __shared__ int off[NE];
    int tid = threadIdx.x;
    if (tid < NE) cnt[tid] = 0;
    __syncthreads();
    for (int a = tid; a < BT * 2; a += 256) atomicAdd(&cnt[eidx[a]], 1);
    __syncthreads();
    if (tid == 0) {
        int o = 0;
        for (int e = 0; e < NE; e++) { off[e] = o; o = (o + cnt[e] + 127) & ~127; }
        for (int tt = 0; tt < NTILES; tt++) tile_e[tt] = -1;
        for (int e = 0; e < NE; e++) {
            int nt = (cnt[e] + 127) >> 7;
            int t0 = off[e] >> 7;
            for (int i = 0; i < nt; i++) tile_e[t0 + i] = e;
        }
    }
    __syncthreads();
    if (tid < NE) cnt[tid] = 0;
    __syncthreads();
    for (int a = tid; a < BT * 2; a += 256) {
        int e = eidx[a];
        int pos = atomicAdd(&cnt[e], 1);
        rows[a] = off[e] + pos;
    }
}

// ---------------- gather fp16 rows ----------------
__global__ __launch_bounds__(128) void gather_hf(const __half* __restrict__ xhi,
                                                 const __half* __restrict__ xlo,
                                                 const int* __restrict__ rows,
                                                 __half* __restrict__ ghi,
                                                 __half* __restrict__ glo) {
    int a = blockIdx.x;
    int r = rows[a];
    int t = a >> 1;
    int tid = threadIdx.x;
    ((uint4*)(ghi + (size_t)r * DMODEL))[tid] = ((const uint4*)(xhi + (size_t)t * DMODEL))[tid];
    ((uint4*)(glo + (size_t)r * DMODEL))[tid] = ((const uint4*)(xlo + (size_t)t * DMODEL))[tid];
}

// ---------------- combine ----------------
__global__ __launch_bounds__(256) void combine_kernel(const float* __restrict__ xn,
                                                      const float* __restrict__ eo,
                                                      const int* __restrict__ rows,
                                                      const float* __restrict__ wts,
                                                      float* __restrict__ out) {
    int t = blockIdx.x;
    int r0 = rows[2 * t], r1 = rows[2 * t + 1];
    float w0 = wts[2 * t], w1 = wts[2 * t + 1];
    int tid = threadIdx.x;
    float4 a = *(const float4*)(xn + (size_t)t * DMODEL + tid * 4);
    float4 b = *(const float4*)(eo + (size_t)r0 * DMODEL + tid * 4);
    float4 c = *(const float4*)(eo + (size_t)r1 * DMODEL + tid * 4);
    float4 r;
    r.x = a.x + w0 * b.x + w1 * c.x;
    r.y = a.y + w0 * b.y + w1 * c.y;
    r.z = a.z + w0 * b.z + w1 * c.z;
    r.w = a.w + w0 * b.w + w1 * c.w;
    *(float4*)(out + (size_t)t * DMODEL + tid * 4) = r;
}

// ---------------- host launcher ----------------
extern "C" void kernel_launch(void* const* d_in, const int* in_sizes, int n_in,
                              void* d_out, int out_size) {
    const float* x        = (const float*)d_in[0];
    const float* c        = (const float*)d_in[1];
    const float* ln1_w    = (const float*)d_in[2];
    const float* w_qkv    = (const float*)d_in[3];
    const float* w_proj   = (const float*)d_in[4];
    const float* ln2_w    = (const float*)d_in[5];
    const float* router_w = (const float*)d_in[6];
    const float* ew1      = (const float*)d_in[7];
    const float* ew2      = (const float*)d_in[8];
    float* out = (float*)d_out;

    float *p_x2, *p_xn, *p_eo, *p_wts;
    int *p_eidx, *p_rows, *p_te;
    __half *p_aHi, *p_aLo, *p_qkvHi, *p_qkvLo, *p_wHi, *p_wLo;
    __half *p_xgHi, *p_xgLo, *p_hidHi, *p_hidLo;
    cudaGetSymbolAddress((void**)&p_x2,    g_x2);
    cudaGetSymbolAddress((void**)&p_xn,    g_xn);
    cudaGetSymbolAddress((void**)&p_eo,    g_eo);
    cudaGetSymbolAddress((void**)&p_wts,   g_wts);
    cudaGetSymbolAddress((void**)&p_eidx,  g_eidx);
    cudaGetSymbolAddress((void**)&p_rows,  g_rows);
    cudaGetSymbolAddress((void**)&p_te,    g_tile_e);
    cudaGetSymbolAddress((void**)&p_aHi,   g_aHi);
    cudaGetSymbolAddress((void**)&p_aLo,   g_aLo);
    cudaGetSymbolAddress((void**)&p_qkvHi, g_qkvHi);
    cudaGetSymbolAddress((void**)&p_qkvLo, g_qkvLo);
    cudaGetSymbolAddress((void**)&p_wHi,   g_wHi);
    cudaGetSymbolAddress((void**)&p_wLo,   g_wLo);
    cudaGetSymbolAddress((void**)&p_xgHi,  g_xgHi);
    cudaGetSymbolAddress((void**)&p_xgLo,  g_xgLo);
    cudaGetSymbolAddress((void**)&p_hidHi, g_hidHi);
    cudaGetSymbolAddress((void**)&p_hidLo, g_hidLo);

    cudaFuncSetAttribute(hmma_gemm<0>, cudaFuncAttributeMaxDynamicSharedMemorySize, SMEMB);
    cudaFuncSetAttribute(hmma_gemm<1>, cudaFuncAttributeMaxDynamicSharedMemorySize, SMEMB);
    cudaFuncSetAttribute(hmma_gemm<2>, cudaFuncAttributeMaxDynamicSharedMemorySize, SMEMB);
    cudaFuncSetAttribute(hmma_gemm<3>, cudaFuncAttributeMaxDynamicSharedMemorySize, SMEMB);
    cudaFuncSetAttribute(attn_hmma, cudaFuncAttributeMaxDynamicSharedMemorySize, AT_SMEM);

    // 1) h = LN1(x)*w + c -> fp16 hi/lo directly
    ln_fused<0><<<BT, 256>>>(x, ln1_w, c, nullptr, p_aHi, p_aLo);
    split2_kernel<<<(3 * DMODEL * DMODEL / 4 + 255) / 256, 256>>>(w_qkv, p_wHi, p_wLo, 3 * DMODEL * DMODEL / 4);

    // 2) qkv = h @ w_qkv^T -> fp16 hi/lo
    hmma_gemm<3><<<dim3(24, 32), 128, SMEMB>>>(p_aHi, p_aLo, p_wHi, p_wLo, 0, nullptr,
                                               nullptr, nullptr, p_qkvHi, p_qkvLo, 3072, 1024);

    // 3) causal attention (HMMA) -> o as fp16 hi/lo into aHi/aLo
    attn_hmma<<<dim3(16, 64), 128, AT_SMEM>>>(p_qkvHi, p_qkvLo, p_aHi, p_aLo);

    // 4) x2 = x + o @ w_proj^T
    split2_kernel<<<(DMODEL * DMODEL / 4 + 255) / 256, 256>>>(w_proj, p_wHi, p_wLo, DMODEL * DMODEL / 4);
    hmma_gemm<1><<<dim3(8, 32), 128, SMEMB>>>(p_aHi, p_aLo, p_wHi, p_wLo, 0, nullptr,
                                              p_x2, x, nullptr, nullptr, 1024, 1024);

    // 5) xn = LN2(x2) -> fp32 + fp16 hi/lo
    ln_fused<1><<<BT, 256>>>(p_x2, ln2_w, nullptr, p_xn, p_aHi, p_aLo);

    // 6) router + CSR
    router_kernel<<<BT, 256>>>(p_xn, router_w, p_eidx, p_wts);
    build_kernel<<<1, 256>>>(p_eidx, p_rows, p_te);

    // 7) gather fp16
    gather_hf<<<BT * 2, 128>>>(p_aHi, p_aLo, p_rows, p_xgHi, p_xgLo);

    // 8) hid = gelu(xg @ w1[e]^T), fp16 hi/lo out
    split2_kernel<<<(NE * FF * DMODEL / 4 + 255) / 256, 256>>>(ew1, p_wHi, p_wLo, NE * FF * DMODEL / 4);
    hmma_gemm<2><<<dim3(32, NTILES), 128, SMEMB>>>(p_xgHi, p_xgLo, p_wHi, p_wLo,
                                                   (size_t)FF * DMODEL, p_te,
                                                   nullptr, nullptr, p_hidHi, p_hidLo, FF, 1024);

    // 9) eo = hid @ w2[e]^T
    split2_kernel<<<(NE * DMODEL * FF / 4 + 255) / 256, 256>>>(ew2, p_wHi, p_wLo, NE * DMODEL * FF / 4);
    hmma_gemm<0><<<dim3(8, NTILES), 128, SMEMB>>>(p_hidHi, p_hidLo, p_wHi, p_wLo,
                                                  (size_t)DMODEL * FF, p_te,
                                                  p_eo, nullptr, nullptr, nullptr, 1024, 4096);

    // 10) out = xn + sum_k w_k * eo
    combine_kernel<<<BT, 256>>>(p_xn, p_eo, p_rows, p_wts, out);
}

// round 10
// speedup vs baseline: 3.3882x; 1.2743x over previous
#include <cuda_runtime.h>
#include <cuda_fp16.h>
#include <math.h>
#include <stdint.h>

// Problem dims
#define BATCH 4
#define TSEQ  1024
#define BT    4096
#define DMODEL 1024
#define NE    8
#define FF    4096
#define CAP   9216
#define NTILES 72

// ---------------- static device scratch ----------------
__device__ float g_x2 [BT * DMODEL];
__device__ float g_xn [BT * DMODEL];
__device__ float g_eo [CAP * DMODEL];
__device__ int   g_eidx[BT * 2];
__device__ float g_wts [BT * 2];
__device__ int   g_rows[BT * 2];
__device__ int   g_tile_e[NTILES];

// fp16 split scratch
__device__ __half g_aHi [BT * DMODEL];
__device__ __half g_aLo [BT * DMODEL];
__device__ __half g_qkvHi[BT * 3 * DMODEL];
__device__ __half g_qkvLo[BT * 3 * DMODEL];
__device__ __half g_wHi [NE * FF * DMODEL];
__device__ __half g_wLo [NE * FF * DMODEL];
__device__ __half g_xgHi[CAP * DMODEL];
__device__ __half g_xgLo[CAP * DMODEL];
__device__ __half g_hidHi[CAP * FF];
__device__ __half g_hidLo[CAP * FF];

__device__ __forceinline__ float gelu_f(float v) {
    return 0.5f * v * (1.0f + erff(v * 0.70710678118654752f));
}

// ---------------- PTX helpers ----------------
__device__ __forceinline__ uint32_t smem_u32(const void* p) {
    uint32_t a;
    asm("{ .reg .u64 t; cvta.to.shared.u64 t, %1; cvt.u32.u64 %0, t; }" : "=r"(a) : "l"(p));
    return a;
}
__device__ __forceinline__ void cpa16(uint32_t dst, const void* src) {
    asm volatile("cp.async.cg.shared.global [%0], [%1], 16;" :: "r"(dst), "l"(src));
}
__device__ __forceinline__ void cp_commit() { asm volatile("cp.async.commit_group;" ::: "memory"); }
template<int NPEND> __device__ __forceinline__ void cp_wait() {
    asm volatile("cp.async.wait_group %0;" :: "n"(NPEND) : "memory");
}
__device__ __forceinline__ void ldm_x4(uint32_t* r, uint32_t a) {
    asm volatile("ldmatrix.sync.aligned.m8n8.x4.shared.b16 {%0,%1,%2,%3}, [%4];"
        : "=r"(r[0]), "=r"(r[1]), "=r"(r[2]), "=r"(r[3]) : "r"(a));
}
__device__ __forceinline__ void ldm_x4t(uint32_t* r, uint32_t a) {
    asm volatile("ldmatrix.sync.aligned.m8n8.x4.trans.shared.b16 {%0,%1,%2,%3}, [%4];"
        : "=r"(r[0]), "=r"(r[1]), "=r"(r[2]), "=r"(r[3]) : "r"(a));
}
__device__ __forceinline__ void mma_f16(float* d, const uint32_t* a, const uint32_t* b) {
    asm volatile("mma.sync.aligned.m16n8k16.row.col.f32.f16.f16.f32 "
        "{%0,%1,%2,%3}, {%4,%5,%6,%7}, {%8,%9}, {%0,%1,%2,%3};"
        : "+f"(d[0]), "+f"(d[1]), "+f"(d[2]), "+f"(d[3])
        : "r"(a[0]), "r"(a[1]), "r"(a[2]), "r"(a[3]), "r"(b[0]), "r"(b[1]));
}
__device__ __forceinline__ uint32_t pack2h(float x, float y) {
    __half2 h = __halves2half2(__float2half(x), __float2half(y));
    return *(uint32_t*)&h;
}

// ---------------- HMMA NT GEMM ----------------
// TERMS=3: D = Ahi*Bhi + Ahi*Blo + Alo*Bhi   (full precision path)
// TERMS=2: D = Ahi*B + Alo*B = (Ahi+Alo)*B   (post-router path; error = B quant)
#define NSTG 3
#define KCH  32
#define MATB  (128 * 64)
#define SWO(row_, chk_) ((uint32_t)((row_) * 64 + (((chk_) ^ (((row_) >> 1) & 3)) << 4)))

// EPI: 0 fp32; 1 fp32+Res; 2 gelu->hi/lo; 3 hi/lo
template<int EPI, int TERMS>
__global__ void __launch_bounds__(128, 2) hmma_gemm(
    const __half* __restrict__ Ahi, const __half* __restrict__ Alo,
    const __half* __restrict__ Bhi, const __half* __restrict__ Blo,
    size_t bstride, const int* __restrict__ tile_e,
    float* __restrict__ C, const float* __restrict__ Res,
    __half* __restrict__ Chi, __half* __restrict__ Clo,
    int N, int K)
{
    constexpr int NMAT = (TERMS == 3) ? 4 : 3;
    constexpr uint32_t STGB = NMAT * MATB;
    extern __shared__ char smem[];
    uint32_t sbase = smem_u32(smem);
    int by = blockIdx.y, bx = blockIdx.x;

    const __half* Bh = Bhi;
    const __half* Bl = Blo;
    if (tile_e) {
        int e = tile_e[by];
        if (e < 0) return;
        Bh += (size_t)e * bstride;
        if (TERMS == 3) Bl += (size_t)e * bstride;
    }

    int tid = threadIdx.x, wid = tid >> 5, lane = tid & 31;
    int warpM = (wid >> 1) * 64, warpN = (wid & 1) * 64;

    int lrow = tid >> 2;
    int lchk = tid & 3;
    const __half* pAh = Ahi + (size_t)(by * 128 + lrow) * K + lchk * 8;
    const __half* pAl = Alo + (size_t)(by * 128 + lrow) * K + lchk * 8;
    const __half* pB0 = Bh + (size_t)(bx * 128 + lrow) * K + lchk * 8;
    const __half* pB1 = (TERMS == 3) ? (Bl + (size_t)(bx * 128 + lrow) * K + lchk * 8) : nullptr;
    uint32_t so = SWO(lrow, lchk);

#define LOADST(s_) do { \
        uint32_t sb_ = sbase + ((s_) % NSTG) * STGB; \
        size_t ko_ = (size_t)(s_) * KCH; \
        _Pragma("unroll") \
        for (int p_ = 0; p_ < 4; p_++) { \
            uint32_t o_ = so + p_ * (32 * 64); \
            size_t g_ = ko_ + (size_t)p_ * 32 * K; \
            cpa16(sb_ + o_,            pAh + g_); \
            cpa16(sb_ + MATB + o_,     pAl + g_); \
            cpa16(sb_ + 2 * MATB + o_, pB0 + g_); \
            if (TERMS == 3) cpa16(sb_ + 3 * MATB + o_, pB1 + g_); \
        } \
        cp_commit(); \
    } while (0)

    float acc[4][8][4];
#pragma unroll
    for (int i = 0; i < 4; i++)
#pragma unroll
        for (int j = 0; j < 8; j++)
#pragma unroll
            for (int q = 0; q < 4; q++) acc[i][j][q] = 0.f;

    int S = K / KCH;
    LOADST(0);
    LOADST(1);

    int a_r = lane & 15;
    int a_c = lane >> 4;
    int b_r = ((lane >> 3) & 1) * 8 + (lane & 7);
    int b_c = lane >> 4;

    for (int s = 0; s < S; s++) {
        if (s == S - 1) cp_wait<0>(); else cp_wait<1>();
        __syncthreads();
        if (s + 2 < S) LOADST(s + 2);

        uint32_t sa = sbase + (s % NSTG) * STGB;
#pragma unroll
        for (int ks = 0; ks < 2; ks++) {
            uint32_t ah[4][4], al[4][4], bhf[8][2];
#pragma unroll
            for (int i = 0; i < 4; i++) {
                int row = warpM + 16 * i + a_r;
                uint32_t ad = sa + SWO(row, ks * 2 + a_c);
                ldm_x4(ah[i], ad);
                ldm_x4(al[i], ad + MATB);
            }
#pragma unroll
            for (int jj = 0; jj < 4; jj++) {
                int row = warpN + 16 * jj + b_r;
                uint32_t bd = sa + 2 * MATB + SWO(row, ks * 2 + b_c);
                uint32_t q[4];
                ldm_x4(q, bd);
                bhf[2 * jj][0] = q[0]; bhf[2 * jj][1] = q[2];
                bhf[2 * jj + 1][0] = q[1]; bhf[2 * jj + 1][1] = q[3];
            }
#pragma unroll
            for (int i = 0; i < 4; i++)
#pragma unroll
                for (int j = 0; j < 8; j++)
                    mma_f16(acc[i][j], ah[i], bhf[j]);
#pragma unroll
            for (int i = 0; i < 4; i++)
#pragma unroll
                for (int j = 0; j < 8; j++)
                    mma_f16(acc[i][j], al[i], bhf[j]);
            if (TERMS == 3) {
                uint32_t blf[8][2];
#pragma unroll
                for (int jj = 0; jj < 4; jj++) {
                    int row = warpN + 16 * jj + b_r;
                    uint32_t bd = sa + 3 * MATB + SWO(row, ks * 2 + b_c);
                    uint32_t p[4];
                    ldm_x4(p, bd);
                    blf[2 * jj][0] = p[0]; blf[2 * jj][1] = p[2];
                    blf[2 * jj + 1][0] = p[1]; blf[2 * jj + 1][1] = p[3];
                }
#pragma unroll
                for (int i = 0; i < 4; i++)
#pragma unroll
                    for (int j = 0; j < 8; j++)
                        mma_f16(acc[i][j], ah[i], blf[j]);
            }
        }
    }
#undef LOADST

    int r0 = lane >> 2, c0 = (lane & 3) * 2;
#pragma unroll
    for (int i = 0; i < 4; i++) {
#pragma unroll
        for (int j = 0; j < 8; j++) {
            int row = by * 128 + warpM + 16 * i + r0;
            int col = bx * 128 + warpN + 8 * j + c0;
#pragma unroll
            for (int half = 0; half < 2; half++) {
                size_t off = (size_t)(row + half * 8) * N + col;
                float v0 = acc[i][j][2 * half];
                float v1 = acc[i][j][2 * half + 1];
                if (EPI == 0) {
                    *(float2*)(C + off) = make_float2(v0, v1);
                } else if (EPI == 1) {
                    float2 rr = *(const float2*)(Res + off);
                    *(float2*)(C + off) = make_float2(v0 + rr.x, v1 + rr.y);
                } else {
                    if (EPI == 2) { v0 = gelu_f(v0); v1 = gelu_f(v1); }
                    __half h0 = __float2half(v0);
                    __half h1 = __float2half(v1);
                    __half l0 = __float2half(v0 - __half2float(h0));
                    __half l1 = __float2half(v1 - __half2float(h1));
                    *(__half2*)(Chi + off) = __halves2half2(h0, h1);
                    *(__half2*)(Clo + off) = __halves2half2(l0, l1);
                }
            }
        }
    }
}

// ---------------- HMMA flash attention (round-9, unchanged) ----------------
#define SWO8(row_, chk_) ((uint32_t)((row_) * 128 + (((chk_) ^ ((row_) & 7)) << 4)))
#define AT_Q   0
#define AT_QL  8192
#define AT_K   16384
#define AT_KL  24576
#define AT_V   32768
#define AT_VL  40960
#define AT_SMEM 49152

__global__ void __launch_bounds__(128) attn_hmma(
    const __half* __restrict__ qkvHi, const __half* __restrict__ qkvLo,
    __half* __restrict__ oHi, __half* __restrict__ oLo)
{
    extern __shared__ char smem[];
    uint32_t sbase = smem_u32(smem);
    int qi = blockIdx.x;
    int bh = blockIdx.y;
    int b = bh >> 4, h = bh & 15;
    int tid = threadIdx.x, wid = tid >> 5, lane = tid & 31;
    int warpM = wid * 16;

    const size_t tokbase = (size_t)b * TSEQ * 3072;
    const __half* qH = qkvHi + tokbase + h * 64;
    const __half* qL = qkvLo + tokbase + h * 64;
    const __half* kH = qH + 1024;
    const __half* kL = qL + 1024;
    const __half* vH = qH + 2048;
    const __half* vL = qL + 2048;

    int lrow = tid >> 1;
    int lc0 = (tid & 1) * 4;

#pragma unroll
    for (int i = 0; i < 4; i++) {
        int chk = lc0 + i;
        size_t g = (size_t)(qi * 64 + lrow) * 3072 + chk * 8;
        cpa16(sbase + AT_Q + SWO8(lrow, chk), qH + g);
        cpa16(sbase + AT_QL + SWO8(lrow, chk), qL + g);
    }
    cp_commit();

    float acc_o[8][4];
#pragma unroll
    for (int j = 0; j < 8; j++)
#pragma unroll
        for (int q = 0; q < 4; q++) acc_o[j][q] = 0.f;
    float mrow[2] = {-1e30f, -1e30f};
    float lrw[2] = {0.f, 0.f};

    int a_r = lane & 15;
    int a_c = lane >> 4;
    int b_r = ((lane >> 3) & 1) * 8 + (lane & 7);
    int b_c = lane >> 4;

    for (int jt = 0; jt <= qi; jt++) {
        __syncthreads();
#pragma unroll
        for (int i = 0; i < 4; i++) {
            int chk = lc0 + i;
            size_t g = (size_t)(jt * 64 + lrow) * 3072 + chk * 8;
            uint32_t soff = SWO8(lrow, chk);
            cpa16(sbase + AT_K + soff, kH + g);
            cpa16(sbase + AT_KL + soff, kL + g);
            cpa16(sbase + AT_V + soff, vH + g);
            cpa16(sbase + AT_VL + soff, vL + g);
        }
        cp_commit();
        cp_wait<0>();
        __syncthreads();

        float s[8][4];
#pragma unroll
        for (int j = 0; j < 8; j++)
#pragma unroll
            for (int q = 0; q < 4; q++) s[j][q] = 0.f;

#pragma unroll
        for (int kc = 0; kc < 4; kc++) {
            uint32_t ah[4], al[4], kf[8][2];
            uint32_t ad = sbase + AT_Q + SWO8(warpM + a_r, kc * 2 + a_c);
            ldm_x4(ah, ad);
            ldm_x4(al, ad + (AT_QL - AT_Q));
#pragma unroll
            for (int jj = 0; jj < 4; jj++) {
                uint32_t bd = sbase + AT_K + SWO8(16 * jj + b_r, kc * 2 + b_c);
                uint32_t q[4];
                ldm_x4(q, bd);
                kf[2 * jj][0] = q[0]; kf[2 * jj][1] = q[2];
                kf[2 * jj + 1][0] = q[1]; kf[2 * jj + 1][1] = q[3];
            }
#pragma unroll
            for (int j = 0; j < 8; j++)
                mma_f16(s[j], ah, kf[j]);
#pragma unroll
            for (int j = 0; j < 8; j++)
                mma_f16(s[j], al, kf[j]);
            uint32_t klf[8][2];
#pragma unroll
            for (int jj = 0; jj < 4; jj++) {
                uint32_t bd = sbase + AT_KL + SWO8(16 * jj + b_r, kc * 2 + b_c);
                uint32_t p[4];
                ldm_x4(p, bd);
                klf[2 * jj][0] = p[0]; klf[2 * jj][1] = p[2];
                klf[2 * jj + 1][0] = p[1]; klf[2 * jj + 1][1] = p[3];
            }
#pragma unroll
            for (int j = 0; j < 8; j++)
                mma_f16(s[j], ah, klf[j]);
        }

        int rA = qi * 64 + warpM + (lane >> 2);
        int cbase = jt * 64 + (lane & 3) * 2;
#pragma unroll
        for (int j = 0; j < 8; j++) {
#pragma unroll
            for (int q = 0; q < 4; q++) {
                float v = s[j][q] * 0.125f;
                if (jt == qi) {
                    int col = cbase + j * 8 + (q & 1);
                    int row = rA + (q >= 2 ? 8 : 0);
                    if (col > row) v = -1e30f;
                }
                s[j][q] = v;
            }
        }

#pragma unroll
        for (int hf = 0; hf < 2; hf++) {
            float mt = -1e30f;
#pragma unroll
            for (int j = 0; j < 8; j++)
                mt = fmaxf(mt, fmaxf(s[j][2 * hf], s[j][2 * hf + 1]));
            mt = fmaxf(mt, __shfl_xor_sync(0xffffffffu, mt, 1));
            mt = fmaxf(mt, __shfl_xor_sync(0xffffffffu, mt, 2));
            float mn = fmaxf(mrow[hf], mt);
            float alpha = __expf(mrow[hf] - mn);
            float ls = 0.f;
#pragma unroll
            for (int j = 0; j < 8; j++) {
                float p0 = __expf(s[j][2 * hf] - mn);
                float p1 = __expf(s[j][2 * hf + 1] - mn);
                s[j][2 * hf] = p0; s[j][2 * hf + 1] = p1;
                ls += p0 + p1;
            }
            ls += __shfl_xor_sync(0xffffffffu, ls, 1);
            ls += __shfl_xor_sync(0xffffffffu, ls, 2);
            lrw[hf] = lrw[hf] * alpha + ls;
            mrow[hf] = mn;
#pragma unroll
            for (int j = 0; j < 8; j++) {
                acc_o[j][2 * hf] *= alpha;
                acc_o[j][2 * hf + 1] *= alpha;
            }
        }

#pragma unroll
        for (int kc = 0; kc < 4; kc++) {
            uint32_t phi[4], plo[4];
            {
                float p00 = s[2 * kc][0], p01 = s[2 * kc][1];
                float p02 = s[2 * kc][2], p03 = s[2 * kc][3];
                float p10 = s[2 * kc + 1][0], p11 = s[2 * kc + 1][1];
                float p12 = s[2 * kc + 1][2], p13 = s[2 * kc + 1][3];
                phi[0] = pack2h(p00, p01);
                phi[1] = pack2h(p02, p03);
                phi[2] = pack2h(p10, p11);
                phi[3] = pack2h(p12, p13);
                __half2 h0 = *(__half2*)&phi[0];
                __half2 h1 = *(__half2*)&phi[1];
                __half2 h2 = *(__half2*)&phi[2];
                __half2 h3 = *(__half2*)&phi[3];
                plo[0] = pack2h(p00 - __half2float(__low2half(h0)), p01 - __half2float(__high2half(h0)));
                plo[1] = pack2h(p02 - __half2float(__low2half(h1)), p03 - __half2float(__high2half(h1)));
                plo[2] = pack2h(p10 - __half2float(__low2half(h2)), p11 - __half2float(__high2half(h2)));
                plo[3] = pack2h(p12 - __half2float(__low2half(h3)), p13 - __half2float(__high2half(h3)));
            }
            uint32_t vfh[8][2], vfl[8][2];
#pragma unroll
            for (int g = 0; g < 4; g++) {
                uint32_t bd = sbase + AT_V + SWO8(kc * 16 + b_r, 2 * g + b_c);
                uint32_t q[4];
                ldm_x4t(q, bd);
                vfh[2 * g][0] = q[0]; vfh[2 * g][1] = q[1];
                vfh[2 * g + 1][0] = q[2]; vfh[2 * g + 1][1] = q[3];
                uint32_t p[4];
                ldm_x4t(p, bd + (AT_VL - AT_V));
                vfl[2 * g][0] = p[0]; vfl[2 * g][1] = p[1];
                vfl[2 * g + 1][0] = p[2]; vfl[2 * g + 1][1] = p[3];
            }
#pragma unroll
            for (int j = 0; j < 8; j++)
                mma_f16(acc_o[j], phi, vfh[j]);
#pragma unroll
            for (int j = 0; j < 8; j++)
                mma_f16(acc_o[j], phi, vfl[j]);
#pragma unroll
            for (int j = 0; j < 8; j++)
                mma_f16(acc_o[j], plo, vfh[j]);
        }
    }

    float inv0 = 1.0f / lrw[0];
    float inv1 = 1.0f / lrw[1];
#pragma unroll
    for (int j = 0; j < 8; j++) {
#pragma unroll
        for (int hf = 0; hf < 2; hf++) {
            int row = b * TSEQ + qi * 64 + warpM + (lane >> 2) + hf * 8;
            int col = h * 64 + j * 8 + (lane & 3) * 2;
            float inv = hf ? inv1 : inv0;
            float v0 = acc_o[j][2 * hf] * inv;
            float v1 = acc_o[j][2 * hf + 1] * inv;
            __half h0 = __float2half(v0);
            __half h1 = __float2half(v1);
            __half l0 = __float2half(v0 - __half2float(h0));
            __half l1 = __float2half(v1 - __half2float(h1));
            size_t off = (size_t)row * DMODEL + col;
            *(__half2*)(oHi + off) = __halves2half2(h0, h1);
            *(__half2*)(oLo + off) = __halves2half2(l0, l1);
        }
    }
}

// ---------------- fp32 -> fp16 hi/lo split ----------------
__global__ __launch_bounds__(256) void split2_kernel(const float* __restrict__ x,
                                                     __half* __restrict__ hi,
                                                     __half* __restrict__ lo, int n4) {
    int i = blockIdx.x * 256 + threadIdx.x;
    if (i >= n4) return;
    float4 v = ((const float4*)x)[i];
    __half h0 = __float2half(v.x), h1 = __float2half(v.y);
    __half h2 = __float2half(v.z), h3 = __float2half(v.w);
    __half l0 = __float2half(v.x - __half2float(h0));
    __half l1 = __float2half(v.y - __half2float(h1));
    __half l2 = __float2half(v.z - __half2float(h2));
    __half l3 = __float2half(v.w - __half2float(h3));
    ((__half2*)hi)[2 * i]     = __halves2half2(h0, h1);
    ((__half2*)hi)[2 * i + 1] = __halves2half2(h2, h3);
    ((__half2*)lo)[2 * i]     = __halves2half2(l0, l1);
    ((__half2*)lo)[2 * i + 1] = __halves2half2(l2, l3);
}

// ---------------- fp32 -> fp16 single (post-router weights) ----------------
__global__ __launch_bounds__(256) void cvt_kernel(const float* __restrict__ x,
                                                  __half* __restrict__ y, int n4) {
    int i = blockIdx.x * 256 + threadIdx.x;
    if (i >= n4) return;
    float4 v = ((const float4*)x)[i];
    ((__half2*)y)[2 * i]     = __floats2half2_rn(v.x, v.y);
    ((__half2*)y)[2 * i + 1] = __floats2half2_rn(v.z, v.w);
}

// ---------------- LayerNorm fused with hi/lo split ----------------
template<int MODE>
__global__ __launch_bounds__(256) void ln_fused(const float* __restrict__ x,
                                                const float* __restrict__ w,
                                                const float* __restrict__ c,
                                                float* __restrict__ outf,
                                                __half* __restrict__ hi,
                                                __half* __restrict__ lo) {
    int row = blockIdx.x;
    int tid = threadIdx.x;
    const float* xr = x + (size_t)row * DMODEL;
    float4 v = *(const float4*)(xr + tid * 4);

    __shared__ float red[8];
    __shared__ float tot;

    float s = v.x + v.y + v.z + v.w;
#pragma unroll
    for (int m = 16; m > 0; m >>= 1) s += __shfl_xor_sync(0xffffffffu, s, m);
    if ((tid & 31) == 0) red[tid >> 5] = s;
    __syncthreads();
    if (tid == 0) { float t = 0.f; for (int i = 0; i < 8; i++) t += red[i]; tot = t; }
    __syncthreads();
    float mean = tot * (1.0f / DMODEL);
    float dx = v.x - mean, dy = v.y - mean, dz = v.z - mean, dw = v.w - mean;
    float s2 = dx * dx + dy * dy + dz * dz + dw * dw;
    __syncthreads();
#pragma unroll
    for (int m = 16; m > 0; m >>= 1) s2 += __shfl_xor_sync(0xffffffffu, s2, m);
    if ((tid & 31) == 0) red[tid >> 5] = s2;
    __syncthreads();
    if (tid == 0) { float t = 0.f; for (int i = 0; i < 8; i++) t += red[i]; tot = t; }
    __syncthreads();
    float inv = rsqrtf(tot * (1.0f / DMODEL) + 1e-5f);

    int d0 = tid * 4;
    float4 w4 = *(const float4*)(w + d0);
    float r0 = dx * inv * w4.x;
    float r1 = dy * inv * w4.y;
    float r2 = dz * inv * w4.z;
    float r3 = dw * inv * w4.w;
    if (MODE == 0) {
        int b = row >> 10;
        float4 c4 = *(const float4*)(c + (size_t)b * DMODEL + d0);
        r0 += c4.x; r1 += c4.y; r2 += c4.z; r3 += c4.w;
    }
    if (MODE == 1)
        *(float4*)(outf + (size_t)row * DMODEL + d0) = make_float4(r0, r1, r2, r3);
    __half h0 = __float2half(r0), h1 = __float2half(r1);
    __half h2 = __float2half(r2), h3 = __float2half(r3);
    __half l0 = __float2half(r0 - __half2float(h0));
    __half l1 = __float2half(r1 - __half2float(h1));
    __half l2 = __float2half(r2 - __half2float(h2));
    __half l3 = __float2half(r3 - __half2float(h3));
    size_t ho = (size_t)row * DMODEL + d0;
    *(__half2*)(hi + ho)     = __halves2half2(h0, h1);
    *(__half2*)(hi + ho + 2) = __halves2half2(h2, h3);
    *(__half2*)(lo + ho)     = __halves2half2(l0, l1);
    *(__half2*)(lo + ho + 2) = __halves2half2(l2, l3);
}

// ---------------- router ----------------
__global__ __launch_bounds__(256) void router_kernel(const float* __restrict__ xn,
                                                     const float* __restrict__ rw,
                                                     int* __restrict__ eidx,
                                                     float* __restrict__ wts) {
    int t = blockIdx.x;
    int tid = threadIdx.x, lane = tid & 31, wp = tid >> 5;
    const float* xr = xn + (size_t)t * DMODEL;
    const float* wr = rw + (size_t)wp * DMODEL;
    float s = 0.f;
    for (int d = lane * 4; d < DMODEL; d += 128) {
        float4 a = *(const float4*)(xr + d);
        float4 b = *(const float4*)(wr + d);
        s += a.x * b.x + a.y * b.y + a.z * b.z + a.w * b.w;
    }
#pragma unroll
    for (int mm = 16; mm > 0; mm >>= 1) s += __shfl_xor_sync(0xffffffffu, s, mm);
    __shared__ float lg[8];
    if (lane == 0) lg[wp] = s;
    __syncthreads();
    if (tid == 0) {
        float mx = lg[0];
        for (int e = 1; e < NE; e++) mx = fmaxf(mx, lg[e]);
        float p[NE]; float sum = 0.f;
        for (int e = 0; e < NE; e++) { p[e] = expf(lg[e] - mx); sum += p[e]; }
        float inv = 1.0f / sum;
        for (int e = 0; e < NE; e++) {
            float v = p[e] * inv + 1e-9f;
            p[e] = fminf(fmaxf(v, 1e-9f), 1.0f - 1e-9f);
        }
        int i0 = 0;
        for (int e = 1; e < NE; e++) if (p[e] > p[i0]) i0 = e;
        int i1 = (i0 == 0) ? 1 : 0;
        for (int e = 0; e < NE; e++) if (e != i0 && p[e] > p[i1]) i1 = e;
        float d2 = 1.0f / (p[i0] + p[i1]);
        eidx[2 * t] = i0; eidx[2 * t + 1] = i1;
        wts[2 * t] = p[i0] * d2; wts[2 * t + 1] = p[i1] * d2;
    }
}

// ---------------- build per-expert CSR ----------------
__global__ __launch_bounds__(256) void build_kernel(const int* __restrict__ eidx,
                                                    int* __restrict__ rows,
                                                    int* __restrict__ tile_e) {
    __shared__ int cnt[NE];
    __shared__ int off[NE];
    int tid = threadIdx.x;
    if (tid < NE) cnt[tid] = 0;
    __syncthreads();
    for (int a = tid; a < BT * 2; a += 256) atomicAdd(&cnt[eidx[a]], 1);
    __syncthreads();
    if (tid == 0) {
        int o = 0;
        for (int e = 0; e < NE; e++) { off[e] = o; o = (o + cnt[e] + 127) & ~127; }
        for (int tt = 0; tt < NTILES; tt++) tile_e[tt] = -1;
        for (int e = 0; e < NE; e++) {
            int nt = (cnt[e] + 127) >> 7;
            int t0 = off[e] >> 7;
            for (int i = 0; i < nt; i++) tile_e[t0 + i] = e;
        }
    }
    __syncthreads();
    if (tid < NE) cnt[tid] = 0;
    __syncthreads();
    for (int a = tid; a < BT * 2; a += 256) {
        int e = eidx[a];
        int pos = atomicAdd(&cnt[e], 1);
        rows[a] = off[e] + pos;
    }
}

// ---------------- gather fp16 rows ----------------
__global__ __launch_bounds__(128) void gather_hf(const __half* __restrict__ xhi,
                                                 const __half* __restrict__ xlo,
                                                 const int* __restrict__ rows,
                                                 __half* __restrict__ ghi,
                                                 __half* __restrict__ glo) {
    int a = blockIdx.x;
    int r = rows[a];
    int t = a >> 1;
    int tid = threadIdx.x;
    ((uint4*)(ghi + (size_t)r * DMODEL))[tid] = ((const uint4*)(xhi + (size_t)t * DMODEL))[tid];
    ((uint4*)(glo + (size_t)r * DMODEL))[tid] = ((const uint4*)(xlo + (size_t)t * DMODEL))[tid];
}

// ---------------- combine ----------------
__global__ __launch_bounds__(256) void combine_kernel(const float* __restrict__ xn,
                                                      const float* __restrict__ eo,
                                                      const int* __restrict__ rows,
                                                      const float* __restrict__ wts,
                                                      float* __restrict__ out) {
    int t = blockIdx.x;
    int r0 = rows[2 * t], r1 = rows[2 * t + 1];
    float w0 = wts[2 * t], w1 = wts[2 * t + 1];
    int tid = threadIdx.x;
    float4 a = *(const float4*)(xn + (size_t)t * DMODEL + tid * 4);
    float4 b = *(const float4*)(eo + (size_t)r0 * DMODEL + tid * 4);
    float4 c = *(const float4*)(eo + (size_t)r1 * DMODEL + tid * 4);
    float4 r;
    r.x = a.x + w0 * b.x + w1 * c.x;
    r.y = a.y + w0 * b.y + w1 * c.y;
    r.z = a.z + w0 * b.z + w1 * c.z;
    r.w = a.w + w0 * b.w + w1 * c.w;
    *(float4*)(out + (size_t)t * DMODEL + tid * 4) = r;
}

// ---------------- host launcher ----------------
extern "C" void kernel_launch(void* const* d_in, const int* in_sizes, int n_in,
                              void* d_out, int out_size) {
    const float* x        = (const float*)d_in[0];
    const float* c        = (const float*)d_in[1];
    const float* ln1_w    = (const float*)d_in[2];
    const float* w_qkv    = (const float*)d_in[3];
    const float* w_proj   = (const float*)d_in[4];
    const float* ln2_w    = (const float*)d_in[5];
    const float* router_w = (const float*)d_in[6];
    const float* ew1      = (const float*)d_in[7];
    const float* ew2      = (const float*)d_in[8];
    float* out = (float*)d_out;

    float *p_x2, *p_xn, *p_eo, *p_wts;
    int *p_eidx, *p_rows, *p_te;
    __half *p_aHi, *p_aLo, *p_qkvHi, *p_qkvLo, *p_wHi, *p_wLo;
    __half *p_xgHi, *p_xgLo, *p_hidHi, *p_hidLo;
    cudaGetSymbolAddress((void**)&p_x2,    g_x2);
    cudaGetSymbolAddress((void**)&p_xn,    g_xn);
    cudaGetSymbolAddress((void**)&p_eo,    g_eo);
    cudaGetSymbolAddress((void**)&p_wts,   g_wts);
    cudaGetSymbolAddress((void**)&p_eidx,  g_eidx);
    cudaGetSymbolAddress((void**)&p_rows,  g_rows);
    cudaGetSymbolAddress((void**)&p_te,    g_tile_e);
    cudaGetSymbolAddress((void**)&p_aHi,   g_aHi);
    cudaGetSymbolAddress((void**)&p_aLo,   g_aLo);
    cudaGetSymbolAddress((void**)&p_qkvHi, g_qkvHi);
    cudaGetSymbolAddress((void**)&p_qkvLo, g_qkvLo);
    cudaGetSymbolAddress((void**)&p_wHi,   g_wHi);
    cudaGetSymbolAddress((void**)&p_wLo,   g_wLo);
    cudaGetSymbolAddress((void**)&p_xgHi,  g_xgHi);
    cudaGetSymbolAddress((void**)&p_xgLo,  g_xgLo);
    cudaGetSymbolAddress((void**)&p_hidHi, g_hidHi);
    cudaGetSymbolAddress((void**)&p_hidLo, g_hidLo);

    const int SMEM3 = NSTG * 4 * MATB;   // 98304 for 3-term
    const int SMEM2 = NSTG * 3 * MATB;   // 73728 for 2-term
    cudaFuncSetAttribute((const void*)hmma_gemm<1, 3>, cudaFuncAttributeMaxDynamicSharedMemorySize, SMEM3);
    cudaFuncSetAttribute((const void*)hmma_gemm<3, 3>, cudaFuncAttributeMaxDynamicSharedMemorySize, SMEM3);
    cudaFuncSetAttribute((const void*)hmma_gemm<2, 2>, cudaFuncAttributeMaxDynamicSharedMemorySize, SMEM2);
    cudaFuncSetAttribute((const void*)hmma_gemm<0, 2>, cudaFuncAttributeMaxDynamicSharedMemorySize, SMEM2);
    cudaFuncSetAttribute(attn_hmma, cudaFuncAttributeMaxDynamicSharedMemorySize, AT_SMEM);

    // 1) h = LN1(x)*w + c -> fp16 hi/lo directly
    ln_fused<0><<<BT, 256>>>(x, ln1_w, c, nullptr, p_aHi, p_aLo);
    split2_kernel<<<(3 * DMODEL * DMODEL / 4 + 255) / 256, 256>>>(w_qkv, p_wHi, p_wLo, 3 * DMODEL * DMODEL / 4);

    // 2) qkv = h @ w_qkv^T -> fp16 hi/lo  (3-term: pre-router precision)
    hmma_gemm<3, 3><<<dim3(24, 32), 128, SMEM3>>>(p_aHi, p_aLo, p_wHi, p_wLo, 0, nullptr,
                                                  nullptr, nullptr, p_qkvHi, p_qkvLo, 3072, 1024);

    // 3) causal attention (HMMA, 3-term)
    attn_hmma<<<dim3(16, 64), 128, AT_SMEM>>>(p_qkvHi, p_qkvLo, p_aHi, p_aLo);

    // 4) x2 = x + o @ w_proj^T  (3-term)
    split2_kernel<<<(DMODEL * DMODEL / 4 + 255) / 256, 256>>>(w_proj, p_wHi, p_wLo, DMODEL * DMODEL / 4);
    hmma_gemm<1, 3><<<dim3(8, 32), 128, SMEM3>>>(p_aHi, p_aLo, p_wHi, p_wLo, 0, nullptr,
                                                 p_x2, x, nullptr, nullptr, 1024, 1024);

    // 5) xn = LN2(x2) -> fp32 + fp16 hi/lo
    ln_fused<1><<<BT, 256>>>(p_x2, ln2_w, nullptr, p_xn, p_aHi, p_aLo);

    // 6) router + CSR  (fp32 inputs: routing decisions exact)
    router_kernel<<<BT, 256>>>(p_xn, router_w, p_eidx, p_wts);
    build_kernel<<<1, 256>>>(p_eidx, p_rows, p_te);

    // 7) gather fp16
    gather_hf<<<BT * 2, 128>>>(p_aHi, p_aLo, p_rows, p_xgHi, p_xgLo);

    // 8) hid = gelu(xg @ w1[e]^T)  (2-term: post-router, additive error only)
    cvt_kernel<<<(NE * FF * DMODEL / 4 + 255) / 256, 256>>>(ew1, p_wHi, NE * FF * DMODEL / 4);
    hmma_gemm<2, 2><<<dim3(32, NTILES), 128, SMEM2>>>(p_xgHi, p_xgLo, p_wHi, nullptr,
                                                      (size_t)FF * DMODEL, p_te,
                                                      nullptr, nullptr, p_hidHi, p_hidLo, FF, 1024);

    // 9) eo = hid @ w2[e]^T  (2-term)
    cvt_kernel<<<(NE * DMODEL * FF / 4 + 255) / 256, 256>>>(ew2, p_wHi, NE * DMODEL * FF / 4);
    hmma_gemm<0, 2><<<dim3(8, NTILES), 128, SMEM2>>>(p_hidHi, p_hidLo, p_wHi, nullptr,
                                                     (size_t)DMODEL * FF, p_te,
                                                     p_eo, nullptr, nullptr, nullptr, 1024, 4096);

    // 10) out = xn + sum_k w_k * eo
    combine_kernel<<<BT, 256>>>(p_xn, p_eo, p_rows, p_wts, out);
}